// round 9
// baseline (speedup 1.0000x reference)
#include <cuda_runtime.h>
#include <math.h>

#define BB   4
#define TT0  128
#define WD   128
#define EB   16
#define LL   2048
#define ODIM 24
#define TF   122

// ---------------- scratch (no allocations allowed) ----------------
__device__ float g_bufA[BB*WD*TT0*EB];   // 4 MB
__device__ float g_bufB[BB*WD*TT0*EB];   // 4 MB
__device__ float g_bufR[BB*WD*TT0*EB];   // 4 MB (residual-path output)
__device__ float g_Mt[2*WD*WD];          // Mt[m*128+n] = (Wq Wk^T)[n][m]
__device__ float g_uu[2*WD];             // u = Wq bk
__device__ float g_ww[2*WD];             // w = Wk bq
__device__ float g_cc[2];                // c = bq . bk
__device__ float g_yv[BB*126*WD];        // per-(b,t) y vectors

// ---------------- f32x2 packed helpers ----------------
__device__ __forceinline__ unsigned long long fma2(unsigned long long a,
                                                   unsigned long long b,
                                                   unsigned long long c) {
    unsigned long long d;
    asm("fma.rn.f32x2 %0, %1, %2, %3;" : "=l"(d) : "l"(a), "l"(b), "l"(c));
    return d;
}
__device__ __forceinline__ unsigned long long pack2(float v) {
    unsigned long long r;
    asm("mov.b64 %0, {%1, %1};" : "=l"(r) : "f"(v));
    return r;
}
__device__ __forceinline__ void unpack2(unsigned long long v, float& lo, float& hi) {
    asm("mov.b64 {%0, %1}, %2;" : "=f"(lo), "=f"(hi) : "l"(v));
}

// ---------------- embed: x_in -> (B,N,T,E) ----------------
__global__ void k_embed(const float* __restrict__ x_in,
                        const float* __restrict__ emb_w,
                        const float* __restrict__ emb_b,
                        float* __restrict__ out) {
    int idx = blockIdx.x*blockDim.x + threadIdx.x;   // over B*T*N
    if (idx >= BB*TT0*WD) return;
    int n = idx & 127;
    int t = (idx >> 7) & 127;
    int b = idx >> 14;
    const float* xi = x_in + (b*TT0 + t)*131;
    float v  = xi[n];
    float f0 = xi[128], f1 = xi[129], f2 = xi[130];
    float* o = out + ((b*WD + n)*TT0 + t)*EB;
    #pragma unroll
    for (int e = 0; e < EB; e++)
        o[e] = v*emb_w[e] + f0*emb_w[16+e] + f1*emb_w[32+e] + f2*emb_w[48+e] + emb_b[e];
}

// ---------------- precompute Mt[m*128+n] = sum_l Wq[n,l]*Wk[m,l], both layers ----------------
__global__ void k_mt(const float* __restrict__ Wq0, const float* __restrict__ Wk0,
                     const float* __restrict__ Wq1, const float* __restrict__ Wk1,
                     float* __restrict__ Mt) {
    __shared__ float Aq[16][65], Ak[16][65];
    int ly = blockIdx.y;
    const float* Wq = ly ? Wq1 : Wq0;
    const float* Wk = ly ? Wk1 : Wk0;
    float* Mto = Mt + ly*WD*WD;
    int bm = blockIdx.x >> 3, bn = blockIdx.x & 7;
    int m0 = bm*16, n0 = bn*16;
    int ty = threadIdx.x >> 4, tx = threadIdx.x & 15;  // ty -> m, tx -> n
    float acc = 0.f;
    for (int l0 = 0; l0 < LL; l0 += 64) {
        #pragma unroll
        for (int r = 0; r < 4; r++) {
            int idx = threadIdx.x + r*256;
            int row = idx >> 6, col = idx & 63;
            Aq[row][col] = Wq[(n0+row)*LL + l0 + col];
            Ak[row][col] = Wk[(m0+row)*LL + l0 + col];
        }
        __syncthreads();
        #pragma unroll
        for (int lc = 0; lc < 64; lc++)
            acc += Ak[ty][lc]*Aq[tx][lc];
        __syncthreads();
    }
    Mto[(m0+ty)*WD + (n0+tx)] = acc;
}

// ---------------- precompute u, w, c (both layers) ----------------
__global__ void k_uw(const float* __restrict__ Wq0, const float* __restrict__ Wk0,
                     const float* __restrict__ bq0, const float* __restrict__ bk0,
                     const float* __restrict__ Wq1, const float* __restrict__ Wk1,
                     const float* __restrict__ bq1, const float* __restrict__ bk1,
                     float* __restrict__ u, float* __restrict__ w, float* __restrict__ cp) {
    int ly = blockIdx.y;
    const float* Wq = ly ? Wq1 : Wq0;
    const float* Wk = ly ? Wk1 : Wk0;
    const float* bq = ly ? bq1 : bq0;
    const float* bk = ly ? bk1 : bk0;
    int n = blockIdx.x;
    __shared__ float su[256], sw[256], sc[256];
    float pu = 0.f, pw = 0.f, pc = 0.f;
    for (int l = threadIdx.x; l < LL; l += 256) {
        float bkl = bk[l], bql = bq[l];
        pu += Wq[n*LL + l]*bkl;
        pw += Wk[n*LL + l]*bql;
        if (n == 0) pc += bql*bkl;
    }
    su[threadIdx.x] = pu; sw[threadIdx.x] = pw; sc[threadIdx.x] = pc;
    __syncthreads();
    for (int s = 128; s > 0; s >>= 1) {
        if (threadIdx.x < s) {
            su[threadIdx.x] += su[threadIdx.x + s];
            sw[threadIdx.x] += sw[threadIdx.x + s];
            sc[threadIdx.x] += sc[threadIdx.x + s];
        }
        __syncthreads();
    }
    if (threadIdx.x == 0) {
        u[ly*WD + n] = su[0]; w[ly*WD + n] = sw[0];
        if (n == 0) cp[ly] = sc[0];
    }
}

// ---------------- gated conv GEMM v2: 256 thr, thread tile 2o x 8j ----------------
// j = t*16+e flattened per batch. Block tile 64o x 64j. Y = tanh(F+bf)*sigmoid(G+bg)
template<int TIN, int TOUT, int D>
__global__ void k_gatedg(const float* __restrict__ X,
                         const float* __restrict__ wf, const float* __restrict__ bf,
                         const float* __restrict__ wg, const float* __restrict__ bg,
                         float* __restrict__ Y) {
    constexpr int TIN16  = TIN*16;
    constexpr int TOUT16 = TOUT*16;
    constexpr int OFF    = 16*D;          // tap-1 column offset (32 or 64)
    __shared__ float Af[64][33];          // [o_local][kk]  kk = il*2+tap
    __shared__ float Ag[64][33];
    __shared__ float Bs[16][136];         // [il][c], c = 0..127

    int bx = blockIdx.x;
    int oB = bx & 1;                      // o-half
    int jT = bx >> 1;                     // j tile
    int b  = blockIdx.y;
    int j0b = jT*64;
    int tid = threadIdx.x;                // 256
    int jt = tid & 7;                     // j = j0b + jt*8 .. +7
    int ot = tid >> 3;                    // o_local = ot*2 .. +1

    unsigned long long fa[2][4], ga[2][4];
    #pragma unroll
    for (int oo = 0; oo < 2; oo++)
        #pragma unroll
        for (int p = 0; p < 4; p++) { fa[oo][p] = 0ull; ga[oo][p] = 0ull; }

    for (int i0 = 0; i0 < WD; i0 += 16) {
        __syncthreads();
        // stage weights (coalesced): Af[ol][kk] = wf[(oB*64+ol)*256 + i0*2 + kk]
        #pragma unroll
        for (int r = 0; r < 8; r++) {
            int idx = tid + r*256;
            int kk = idx & 31, ol = idx >> 5;
            Af[ol][kk] = wf[(oB*64 + ol)*(WD*2) + i0*2 + kk];
            Ag[ol][kk] = wg[(oB*64 + ol)*(WD*2) + i0*2 + kk];
        }
        // stage X: Bs[il][c] = X[b, i0+il, j0b + c]
        #pragma unroll
        for (int r = 0; r < 8; r++) {
            int idx = tid + r*256;
            int c = idx & 127, il = idx >> 7;
            int jg = j0b + c;
            Bs[il][c] = (jg < TIN16) ? X[((size_t)(b*WD + i0 + il))*TIN16 + jg] : 0.f;
        }
        __syncthreads();
        #pragma unroll 4
        for (int il = 0; il < 16; il++) {
            #pragma unroll
            for (int tap = 0; tap < 2; tap++) {
                int k = il*2 + tap;
                const float* bp = &Bs[il][jt*8 + tap*OFF];
                ulonglong2 q0 = *(const ulonglong2*)bp;
                ulonglong2 q1 = *(const ulonglong2*)(bp + 4);
                unsigned long long bq[4] = {q0.x, q0.y, q1.x, q1.y};
                #pragma unroll
                for (int oo = 0; oo < 2; oo++) {
                    unsigned long long paf = pack2(Af[ot*2 + oo][k]);
                    unsigned long long pag = pack2(Ag[ot*2 + oo][k]);
                    #pragma unroll
                    for (int p = 0; p < 4; p++) {
                        fa[oo][p] = fma2(paf, bq[p], fa[oo][p]);
                        ga[oo][p] = fma2(pag, bq[p], ga[oo][p]);
                    }
                }
            }
        }
    }

    int jbase = j0b + jt*8;
    if (jbase < TOUT16) {   // TOUT16 % 8 == 0 -> whole 8-j group valid
        #pragma unroll
        for (int oo = 0; oo < 2; oo++) {
            int o = oB*64 + ot*2 + oo;
            float bfo = bf[o], bgo = bg[o];
            float fv[8], gv[8];
            #pragma unroll
            for (int p = 0; p < 4; p++) {
                unpack2(fa[oo][p], fv[2*p], fv[2*p+1]);
                unpack2(ga[oo][p], gv[2*p], gv[2*p+1]);
            }
            float yv[8];
            #pragma unroll
            for (int q = 0; q < 8; q++)
                yv[q] = tanhf(fv[q] + bfo)*(1.f/(1.f + expf(-(gv[q] + bgo))));
            float* yp = Y + ((size_t)(b*WD + o))*TOUT16 + jbase;
            *(float4*)(yp)     = make_float4(yv[0], yv[1], yv[2], yv[3]);
            *(float4*)(yp + 4) = make_float4(yv[4], yv[5], yv[6], yv[7]);
        }
    }
}

// ---------------- residual path v3: R[b,n,s,e] = sum_t X[b,n,t,e]*ws[t,s] + bs[s] ----
// 32-row tiles -> grid = BB*64 blocks. Pure write (no RMW).
template<int TIN, int TOUT>
__global__ void k_res3(const float* __restrict__ X, const float* __restrict__ ws,
                       const float* __restrict__ bs, float* __restrict__ Y) {
    constexpr int RPB = 32;
    constexpr int KC  = 32;
    __shared__ float As[KC][RPB];       // [t][row]
    __shared__ float Ws[KC][132];       // [t][s]
    int b  = blockIdx.x >> 6;
    int r0 = (blockIdx.x & 63)*RPB;
    int tid = threadIdx.x;              // 256
    int rq = tid >> 4;                  // 0..15 -> rows rq*2..+1
    int sg = tid & 15;                  // s = sg*8 .. +7

    unsigned long long acc[2][4];
    #pragma unroll
    for (int r = 0; r < 2; r++)
        #pragma unroll
        for (int j = 0; j < 4; j++) acc[r][j] = 0ull;

    for (int t0 = 0; t0 < TIN; t0 += KC) {
        __syncthreads();
        #pragma unroll
        for (int j = 0; j < (RPB*KC)/256; j++) {
            int idx = tid + j*256;
            int row = idx & (RPB-1);
            int t = idx >> 5;
            int rr = r0 + row;
            int n = rr >> 4, e = rr & 15;
            int tg = t0 + t;
            As[t][row] = (tg < TIN) ? X[((b*WD + n)*TIN + tg)*EB + e] : 0.f;
        }
        #pragma unroll
        for (int j = 0; j < (KC*128)/256; j++) {
            int idx = tid + j*256;
            int s = idx & 127;
            int t = idx >> 7;
            int tg = t0 + t;
            Ws[t][s] = (tg < TIN && s < TOUT) ? ws[tg*TOUT + s] : 0.f;
        }
        __syncthreads();
        #pragma unroll
        for (int t = 0; t < KC; t++) {
            float4 w0 = *(const float4*)(&Ws[t][sg*8]);
            float4 w1 = *(const float4*)(&Ws[t][sg*8 + 4]);
            unsigned long long wv[4];
            wv[0] = ((unsigned long long)__float_as_uint(w0.y) << 32) | __float_as_uint(w0.x);
            wv[1] = ((unsigned long long)__float_as_uint(w0.w) << 32) | __float_as_uint(w0.z);
            wv[2] = ((unsigned long long)__float_as_uint(w1.y) << 32) | __float_as_uint(w1.x);
            wv[3] = ((unsigned long long)__float_as_uint(w1.w) << 32) | __float_as_uint(w1.z);
            #pragma unroll
            for (int r = 0; r < 2; r++) {
                unsigned long long av = pack2(As[t][rq*2 + r]);
                #pragma unroll
                for (int j = 0; j < 4; j++)
                    acc[r][j] = fma2(av, wv[j], acc[r][j]);
            }
        }
    }
    #pragma unroll
    for (int r = 0; r < 2; r++) {
        int rr = r0 + rq*2 + r;
        int n = rr >> 4, e = rr & 15;
        float* yp = Y + ((size_t)(b*WD + n)*TOUT)*EB + e;
        #pragma unroll
        for (int j = 0; j < 4; j++) {
            float lo, hi; unpack2(acc[r][j], lo, hi);
            int s0 = sg*8 + j*2;
            if (s0 < TOUT)   yp[s0*EB]     = lo + bs[s0];
            if (s0+1 < TOUT) yp[(s0+1)*EB] = hi + bs[s0+1];
        }
    }
}

// ---------------- fused attention: X = Xg+Xr; Z GEMM + softmax + ybar ----------------
template<int T>
__global__ void k_attn2(const float* __restrict__ Xg, const float* __restrict__ Xr,
                        const float* __restrict__ Mt,
                        const float* __restrict__ u, const float* __restrict__ w,
                        const float* __restrict__ cptr, float* __restrict__ yout) {
    __shared__ __align__(16) float Xs[WD*EB];   // [n][e] 8KB
    __shared__ __align__(16) float Ms[32*WD];   // Mt chunk [k][n] 16KB
    __shared__ float Zs[EB][WD+5];              // [f][n]
    __shared__ float Ss[EB][EB+1];
    __shared__ float uev[EB], wfv[EB], abar[EB];
    int bt = blockIdx.x;
    int b = bt / T, t = bt % T;
    int tid = threadIdx.x;                      // 256
    // load Xs = Xg + Xr (vectorized)
    for (int idx = tid; idx < WD*4; idx += 256) {
        int n = idx >> 2, q = idx & 3;
        size_t off = ((size_t)((b*WD + n)*T + t))*EB + q*4;
        float4 a = *(const float4*)(Xg + off);
        float4 r = *(const float4*)(Xr + off);
        ((float4*)Xs)[idx] = make_float4(a.x + r.x, a.y + r.y, a.z + r.z, a.w + r.w);
    }
    // Z[fh*8..+7][n] per thread (n = tid&127, fh = tid>>7)
    int n_ = tid & 127, fh = tid >> 7;
    unsigned long long zacc[4] = {0ull, 0ull, 0ull, 0ull};
    for (int m0 = 0; m0 < WD; m0 += 32) {
        __syncthreads();
        #pragma unroll
        for (int rep = 0; rep < (32*WD/4)/256; rep++)
            ((float4*)Ms)[tid + rep*256] = ((const float4*)(Mt + m0*WD))[tid + rep*256];
        __syncthreads();
        #pragma unroll
        for (int k = 0; k < 32; k++) {
            unsigned long long pm = pack2(Ms[k*WD + n_]);
            const ulonglong2* xp = (const ulonglong2*)(Xs + (m0 + k)*16 + fh*8);
            ulonglong2 xa = xp[0];
            zacc[0] = fma2(pm, xa.x, zacc[0]);
            zacc[1] = fma2(pm, xa.y, zacc[1]);
            ulonglong2 xb = xp[1];
            zacc[2] = fma2(pm, xb.x, zacc[2]);
            zacc[3] = fma2(pm, xb.y, zacc[3]);
        }
    }
    #pragma unroll
    for (int j = 0; j < 4; j++) {
        float lo, hi; unpack2(zacc[j], lo, hi);
        Zs[fh*8 + 2*j][n_]     = lo;
        Zs[fh*8 + 2*j + 1][n_] = hi;
    }
    if (tid < 16) {
        float a = 0.f;
        for (int n = 0; n < WD; n++) a += Xs[n*16 + tid]*u[n];
        uev[tid] = a;
    } else if (tid < 32) {
        int f = tid - 16;
        float a = 0.f;
        for (int n = 0; n < WD; n++) a += Xs[n*16 + f]*w[n];
        wfv[f] = a;
    }
    __syncthreads();
    {
        int e = tid >> 4, f = tid & 15;
        float acc = 0.f;
        #pragma unroll 4
        for (int n = 0; n < WD; n++)
            acc += Xs[n*16 + e]*Zs[f][n];
        const float scale = 0.022097086912079608f; // 1/sqrt(2048)
        Ss[e][f] = (acc + uev[e] + wfv[f] + cptr[0])*scale;
    }
    __syncthreads();
    if (tid < 16) {
        int e = tid;
        float mx = -1e30f;
        #pragma unroll
        for (int f = 0; f < 16; f++) mx = fmaxf(mx, Ss[e][f]);
        float ex[16]; float sum = 0.f;
        #pragma unroll
        for (int f = 0; f < 16; f++) { ex[f] = expf(Ss[e][f] - mx); sum += ex[f]; }
        float inv = 1.f/sum;
        #pragma unroll
        for (int f = 0; f < 16; f++) Ss[e][f] = ex[f]*inv;
    }
    __syncthreads();
    if (tid < 16) {
        int f = tid;
        float a = 0.f;
        #pragma unroll
        for (int e = 0; e < 16; e++) a += Ss[e][f];
        abar[f] = a*(1.f/16.f);
    }
    __syncthreads();
    if (tid < 128) {
        int n = tid;
        float a = 0.f;
        #pragma unroll
        for (int f = 0; f < 16; f++) a += Xs[n*16 + f]*abar[f];
        yout[bt*WD + n] = a;
    }
}

// ---------------- attention out: Y = (Xg+Xr) + y @ Wv + bv ----------------
template<int T>
__global__ void k_attn_out(const float* __restrict__ Xg, const float* __restrict__ Xr,
                           const float* __restrict__ yv,
                           const float* __restrict__ Wv, const float* __restrict__ bv,
                           float* __restrict__ Yout) {
    __shared__ float ys[64][WD];
    const int BT = BB*T;
    int bt0 = blockIdx.y*64;
    int l = blockIdx.x*128 + (threadIdx.x & 127);
    int half = threadIdx.x >> 7;
    for (int idx = threadIdx.x; idx < 64*WD; idx += 256) {
        int r = idx >> 7, m = idx & 127;
        int bt = bt0 + r;
        ys[r][m] = (bt < BT) ? yv[bt*WD + m] : 0.f;
    }
    __syncthreads();
    float acc[32];
    #pragma unroll
    for (int j = 0; j < 32; j++) acc[j] = 0.f;
    for (int m = 0; m < WD; m++) {
        float wvv = Wv[m*LL + l];
        #pragma unroll
        for (int j = 0; j < 32; j++) acc[j] += ys[half*32 + j][m]*wvv;
    }
    float bvl = bv[l];
    int n = l >> 4, e = l & 15;
    #pragma unroll
    for (int j = 0; j < 32; j++) {
        int bt = bt0 + half*32 + j;
        if (bt < BT) {
            int b = bt / T, t = bt % T;
            size_t idx = ((size_t)((b*WD + n)*T + t))*EB + e;
            Yout[idx] = Xg[idx] + Xr[idx] + acc[j] + bvl;
        }
    }
}

// ---------------- decode + time-mix output ----------------
__global__ void k_decode(const float* __restrict__ X, const float* __restrict__ dec_w,
                         const float* __restrict__ dec_b, const float* __restrict__ out_w,
                         const float* __restrict__ out_b, float* __restrict__ out) {
    __shared__ float sy[TF];
    int b = blockIdx.x >> 7, n = blockIdx.x & 127;
    int t = threadIdx.x;
    if (t < TF) {
        const float* xp = X + ((size_t)(b*WD + n)*TF + t)*EB;
        float a = dec_b[n];
        #pragma unroll
        for (int e = 0; e < EB; e++) a += xp[e]*dec_w[n*EB + e];
        sy[t] = a;
    }
    __syncthreads();
    if (t < ODIM) {
        float a = out_b[t];
        for (int tt = 0; tt < TF; tt++) a += sy[tt]*out_w[tt*ODIM + t];
        out[(b*ODIM + t)*WD + n] = a;
    }
}

// ---------------- launcher with forked-stream capture ----------------
extern "C" void kernel_launch(void* const* d_in, const int* in_sizes, int n_in,
                              void* d_out, int out_size) {
    const float* x_in  = (const float*)d_in[0];
    const float* emb_w = (const float*)d_in[1];
    const float* emb_b = (const float*)d_in[2];
    const float* g0_wf = (const float*)d_in[3];
    const float* g0_bf = (const float*)d_in[4];
    const float* g0_wg = (const float*)d_in[5];
    const float* g0_bg = (const float*)d_in[6];
    const float* g0_ws = (const float*)d_in[7];
    const float* g0_bs = (const float*)d_in[8];
    const float* a0_wq = (const float*)d_in[9];
    const float* a0_bq = (const float*)d_in[10];
    const float* a0_wk = (const float*)d_in[11];
    const float* a0_bk = (const float*)d_in[12];
    const float* a0_wv = (const float*)d_in[13];
    const float* a0_bv = (const float*)d_in[14];
    const float* g1_wf = (const float*)d_in[15];
    const float* g1_bf = (const float*)d_in[16];
    const float* g1_wg = (const float*)d_in[17];
    const float* g1_bg = (const float*)d_in[18];
    const float* g1_ws = (const float*)d_in[19];
    const float* g1_bs = (const float*)d_in[20];
    const float* a1_wq = (const float*)d_in[21];
    const float* a1_bq = (const float*)d_in[22];
    const float* a1_wk = (const float*)d_in[23];
    const float* a1_bk = (const float*)d_in[24];
    const float* a1_wv = (const float*)d_in[25];
    const float* a1_bv = (const float*)d_in[26];
    const float* dec_w = (const float*)d_in[27];
    const float* dec_b = (const float*)d_in[28];
    const float* out_w = (const float*)d_in[29];
    const float* out_b = (const float*)d_in[30];

    float *dA, *dB, *dR, *dMt, *dU, *dW, *dC, *dY;
    cudaGetSymbolAddress((void**)&dA,  g_bufA);
    cudaGetSymbolAddress((void**)&dB,  g_bufB);
    cudaGetSymbolAddress((void**)&dR,  g_bufR);
    cudaGetSymbolAddress((void**)&dMt, g_Mt);
    cudaGetSymbolAddress((void**)&dU,  g_uu);
    cudaGetSymbolAddress((void**)&dW,  g_ww);
    cudaGetSymbolAddress((void**)&dC,  g_cc);
    cudaGetSymbolAddress((void**)&dY,  g_yv);

    // side stream + events, created once (host resources, no device allocs)
    static cudaStream_t s2 = nullptr;
    static cudaEvent_t evOrigin = nullptr, evEmbed = nullptr,
                       evRes0 = nullptr, evAO0 = nullptr, evRes1 = nullptr;
    if (s2 == nullptr) {
        cudaStreamCreateWithFlags(&s2, cudaStreamNonBlocking);
        cudaEventCreateWithFlags(&evOrigin, cudaEventDisableTiming);
        cudaEventCreateWithFlags(&evEmbed,  cudaEventDisableTiming);
        cudaEventCreateWithFlags(&evRes0,   cudaEventDisableTiming);
        cudaEventCreateWithFlags(&evAO0,    cudaEventDisableTiming);
        cudaEventCreateWithFlags(&evRes1,   cudaEventDisableTiming);
    }

    // ---- fork ----
    cudaEventRecord(evOrigin, 0);
    cudaStreamWaitEvent(s2, evOrigin, 0);

    // main stream: embed
    k_embed<<<(BB*TT0*WD + 255)/256, 256>>>(x_in, emb_w, emb_b, dA);
    cudaEventRecord(evEmbed, 0);

    // side stream: attention precompute (independent), then res0 (needs embed)
    k_mt<<<dim3(64,2), 256, 0, s2>>>(a0_wq, a0_wk, a1_wq, a1_wk, dMt);
    k_uw<<<dim3(128,2), 256, 0, s2>>>(a0_wq, a0_wk, a0_bq, a0_bk,
                                      a1_wq, a1_wk, a1_bq, a1_bk, dU, dW, dC);
    cudaStreamWaitEvent(s2, evEmbed, 0);
    k_res3<128,126><<<BB*64, 256, 0, s2>>>(dA, g0_ws, g0_bs, dR);
    cudaEventRecord(evRes0, s2);

    // main stream: gated0 (runs concurrent with mt/uw/res0)
    {
        const int ntileJ = (126*16 + 63)/64;  // 32
        k_gatedg<128,126,2><<<dim3(ntileJ*2, BB), 256>>>(dA, g0_wf, g0_bf, g0_wg, g0_bg, dB);
    }
    cudaStreamWaitEvent(0, evRes0, 0);
    k_attn2<126><<<BB*126, 256>>>(dB, dR, dMt, dU, dW, dC, dY);
    k_attn_out<126><<<dim3(16, (BB*126 + 63)/64), 256>>>(dB, dR, dY, a0_wv, a0_bv, dA);
    cudaEventRecord(evAO0, 0);

    // side stream: res1 (needs attn_out0's dA; dR free after attn_out0)
    cudaStreamWaitEvent(s2, evAO0, 0);
    k_res3<126,122><<<BB*64, 256, 0, s2>>>(dA, g1_ws, g1_bs, dR);
    cudaEventRecord(evRes1, s2);

    // main stream: gated1 (concurrent with res1)
    {
        const int ntileJ = (122*16 + 63)/64;  // 31
        k_gatedg<126,122,4><<<dim3(ntileJ*2, BB), 256>>>(dA, g1_wf, g1_bf, g1_wg, g1_bg, dB);
    }
    cudaStreamWaitEvent(0, evRes1, 0);   // also joins s2 back into capture origin
    k_attn2<122><<<BB*122, 256>>>(dB, dR, dMt + WD*WD, dU + WD, dW + WD, dC + 1, dY);
    k_attn_out<122><<<dim3(16, (BB*122 + 63)/64), 256>>>(dB, dR, dY, a1_wv, a1_bv, dA);

    // decode
    k_decode<<<BB*WD, 128>>>(dA, dec_w, dec_b, out_w, out_b, (float*)d_out);
}

// round 10
// speedup vs baseline: 1.2066x; 1.2066x over previous
#include <cuda_runtime.h>
#include <math.h>

#define BB   4
#define TT0  128
#define WD   128
#define EB   16
#define LL   2048
#define ODIM 24
#define TF   122

// ---------------- scratch (no allocations allowed) ----------------
__device__ float g_bufA[BB*WD*TT0*EB];   // 4 MB
__device__ float g_bufB[BB*WD*TT0*EB];   // 4 MB
__device__ float g_Mt[2*WD*WD];          // Mt[m*128+n] = (Wq Wk^T)[n][m]
__device__ float g_uu[2*WD];             // u = Wq bk
__device__ float g_ww[2*WD];             // w = Wk bq
__device__ float g_cc[2];                // c = bq . bk
__device__ float g_yv[BB*126*WD];        // per-(b,t) y vectors

// ---------------- f32x2 packed helpers ----------------
__device__ __forceinline__ unsigned long long fma2(unsigned long long a,
                                                   unsigned long long b,
                                                   unsigned long long c) {
    unsigned long long d;
    asm("fma.rn.f32x2 %0, %1, %2, %3;" : "=l"(d) : "l"(a), "l"(b), "l"(c));
    return d;
}
__device__ __forceinline__ unsigned long long pack2(float v) {
    unsigned long long r;
    asm("mov.b64 %0, {%1, %1};" : "=l"(r) : "f"(v));
    return r;
}
__device__ __forceinline__ void unpack2(unsigned long long v, float& lo, float& hi) {
    asm("mov.b64 {%0, %1}, %2;" : "=f"(lo), "=f"(hi) : "l"(v));
}

// ---------------- embed: x_in -> (B,N,T,E) ----------------
__global__ void k_embed(const float* __restrict__ x_in,
                        const float* __restrict__ emb_w,
                        const float* __restrict__ emb_b,
                        float* __restrict__ out) {
    int idx = blockIdx.x*blockDim.x + threadIdx.x;   // over B*T*N
    if (idx >= BB*TT0*WD) return;
    int n = idx & 127;
    int t = (idx >> 7) & 127;
    int b = idx >> 14;
    const float* xi = x_in + (b*TT0 + t)*131;
    float v  = xi[n];
    float f0 = xi[128], f1 = xi[129], f2 = xi[130];
    float* o = out + ((b*WD + n)*TT0 + t)*EB;
    #pragma unroll
    for (int e = 0; e < EB; e++)
        o[e] = v*emb_w[e] + f0*emb_w[16+e] + f1*emb_w[32+e] + f2*emb_w[48+e] + emb_b[e];
}

// ---------------- precompute Mt[m*128+n] = sum_l Wq[n,l]*Wk[m,l], both layers ----------------
__global__ void k_mt(const float* __restrict__ Wq0, const float* __restrict__ Wk0,
                     const float* __restrict__ Wq1, const float* __restrict__ Wk1,
                     float* __restrict__ Mt) {
    __shared__ float Aq[16][65], Ak[16][65];
    int ly = blockIdx.y;
    const float* Wq = ly ? Wq1 : Wq0;
    const float* Wk = ly ? Wk1 : Wk0;
    float* Mto = Mt + ly*WD*WD;
    int bm = blockIdx.x >> 3, bn = blockIdx.x & 7;
    int m0 = bm*16, n0 = bn*16;
    int ty = threadIdx.x >> 4, tx = threadIdx.x & 15;  // ty -> m, tx -> n
    float acc = 0.f;
    for (int l0 = 0; l0 < LL; l0 += 64) {
        #pragma unroll
        for (int r = 0; r < 4; r++) {
            int idx = threadIdx.x + r*256;
            int row = idx >> 6, col = idx & 63;
            Aq[row][col] = Wq[(n0+row)*LL + l0 + col];
            Ak[row][col] = Wk[(m0+row)*LL + l0 + col];
        }
        __syncthreads();
        #pragma unroll
        for (int lc = 0; lc < 64; lc++)
            acc += Ak[ty][lc]*Aq[tx][lc];
        __syncthreads();
    }
    Mto[(m0+ty)*WD + (n0+tx)] = acc;
}

// ---------------- precompute u, w, c (both layers) ----------------
__global__ void k_uw(const float* __restrict__ Wq0, const float* __restrict__ Wk0,
                     const float* __restrict__ bq0, const float* __restrict__ bk0,
                     const float* __restrict__ Wq1, const float* __restrict__ Wk1,
                     const float* __restrict__ bq1, const float* __restrict__ bk1,
                     float* __restrict__ u, float* __restrict__ w, float* __restrict__ cp) {
    int ly = blockIdx.y;
    const float* Wq = ly ? Wq1 : Wq0;
    const float* Wk = ly ? Wk1 : Wk0;
    const float* bq = ly ? bq1 : bq0;
    const float* bk = ly ? bk1 : bk0;
    int n = blockIdx.x;
    __shared__ float su[256], sw[256], sc[256];
    float pu = 0.f, pw = 0.f, pc = 0.f;
    for (int l = threadIdx.x; l < LL; l += 256) {
        float bkl = bk[l], bql = bq[l];
        pu += Wq[n*LL + l]*bkl;
        pw += Wk[n*LL + l]*bql;
        if (n == 0) pc += bql*bkl;
    }
    su[threadIdx.x] = pu; sw[threadIdx.x] = pw; sc[threadIdx.x] = pc;
    __syncthreads();
    for (int s = 128; s > 0; s >>= 1) {
        if (threadIdx.x < s) {
            su[threadIdx.x] += su[threadIdx.x + s];
            sw[threadIdx.x] += sw[threadIdx.x + s];
            sc[threadIdx.x] += sc[threadIdx.x + s];
        }
        __syncthreads();
    }
    if (threadIdx.x == 0) {
        u[ly*WD + n] = su[0]; w[ly*WD + n] = sw[0];
        if (n == 0) cp[ly] = sc[0];
    }
}

// ---------------- gated conv GEMM v2: 256 thr, thread tile 2o x 8j ----------------
// j = t*16+e flattened per batch. Block tile 64o x 64j. Y = tanh(F+bf)*sigmoid(G+bg)
template<int TIN, int TOUT, int D>
__global__ void k_gatedg(const float* __restrict__ X,
                         const float* __restrict__ wf, const float* __restrict__ bf,
                         const float* __restrict__ wg, const float* __restrict__ bg,
                         float* __restrict__ Y) {
    constexpr int TIN16  = TIN*16;
    constexpr int TOUT16 = TOUT*16;
    constexpr int OFF    = 16*D;          // tap-1 column offset (32 or 64)
    __shared__ float Af[64][33];          // [o_local][kk]  kk = il*2+tap
    __shared__ float Ag[64][33];
    __shared__ float Bs[16][136];         // [il][c], c = 0..127

    int bx = blockIdx.x;
    int oB = bx & 1;                      // o-half
    int jT = bx >> 1;                     // j tile
    int b  = blockIdx.y;
    int j0b = jT*64;
    int tid = threadIdx.x;                // 256
    int jt = tid & 7;                     // j = j0b + jt*8 .. +7
    int ot = tid >> 3;                    // o_local = ot*2 .. +1

    unsigned long long fa[2][4], ga[2][4];
    #pragma unroll
    for (int oo = 0; oo < 2; oo++)
        #pragma unroll
        for (int p = 0; p < 4; p++) { fa[oo][p] = 0ull; ga[oo][p] = 0ull; }

    for (int i0 = 0; i0 < WD; i0 += 16) {
        __syncthreads();
        // stage weights (coalesced): Af[ol][kk] = wf[(oB*64+ol)*256 + i0*2 + kk]
        #pragma unroll
        for (int r = 0; r < 8; r++) {
            int idx = tid + r*256;
            int kk = idx & 31, ol = idx >> 5;
            Af[ol][kk] = wf[(oB*64 + ol)*(WD*2) + i0*2 + kk];
            Ag[ol][kk] = wg[(oB*64 + ol)*(WD*2) + i0*2 + kk];
        }
        // stage X: Bs[il][c] = X[b, i0+il, j0b + c]
        #pragma unroll
        for (int r = 0; r < 8; r++) {
            int idx = tid + r*256;
            int c = idx & 127, il = idx >> 7;
            int jg = j0b + c;
            Bs[il][c] = (jg < TIN16) ? X[((size_t)(b*WD + i0 + il))*TIN16 + jg] : 0.f;
        }
        __syncthreads();
        #pragma unroll 4
        for (int il = 0; il < 16; il++) {
            #pragma unroll
            for (int tap = 0; tap < 2; tap++) {
                int k = il*2 + tap;
                const float* bp = &Bs[il][jt*8 + tap*OFF];
                ulonglong2 q0 = *(const ulonglong2*)bp;
                ulonglong2 q1 = *(const ulonglong2*)(bp + 4);
                unsigned long long bq[4] = {q0.x, q0.y, q1.x, q1.y};
                #pragma unroll
                for (int oo = 0; oo < 2; oo++) {
                    unsigned long long paf = pack2(Af[ot*2 + oo][k]);
                    unsigned long long pag = pack2(Ag[ot*2 + oo][k]);
                    #pragma unroll
                    for (int p = 0; p < 4; p++) {
                        fa[oo][p] = fma2(paf, bq[p], fa[oo][p]);
                        ga[oo][p] = fma2(pag, bq[p], ga[oo][p]);
                    }
                }
            }
        }
    }

    int jbase = j0b + jt*8;
    if (jbase < TOUT16) {   // TOUT16 % 8 == 0 -> whole 8-j group valid
        #pragma unroll
        for (int oo = 0; oo < 2; oo++) {
            int o = oB*64 + ot*2 + oo;
            float bfo = bf[o], bgo = bg[o];
            float fv[8], gv[8];
            #pragma unroll
            for (int p = 0; p < 4; p++) {
                unpack2(fa[oo][p], fv[2*p], fv[2*p+1]);
                unpack2(ga[oo][p], gv[2*p], gv[2*p+1]);
            }
            float yv[8];
            #pragma unroll
            for (int q = 0; q < 8; q++)
                yv[q] = tanhf(fv[q] + bfo)*(1.f/(1.f + expf(-(gv[q] + bgo))));
            float* yp = Y + ((size_t)(b*WD + o))*TOUT16 + jbase;
            *(float4*)(yp)     = make_float4(yv[0], yv[1], yv[2], yv[3]);
            *(float4*)(yp + 4) = make_float4(yv[4], yv[5], yv[6], yv[7]);
        }
    }
}

// ---------------- gated residual v2: tiled smem GEMM (RPB=64, += epilogue) ----------------
template<int TIN, int TOUT>
__global__ void k_res2(const float* __restrict__ X, const float* __restrict__ ws,
                       const float* __restrict__ bs, float* __restrict__ Y) {
    constexpr int RPB = 64;
    constexpr int KC  = 32;
    __shared__ float As[KC][RPB];       // [t][row]
    __shared__ float Ws[KC][132];       // [t][s], 16B-aligned rows
    int b  = blockIdx.x >> 5;
    int r0 = (blockIdx.x & 31)*RPB;
    int tid = threadIdx.x;              // 256
    int rq = tid >> 4;                  // 0..15 -> rows rq*4..+3
    int sg = tid & 15;                  // s = sg*8 .. +7

    unsigned long long acc[4][4];
    #pragma unroll
    for (int r = 0; r < 4; r++)
        #pragma unroll
        for (int j = 0; j < 4; j++) acc[r][j] = 0ull;

    for (int t0 = 0; t0 < TIN; t0 += KC) {
        __syncthreads();
        #pragma unroll
        for (int j = 0; j < (RPB*KC)/256; j++) {
            int idx = tid + j*256;
            int row = idx & (RPB-1);
            int t = idx >> 6;
            int rr = r0 + row;
            int n = rr >> 4, e = rr & 15;
            int tg = t0 + t;
            As[t][row] = (tg < TIN) ? X[((b*WD + n)*TIN + tg)*EB + e] : 0.f;
        }
        #pragma unroll
        for (int j = 0; j < (KC*128)/256; j++) {
            int idx = tid + j*256;
            int s = idx & 127;
            int t = idx >> 7;
            int tg = t0 + t;
            Ws[t][s] = (tg < TIN && s < TOUT) ? ws[tg*TOUT + s] : 0.f;
        }
        __syncthreads();
        #pragma unroll
        for (int t = 0; t < KC; t++) {
            float4 w0 = *(const float4*)(&Ws[t][sg*8]);
            float4 w1 = *(const float4*)(&Ws[t][sg*8 + 4]);
            unsigned long long wv[4];
            wv[0] = ((unsigned long long)__float_as_uint(w0.y) << 32) | __float_as_uint(w0.x);
            wv[1] = ((unsigned long long)__float_as_uint(w0.w) << 32) | __float_as_uint(w0.z);
            wv[2] = ((unsigned long long)__float_as_uint(w1.y) << 32) | __float_as_uint(w1.x);
            wv[3] = ((unsigned long long)__float_as_uint(w1.w) << 32) | __float_as_uint(w1.z);
            #pragma unroll
            for (int r = 0; r < 4; r++) {
                unsigned long long av = pack2(As[t][rq*4 + r]);
                #pragma unroll
                for (int j = 0; j < 4; j++)
                    acc[r][j] = fma2(av, wv[j], acc[r][j]);
            }
        }
    }
    #pragma unroll
    for (int r = 0; r < 4; r++) {
        int rr = r0 + rq*4 + r;
        int n = rr >> 4, e = rr & 15;
        float* yp = Y + ((size_t)(b*WD + n)*TOUT)*EB + e;
        #pragma unroll
        for (int j = 0; j < 4; j++) {
            float lo, hi; unpack2(acc[r][j], lo, hi);
            int s0 = sg*8 + j*2;
            if (s0 < TOUT)   yp[s0*EB]       += lo + bs[s0];
            if (s0+1 < TOUT) yp[(s0+1)*EB]   += hi + bs[s0+1];
        }
    }
}

// ---------------- fused attention: Z (in-block GEMM) + softmax + ybar ----------------
template<int T>
__global__ void k_attn2(const float* __restrict__ X, const float* __restrict__ Mt,
                        const float* __restrict__ u, const float* __restrict__ w,
                        const float* __restrict__ cptr, float* __restrict__ yout) {
    __shared__ __align__(16) float Xs[WD*EB];   // [n][e] 8KB
    __shared__ __align__(16) float Ms[32*WD];   // Mt chunk [k][n] 16KB
    __shared__ float Zs[EB][WD+5];              // [f][n]
    __shared__ float Ss[EB][EB+1];
    __shared__ float uev[EB], wfv[EB], abar[EB];
    int bt = blockIdx.x;
    int b = bt / T, t = bt % T;
    int tid = threadIdx.x;                      // 256
    // load Xs (vectorized)
    for (int idx = tid; idx < WD*4; idx += 256) {
        int n = idx >> 2, q = idx & 3;
        ((float4*)Xs)[idx] = *(const float4*)(X + ((b*WD + n)*T + t)*EB + q*4);
    }
    // Z[fh*8..+7][n] per thread (n = tid&127, fh = tid>>7)
    int n_ = tid & 127, fh = tid >> 7;
    unsigned long long zacc[4] = {0ull, 0ull, 0ull, 0ull};
    for (int m0 = 0; m0 < WD; m0 += 32) {
        __syncthreads();
        #pragma unroll
        for (int rep = 0; rep < (32*WD/4)/256; rep++)
            ((float4*)Ms)[tid + rep*256] = ((const float4*)(Mt + m0*WD))[tid + rep*256];
        __syncthreads();
        #pragma unroll
        for (int k = 0; k < 32; k++) {
            unsigned long long pm = pack2(Ms[k*WD + n_]);
            const ulonglong2* xp = (const ulonglong2*)(Xs + (m0 + k)*16 + fh*8);
            ulonglong2 xa = xp[0];
            zacc[0] = fma2(pm, xa.x, zacc[0]);
            zacc[1] = fma2(pm, xa.y, zacc[1]);
            ulonglong2 xb = xp[1];
            zacc[2] = fma2(pm, xb.x, zacc[2]);
            zacc[3] = fma2(pm, xb.y, zacc[3]);
        }
    }
    #pragma unroll
    for (int j = 0; j < 4; j++) {
        float lo, hi; unpack2(zacc[j], lo, hi);
        Zs[fh*8 + 2*j][n_]     = lo;
        Zs[fh*8 + 2*j + 1][n_] = hi;
    }
    if (tid < 16) {
        float a = 0.f;
        for (int n = 0; n < WD; n++) a += Xs[n*16 + tid]*u[n];
        uev[tid] = a;
    } else if (tid < 32) {
        int f = tid - 16;
        float a = 0.f;
        for (int n = 0; n < WD; n++) a += Xs[n*16 + f]*w[n];
        wfv[f] = a;
    }
    __syncthreads();
    {
        int e = tid >> 4, f = tid & 15;
        float acc = 0.f;
        #pragma unroll 4
        for (int n = 0; n < WD; n++)
            acc += Xs[n*16 + e]*Zs[f][n];
        const float scale = 0.022097086912079608f; // 1/sqrt(2048)
        Ss[e][f] = (acc + uev[e] + wfv[f] + cptr[0])*scale;
    }
    __syncthreads();
    if (tid < 16) {
        int e = tid;
        float mx = -1e30f;
        #pragma unroll
        for (int f = 0; f < 16; f++) mx = fmaxf(mx, Ss[e][f]);
        float ex[16]; float sum = 0.f;
        #pragma unroll
        for (int f = 0; f < 16; f++) { ex[f] = expf(Ss[e][f] - mx); sum += ex[f]; }
        float inv = 1.f/sum;
        #pragma unroll
        for (int f = 0; f < 16; f++) Ss[e][f] = ex[f]*inv;
    }
    __syncthreads();
    if (tid < 16) {
        int f = tid;
        float a = 0.f;
        #pragma unroll
        for (int e = 0; e < 16; e++) a += Ss[e][f];
        abar[f] = a*(1.f/16.f);
    }
    __syncthreads();
    if (tid < 128) {
        int n = tid;
        float a = 0.f;
        #pragma unroll
        for (int f = 0; f < 16; f++) a += Xs[n*16 + f]*abar[f];
        yout[bt*WD + n] = a;
    }
}

// ---------------- attention out: Y = X + y @ Wv + bv ----------------
template<int T>
__global__ void k_attn_out(const float* __restrict__ Xin, const float* __restrict__ yv,
                           const float* __restrict__ Wv, const float* __restrict__ bv,
                           float* __restrict__ Yout) {
    __shared__ float ys[64][WD];
    const int BT = BB*T;
    int bt0 = blockIdx.y*64;
    int l = blockIdx.x*128 + (threadIdx.x & 127);
    int half = threadIdx.x >> 7;
    for (int idx = threadIdx.x; idx < 64*WD; idx += 256) {
        int r = idx >> 7, m = idx & 127;
        int bt = bt0 + r;
        ys[r][m] = (bt < BT) ? yv[bt*WD + m] : 0.f;
    }
    __syncthreads();
    float acc[32];
    #pragma unroll
    for (int j = 0; j < 32; j++) acc[j] = 0.f;
    for (int m = 0; m < WD; m++) {
        float wvv = Wv[m*LL + l];
        #pragma unroll
        for (int j = 0; j < 32; j++) acc[j] += ys[half*32 + j][m]*wvv;
    }
    float bvl = bv[l];
    int n = l >> 4, e = l & 15;
    #pragma unroll
    for (int j = 0; j < 32; j++) {
        int bt = bt0 + half*32 + j;
        if (bt < BT) {
            int b = bt / T, t = bt % T;
            int idx = ((b*WD + n)*T + t)*EB + e;
            Yout[idx] = Xin[idx] + acc[j] + bvl;
        }
    }
}

// ---------------- decode + time-mix output ----------------
__global__ void k_decode(const float* __restrict__ X, const float* __restrict__ dec_w,
                         const float* __restrict__ dec_b, const float* __restrict__ out_w,
                         const float* __restrict__ out_b, float* __restrict__ out) {
    __shared__ float sy[TF];
    int b = blockIdx.x >> 7, n = blockIdx.x & 127;
    int t = threadIdx.x;
    if (t < TF) {
        const float* xp = X + ((size_t)(b*WD + n)*TF + t)*EB;
        float a = dec_b[n];
        #pragma unroll
        for (int e = 0; e < EB; e++) a += xp[e]*dec_w[n*EB + e];
        sy[t] = a;
    }
    __syncthreads();
    if (t < ODIM) {
        float a = out_b[t];
        for (int tt = 0; tt < TF; tt++) a += sy[tt]*out_w[tt*ODIM + t];
        out[(b*ODIM + t)*WD + n] = a;
    }
}

// ---------------- launcher (serial stream, Round-8 structure) ----------------
extern "C" void kernel_launch(void* const* d_in, const int* in_sizes, int n_in,
                              void* d_out, int out_size) {
    const float* x_in  = (const float*)d_in[0];
    const float* emb_w = (const float*)d_in[1];
    const float* emb_b = (const float*)d_in[2];
    const float* g0_wf = (const float*)d_in[3];
    const float* g0_bf = (const float*)d_in[4];
    const float* g0_wg = (const float*)d_in[5];
    const float* g0_bg = (const float*)d_in[6];
    const float* g0_ws = (const float*)d_in[7];
    const float* g0_bs = (const float*)d_in[8];
    const float* a0_wq = (const float*)d_in[9];
    const float* a0_bq = (const float*)d_in[10];
    const float* a0_wk = (const float*)d_in[11];
    const float* a0_bk = (const float*)d_in[12];
    const float* a0_wv = (const float*)d_in[13];
    const float* a0_bv = (const float*)d_in[14];
    const float* g1_wf = (const float*)d_in[15];
    const float* g1_bf = (const float*)d_in[16];
    const float* g1_wg = (const float*)d_in[17];
    const float* g1_bg = (const float*)d_in[18];
    const float* g1_ws = (const float*)d_in[19];
    const float* g1_bs = (const float*)d_in[20];
    const float* a1_wq = (const float*)d_in[21];
    const float* a1_bq = (const float*)d_in[22];
    const float* a1_wk = (const float*)d_in[23];
    const float* a1_bk = (const float*)d_in[24];
    const float* a1_wv = (const float*)d_in[25];
    const float* a1_bv = (const float*)d_in[26];
    const float* dec_w = (const float*)d_in[27];
    const float* dec_b = (const float*)d_in[28];
    const float* out_w = (const float*)d_in[29];
    const float* out_b = (const float*)d_in[30];

    float *dA, *dB, *dMt, *dU, *dW, *dC, *dY;
    cudaGetSymbolAddress((void**)&dA,  g_bufA);
    cudaGetSymbolAddress((void**)&dB,  g_bufB);
    cudaGetSymbolAddress((void**)&dMt, g_Mt);
    cudaGetSymbolAddress((void**)&dU,  g_uu);
    cudaGetSymbolAddress((void**)&dW,  g_ww);
    cudaGetSymbolAddress((void**)&dC,  g_cc);
    cudaGetSymbolAddress((void**)&dY,  g_yv);

    // embed + attention precompute (merged launches)
    k_embed<<<(BB*TT0*WD + 255)/256, 256>>>(x_in, emb_w, emb_b, dA);
    k_mt<<<dim3(64,2), 256>>>(a0_wq, a0_wk, a1_wq, a1_wk, dMt);
    k_uw<<<dim3(128,2), 256>>>(a0_wq, a0_wk, a0_bq, a0_bk,
                               a1_wq, a1_wk, a1_bq, a1_bk, dU, dW, dC);

    // layer 0: gated (TIN=128 -> 126, d=2), attention T=126
    {
        const int ntileJ = (126*16 + 63)/64;  // 32
        k_gatedg<128,126,2><<<dim3(ntileJ*2, BB), 256>>>(dA, g0_wf, g0_bf, g0_wg, g0_bg, dB);
        k_res2<128,126><<<BB*32, 256>>>(dA, g0_ws, g0_bs, dB);
        k_attn2<126><<<BB*126, 256>>>(dB, dMt, dU, dW, dC, dY);
        k_attn_out<126><<<dim3(16, (BB*126 + 63)/64), 256>>>(dB, dY, a0_wv, a0_bv, dA);
    }

    // layer 1: gated (TIN=126 -> 122, d=4), attention T=122
    {
        const int ntileJ = (122*16 + 63)/64;  // 31
        k_gatedg<126,122,4><<<dim3(ntileJ*2, BB), 256>>>(dA, g1_wf, g1_bf, g1_wg, g1_bg, dB);
        k_res2<126,122><<<BB*32, 256>>>(dA, g1_ws, g1_bs, dB);
        k_attn2<122><<<BB*122, 256>>>(dB, dMt + WD*WD, dU + WD, dW + WD, dC + 1, dY);
        k_attn_out<122><<<dim3(16, (BB*122 + 63)/64), 256>>>(dB, dY, a1_wv, a1_bv, dA);
    }

    // decode
    k_decode<<<BB*WD, 128>>>(dA, dec_w, dec_b, out_w, out_b, (float*)d_out);
}

// round 11
// speedup vs baseline: 1.3096x; 1.0854x over previous
#include <cuda_runtime.h>
#include <math.h>

#define BB   4
#define TT0  128
#define WD   128
#define EB   16
#define LL   2048
#define ODIM 24
#define TF   122

// ---------------- scratch (no allocations allowed) ----------------
__device__ float g_bufA[BB*WD*TT0*EB];   // 4 MB
__device__ float g_bufB[BB*WD*TT0*EB];   // 4 MB
__device__ float g_Mt[2*WD*WD];          // Mt[m*128+n] = (Wq Wk^T)[n][m]
__device__ float g_uu[2*WD];             // u = Wq bk
__device__ float g_ww[2*WD];             // w = Wk bq
__device__ float g_cc[2];                // c = bq . bk
__device__ float g_yv[BB*126*WD];        // per-(b,t) y vectors

// ---------------- f32x2 packed helpers ----------------
__device__ __forceinline__ unsigned long long fma2(unsigned long long a,
                                                   unsigned long long b,
                                                   unsigned long long c) {
    unsigned long long d;
    asm("fma.rn.f32x2 %0, %1, %2, %3;" : "=l"(d) : "l"(a), "l"(b), "l"(c));
    return d;
}
__device__ __forceinline__ unsigned long long pack2(float v) {
    unsigned long long r;
    asm("mov.b64 %0, {%1, %1};" : "=l"(r) : "f"(v));
    return r;
}
__device__ __forceinline__ void unpack2(unsigned long long v, float& lo, float& hi) {
    asm("mov.b64 {%0, %1}, %2;" : "=f"(lo), "=f"(hi) : "l"(v));
}

// ---------------- embed: x_in -> (B,N,T,E) ----------------
__global__ void k_embed(const float* __restrict__ x_in,
                        const float* __restrict__ emb_w,
                        const float* __restrict__ emb_b,
                        float* __restrict__ out) {
    int idx = blockIdx.x*blockDim.x + threadIdx.x;   // over B*T*N
    if (idx >= BB*TT0*WD) return;
    int n = idx & 127;
    int t = (idx >> 7) & 127;
    int b = idx >> 14;
    const float* xi = x_in + (b*TT0 + t)*131;
    float v  = xi[n];
    float f0 = xi[128], f1 = xi[129], f2 = xi[130];
    float* o = out + ((b*WD + n)*TT0 + t)*EB;
    #pragma unroll
    for (int e = 0; e < EB; e++)
        o[e] = v*emb_w[e] + f0*emb_w[16+e] + f1*emb_w[32+e] + f2*emb_w[48+e] + emb_b[e];
}

// ---------------- precompute Mt[m*128+n] = sum_l Wq[n,l]*Wk[m,l], both layers ----------------
__global__ void k_mt(const float* __restrict__ Wq0, const float* __restrict__ Wk0,
                     const float* __restrict__ Wq1, const float* __restrict__ Wk1,
                     float* __restrict__ Mt) {
    __shared__ float Aq[16][65], Ak[16][65];
    int ly = blockIdx.y;
    const float* Wq = ly ? Wq1 : Wq0;
    const float* Wk = ly ? Wk1 : Wk0;
    float* Mto = Mt + ly*WD*WD;
    int bm = blockIdx.x >> 3, bn = blockIdx.x & 7;
    int m0 = bm*16, n0 = bn*16;
    int ty = threadIdx.x >> 4, tx = threadIdx.x & 15;  // ty -> m, tx -> n
    float acc = 0.f;
    for (int l0 = 0; l0 < LL; l0 += 64) {
        #pragma unroll
        for (int r = 0; r < 4; r++) {
            int idx = threadIdx.x + r*256;
            int row = idx >> 6, col = idx & 63;
            Aq[row][col] = Wq[(n0+row)*LL + l0 + col];
            Ak[row][col] = Wk[(m0+row)*LL + l0 + col];
        }
        __syncthreads();
        #pragma unroll
        for (int lc = 0; lc < 64; lc++)
            acc += Ak[ty][lc]*Aq[tx][lc];
        __syncthreads();
    }
    Mto[(m0+ty)*WD + (n0+tx)] = acc;
}

// ---------------- precompute u, w, c (both layers) ----------------
__global__ void k_uw(const float* __restrict__ Wq0, const float* __restrict__ Wk0,
                     const float* __restrict__ bq0, const float* __restrict__ bk0,
                     const float* __restrict__ Wq1, const float* __restrict__ Wk1,
                     const float* __restrict__ bq1, const float* __restrict__ bk1,
                     float* __restrict__ u, float* __restrict__ w, float* __restrict__ cp) {
    int ly = blockIdx.y;
    const float* Wq = ly ? Wq1 : Wq0;
    const float* Wk = ly ? Wk1 : Wk0;
    const float* bq = ly ? bq1 : bq0;
    const float* bk = ly ? bk1 : bk0;
    int n = blockIdx.x;
    __shared__ float su[256], sw[256], sc[256];
    float pu = 0.f, pw = 0.f, pc = 0.f;
    for (int l = threadIdx.x; l < LL; l += 256) {
        float bkl = bk[l], bql = bq[l];
        pu += Wq[n*LL + l]*bkl;
        pw += Wk[n*LL + l]*bql;
        if (n == 0) pc += bql*bkl;
    }
    su[threadIdx.x] = pu; sw[threadIdx.x] = pw; sc[threadIdx.x] = pc;
    __syncthreads();
    for (int s = 128; s > 0; s >>= 1) {
        if (threadIdx.x < s) {
            su[threadIdx.x] += su[threadIdx.x + s];
            sw[threadIdx.x] += sw[threadIdx.x + s];
            sc[threadIdx.x] += sc[threadIdx.x + s];
        }
        __syncthreads();
    }
    if (threadIdx.x == 0) {
        u[ly*WD + n] = su[0]; w[ly*WD + n] = sw[0];
        if (n == 0) cp[ly] = sc[0];
    }
}

// ---------------- gated conv GEMM v1 + double-buffered pipeline ----------------
// j = t*16+e flattened per batch. Block tile 64o x 64j, thread 4o x 8j, 128 thr.
// Y[o,j] = tanh(F+bf)*sigmoid(G+bg)
template<int TIN, int TOUT, int D>
__global__ void k_gatedg(const float* __restrict__ X,
                         const float* __restrict__ wf, const float* __restrict__ bf,
                         const float* __restrict__ wg, const float* __restrict__ bg,
                         float* __restrict__ Y) {
    constexpr int TIN16  = TIN*16;
    constexpr int TOUT16 = TOUT*16;
    constexpr int OFF    = 16*D;          // tap-1 column offset (32 or 64)
    constexpr int AFS    = 64*33;         // Af/Ag floats per buffer
    constexpr int BSS    = 16*136;        // Bs floats per buffer
    constexpr int STRIDE = 2*AFS + BSS;   // 6400 floats per buffer
    extern __shared__ float sm[];         // 2*STRIDE floats = 51200 bytes

    int bx = blockIdx.x;
    int oB = bx & 1;                      // o-half
    int jT = bx >> 1;                     // j tile
    int b  = blockIdx.y;
    int j0b = jT*64;
    int tid = threadIdx.x;                // 128
    int jt = tid & 7;                     // j-group: j = j0b + jt*8 .. +7
    int ot = tid >> 3;                    // o-group: o_local = ot*4 .. +3

    unsigned long long fa[4][4], ga[4][4];
    #pragma unroll
    for (int oo = 0; oo < 4; oo++)
        #pragma unroll
        for (int p = 0; p < 4; p++) { fa[oo][p] = 0ull; ga[oo][p] = 0ull; }

    // stage chunk i0 into buffer buf
    auto stage = [&](int i0, int buf) {
        float* Af_ = sm + buf*STRIDE;
        float* Ag_ = Af_ + AFS;
        float* Bs_ = Ag_ + AFS;
        #pragma unroll
        for (int r = 0; r < 16; r++) {     // 64 ol x 32 kk
            int idx = tid + r*128;
            int kk = idx & 31, ol = idx >> 5;
            Af_[ol*33 + kk] = wf[(oB*64 + ol)*(WD*2) + i0*2 + kk];
            Ag_[ol*33 + kk] = wg[(oB*64 + ol)*(WD*2) + i0*2 + kk];
        }
        #pragma unroll
        for (int r = 0; r < 16; r++) {     // 16 il x 128 c
            int idx = tid + r*128;
            int c = idx & 127, il = idx >> 7;
            int jg = j0b + c;
            Bs_[il*136 + c] = (jg < TIN16) ? X[((size_t)(b*WD + i0 + il))*TIN16 + jg] : 0.f;
        }
    };

    stage(0, 0);
    __syncthreads();

    #pragma unroll
    for (int ch = 0; ch < 8; ch++) {
        int cur = ch & 1;
        if (ch < 7) stage((ch + 1)*16, cur ^ 1);   // prefetch next chunk (no sync yet)

        const float* Af_ = sm + cur*STRIDE;
        const float* Ag_ = Af_ + AFS;
        const float* Bs_ = Ag_ + AFS;
        #pragma unroll 4
        for (int il = 0; il < 16; il++) {
            #pragma unroll
            for (int tap = 0; tap < 2; tap++) {
                int k = il*2 + tap;
                const float* bp = Bs_ + il*136 + jt*8 + tap*OFF;
                ulonglong2 q0 = *(const ulonglong2*)bp;
                ulonglong2 q1 = *(const ulonglong2*)(bp + 4);
                unsigned long long bq[4] = {q0.x, q0.y, q1.x, q1.y};
                #pragma unroll
                for (int oo = 0; oo < 4; oo++) {
                    unsigned long long paf = pack2(Af_[(ot*4 + oo)*33 + k]);
                    unsigned long long pag = pack2(Ag_[(ot*4 + oo)*33 + k]);
                    #pragma unroll
                    for (int p = 0; p < 4; p++) {
                        fa[oo][p] = fma2(paf, bq[p], fa[oo][p]);
                        ga[oo][p] = fma2(pag, bq[p], ga[oo][p]);
                    }
                }
            }
        }
        __syncthreads();   // compute(cur) done + stage(nxt) stores visible
    }

    int jbase = j0b + jt*8;
    if (jbase < TOUT16) {   // TOUT16 % 8 == 0 -> whole 8-j group valid
        #pragma unroll
        for (int oo = 0; oo < 4; oo++) {
            int o = oB*64 + ot*4 + oo;
            float bfo = bf[o], bgo = bg[o];
            float fv[8], gv[8];
            #pragma unroll
            for (int p = 0; p < 4; p++) {
                unpack2(fa[oo][p], fv[2*p], fv[2*p+1]);
                unpack2(ga[oo][p], gv[2*p], gv[2*p+1]);
            }
            float yv[8];
            #pragma unroll
            for (int q = 0; q < 8; q++)
                yv[q] = tanhf(fv[q] + bfo)*(1.f/(1.f + expf(-(gv[q] + bgo))));
            float* yp = Y + ((size_t)(b*WD + o))*TOUT16 + jbase;
            *(float4*)(yp)     = make_float4(yv[0], yv[1], yv[2], yv[3]);
            *(float4*)(yp + 4) = make_float4(yv[4], yv[5], yv[6], yv[7]);
        }
    }
}

// ---------------- gated residual v2: tiled smem GEMM (RPB=64, += epilogue) ----------------
template<int TIN, int TOUT>
__global__ void k_res2(const float* __restrict__ X, const float* __restrict__ ws,
                       const float* __restrict__ bs, float* __restrict__ Y) {
    constexpr int RPB = 64;
    constexpr int KC  = 32;
    __shared__ float As[KC][RPB];       // [t][row]
    __shared__ float Ws[KC][132];       // [t][s], 16B-aligned rows
    int b  = blockIdx.x >> 5;
    int r0 = (blockIdx.x & 31)*RPB;
    int tid = threadIdx.x;              // 256
    int rq = tid >> 4;                  // 0..15 -> rows rq*4..+3
    int sg = tid & 15;                  // s = sg*8 .. +7

    unsigned long long acc[4][4];
    #pragma unroll
    for (int r = 0; r < 4; r++)
        #pragma unroll
        for (int j = 0; j < 4; j++) acc[r][j] = 0ull;

    for (int t0 = 0; t0 < TIN; t0 += KC) {
        __syncthreads();
        #pragma unroll
        for (int j = 0; j < (RPB*KC)/256; j++) {
            int idx = tid + j*256;
            int row = idx & (RPB-1);
            int t = idx >> 6;
            int rr = r0 + row;
            int n = rr >> 4, e = rr & 15;
            int tg = t0 + t;
            As[t][row] = (tg < TIN) ? X[((b*WD + n)*TIN + tg)*EB + e] : 0.f;
        }
        #pragma unroll
        for (int j = 0; j < (KC*128)/256; j++) {
            int idx = tid + j*256;
            int s = idx & 127;
            int t = idx >> 7;
            int tg = t0 + t;
            Ws[t][s] = (tg < TIN && s < TOUT) ? ws[tg*TOUT + s] : 0.f;
        }
        __syncthreads();
        #pragma unroll
        for (int t = 0; t < KC; t++) {
            float4 w0 = *(const float4*)(&Ws[t][sg*8]);
            float4 w1 = *(const float4*)(&Ws[t][sg*8 + 4]);
            unsigned long long wv[4];
            wv[0] = ((unsigned long long)__float_as_uint(w0.y) << 32) | __float_as_uint(w0.x);
            wv[1] = ((unsigned long long)__float_as_uint(w0.w) << 32) | __float_as_uint(w0.z);
            wv[2] = ((unsigned long long)__float_as_uint(w1.y) << 32) | __float_as_uint(w1.x);
            wv[3] = ((unsigned long long)__float_as_uint(w1.w) << 32) | __float_as_uint(w1.z);
            #pragma unroll
            for (int r = 0; r < 4; r++) {
                unsigned long long av = pack2(As[t][rq*4 + r]);
                #pragma unroll
                for (int j = 0; j < 4; j++)
                    acc[r][j] = fma2(av, wv[j], acc[r][j]);
            }
        }
    }
    #pragma unroll
    for (int r = 0; r < 4; r++) {
        int rr = r0 + rq*4 + r;
        int n = rr >> 4, e = rr & 15;
        float* yp = Y + ((size_t)(b*WD + n)*TOUT)*EB + e;
        #pragma unroll
        for (int j = 0; j < 4; j++) {
            float lo, hi; unpack2(acc[r][j], lo, hi);
            int s0 = sg*8 + j*2;
            if (s0 < TOUT)   yp[s0*EB]       += lo + bs[s0];
            if (s0+1 < TOUT) yp[(s0+1)*EB]   += hi + bs[s0+1];
        }
    }
}

// ---------------- fused attention: Z (in-block GEMM) + softmax + ybar ----------------
template<int T>
__global__ void k_attn2(const float* __restrict__ X, const float* __restrict__ Mt,
                        const float* __restrict__ u, const float* __restrict__ w,
                        const float* __restrict__ cptr, float* __restrict__ yout) {
    __shared__ __align__(16) float Xs[WD*EB];   // [n][e] 8KB
    __shared__ __align__(16) float Ms[32*WD];   // Mt chunk [k][n] 16KB
    __shared__ float Zs[EB][WD+5];              // [f][n]
    __shared__ float Ss[EB][EB+1];
    __shared__ float uev[EB], wfv[EB], abar[EB];
    int bt = blockIdx.x;
    int b = bt / T, t = bt % T;
    int tid = threadIdx.x;                      // 256
    // load Xs (vectorized)
    for (int idx = tid; idx < WD*4; idx += 256) {
        int n = idx >> 2, q = idx & 3;
        ((float4*)Xs)[idx] = *(const float4*)(X + ((b*WD + n)*T + t)*EB + q*4);
    }
    // Z[fh*8..+7][n] per thread (n = tid&127, fh = tid>>7)
    int n_ = tid & 127, fh = tid >> 7;
    unsigned long long zacc[4] = {0ull, 0ull, 0ull, 0ull};
    for (int m0 = 0; m0 < WD; m0 += 32) {
        __syncthreads();
        #pragma unroll
        for (int rep = 0; rep < (32*WD/4)/256; rep++)
            ((float4*)Ms)[tid + rep*256] = ((const float4*)(Mt + m0*WD))[tid + rep*256];
        __syncthreads();
        #pragma unroll
        for (int k = 0; k < 32; k++) {
            unsigned long long pm = pack2(Ms[k*WD + n_]);
            const ulonglong2* xp = (const ulonglong2*)(Xs + (m0 + k)*16 + fh*8);
            ulonglong2 xa = xp[0];
            zacc[0] = fma2(pm, xa.x, zacc[0]);
            zacc[1] = fma2(pm, xa.y, zacc[1]);
            ulonglong2 xb = xp[1];
            zacc[2] = fma2(pm, xb.x, zacc[2]);
            zacc[3] = fma2(pm, xb.y, zacc[3]);
        }
    }
    #pragma unroll
    for (int j = 0; j < 4; j++) {
        float lo, hi; unpack2(zacc[j], lo, hi);
        Zs[fh*8 + 2*j][n_]     = lo;
        Zs[fh*8 + 2*j + 1][n_] = hi;
    }
    if (tid < 16) {
        float a = 0.f;
        for (int n = 0; n < WD; n++) a += Xs[n*16 + tid]*u[n];
        uev[tid] = a;
    } else if (tid < 32) {
        int f = tid - 16;
        float a = 0.f;
        for (int n = 0; n < WD; n++) a += Xs[n*16 + f]*w[n];
        wfv[f] = a;
    }
    __syncthreads();
    {
        int e = tid >> 4, f = tid & 15;
        float acc = 0.f;
        #pragma unroll 4
        for (int n = 0; n < WD; n++)
            acc += Xs[n*16 + e]*Zs[f][n];
        const float scale = 0.022097086912079608f; // 1/sqrt(2048)
        Ss[e][f] = (acc + uev[e] + wfv[f] + cptr[0])*scale;
    }
    __syncthreads();
    if (tid < 16) {
        int e = tid;
        float mx = -1e30f;
        #pragma unroll
        for (int f = 0; f < 16; f++) mx = fmaxf(mx, Ss[e][f]);
        float ex[16]; float sum = 0.f;
        #pragma unroll
        for (int f = 0; f < 16; f++) { ex[f] = expf(Ss[e][f] - mx); sum += ex[f]; }
        float inv = 1.f/sum;
        #pragma unroll
        for (int f = 0; f < 16; f++) Ss[e][f] = ex[f]*inv;
    }
    __syncthreads();
    if (tid < 16) {
        int f = tid;
        float a = 0.f;
        #pragma unroll
        for (int e = 0; e < 16; e++) a += Ss[e][f];
        abar[f] = a*(1.f/16.f);
    }
    __syncthreads();
    if (tid < 128) {
        int n = tid;
        float a = 0.f;
        #pragma unroll
        for (int f = 0; f < 16; f++) a += Xs[n*16 + f]*abar[f];
        yout[bt*WD + n] = a;
    }
}

// ---------------- attention out: Y = X + y @ Wv + bv ----------------
template<int T>
__global__ void k_attn_out(const float* __restrict__ Xin, const float* __restrict__ yv,
                           const float* __restrict__ Wv, const float* __restrict__ bv,
                           float* __restrict__ Yout) {
    __shared__ float ys[64][WD];
    const int BT = BB*T;
    int bt0 = blockIdx.y*64;
    int l = blockIdx.x*128 + (threadIdx.x & 127);
    int half = threadIdx.x >> 7;
    for (int idx = threadIdx.x; idx < 64*WD; idx += 256) {
        int r = idx >> 7, m = idx & 127;
        int bt = bt0 + r;
        ys[r][m] = (bt < BT) ? yv[bt*WD + m] : 0.f;
    }
    __syncthreads();
    float acc[32];
    #pragma unroll
    for (int j = 0; j < 32; j++) acc[j] = 0.f;
    for (int m = 0; m < WD; m++) {
        float wvv = Wv[m*LL + l];
        #pragma unroll
        for (int j = 0; j < 32; j++) acc[j] += ys[half*32 + j][m]*wvv;
    }
    float bvl = bv[l];
    int n = l >> 4, e = l & 15;
    #pragma unroll
    for (int j = 0; j < 32; j++) {
        int bt = bt0 + half*32 + j;
        if (bt < BT) {
            int b = bt / T, t = bt % T;
            int idx = ((b*WD + n)*T + t)*EB + e;
            Yout[idx] = Xin[idx] + acc[j] + bvl;
        }
    }
}

// ---------------- decode + time-mix output ----------------
__global__ void k_decode(const float* __restrict__ X, const float* __restrict__ dec_w,
                         const float* __restrict__ dec_b, const float* __restrict__ out_w,
                         const float* __restrict__ out_b, float* __restrict__ out) {
    __shared__ float sy[TF];
    int b = blockIdx.x >> 7, n = blockIdx.x & 127;
    int t = threadIdx.x;
    if (t < TF) {
        const float* xp = X + ((size_t)(b*WD + n)*TF + t)*EB;
        float a = dec_b[n];
        #pragma unroll
        for (int e = 0; e < EB; e++) a += xp[e]*dec_w[n*EB + e];
        sy[t] = a;
    }
    __syncthreads();
    if (t < ODIM) {
        float a = out_b[t];
        for (int tt = 0; tt < TF; tt++) a += sy[tt]*out_w[tt*ODIM + t];
        out[(b*ODIM + t)*WD + n] = a;
    }
}

// ---------------- launcher (serial stream, Round-8 structure) ----------------
extern "C" void kernel_launch(void* const* d_in, const int* in_sizes, int n_in,
                              void* d_out, int out_size) {
    const float* x_in  = (const float*)d_in[0];
    const float* emb_w = (const float*)d_in[1];
    const float* emb_b = (const float*)d_in[2];
    const float* g0_wf = (const float*)d_in[3];
    const float* g0_bf = (const float*)d_in[4];
    const float* g0_wg = (const float*)d_in[5];
    const float* g0_bg = (const float*)d_in[6];
    const float* g0_ws = (const float*)d_in[7];
    const float* g0_bs = (const float*)d_in[8];
    const float* a0_wq = (const float*)d_in[9];
    const float* a0_bq = (const float*)d_in[10];
    const float* a0_wk = (const float*)d_in[11];
    const float* a0_bk = (const float*)d_in[12];
    const float* a0_wv = (const float*)d_in[13];
    const float* a0_bv = (const float*)d_in[14];
    const float* g1_wf = (const float*)d_in[15];
    const float* g1_bf = (const float*)d_in[16];
    const float* g1_wg = (const float*)d_in[17];
    const float* g1_bg = (const float*)d_in[18];
    const float* g1_ws = (const float*)d_in[19];
    const float* g1_bs = (const float*)d_in[20];
    const float* a1_wq = (const float*)d_in[21];
    const float* a1_bq = (const float*)d_in[22];
    const float* a1_wk = (const float*)d_in[23];
    const float* a1_bk = (const float*)d_in[24];
    const float* a1_wv = (const float*)d_in[25];
    const float* a1_bv = (const float*)d_in[26];
    const float* dec_w = (const float*)d_in[27];
    const float* dec_b = (const float*)d_in[28];
    const float* out_w = (const float*)d_in[29];
    const float* out_b = (const float*)d_in[30];

    float *dA, *dB, *dMt, *dU, *dW, *dC, *dY;
    cudaGetSymbolAddress((void**)&dA,  g_bufA);
    cudaGetSymbolAddress((void**)&dB,  g_bufB);
    cudaGetSymbolAddress((void**)&dMt, g_Mt);
    cudaGetSymbolAddress((void**)&dU,  g_uu);
    cudaGetSymbolAddress((void**)&dW,  g_ww);
    cudaGetSymbolAddress((void**)&dC,  g_cc);
    cudaGetSymbolAddress((void**)&dY,  g_yv);

    // double-buffered smem: 2*(2*64*33 + 16*136)*4 = 51200 bytes
    const int SMEM_G = 2*(2*64*33 + 16*136)*4;
    cudaFuncSetAttribute(k_gatedg<128,126,2>, cudaFuncAttributeMaxDynamicSharedMemorySize, SMEM_G);
    cudaFuncSetAttribute(k_gatedg<126,122,4>, cudaFuncAttributeMaxDynamicSharedMemorySize, SMEM_G);

    // embed + attention precompute (merged launches)
    k_embed<<<(BB*TT0*WD + 255)/256, 256>>>(x_in, emb_w, emb_b, dA);
    k_mt<<<dim3(64,2), 256>>>(a0_wq, a0_wk, a1_wq, a1_wk, dMt);
    k_uw<<<dim3(128,2), 256>>>(a0_wq, a0_wk, a0_bq, a0_bk,
                               a1_wq, a1_wk, a1_bq, a1_bk, dU, dW, dC);

    // layer 0: gated (TIN=128 -> 126, d=2), attention T=126
    {
        const int ntileJ = (126*16 + 63)/64;  // 32
        k_gatedg<128,126,2><<<dim3(ntileJ*2, BB), 128, SMEM_G>>>(dA, g0_wf, g0_bf, g0_wg, g0_bg, dB);
        k_res2<128,126><<<BB*32, 256>>>(dA, g0_ws, g0_bs, dB);
        k_attn2<126><<<BB*126, 256>>>(dB, dMt, dU, dW, dC, dY);
        k_attn_out<126><<<dim3(16, (BB*126 + 63)/64), 256>>>(dB, dY, a0_wv, a0_bv, dA);
    }

    // layer 1: gated (TIN=126 -> 122, d=4), attention T=122
    {
        const int ntileJ = (122*16 + 63)/64;  // 31
        k_gatedg<126,122,4><<<dim3(ntileJ*2, BB), 128, SMEM_G>>>(dA, g1_wf, g1_bf, g1_wg, g1_bg, dB);
        k_res2<126,122><<<BB*32, 256>>>(dA, g1_ws, g1_bs, dB);
        k_attn2<122><<<BB*122, 256>>>(dB, dMt + WD*WD, dU + WD, dW + WD, dC + 1, dY);
        k_attn_out<122><<<dim3(16, (BB*122 + 63)/64), 256>>>(dB, dY, a1_wv, a1_bv, dA);
    }

    // decode
    k_decode<<<BB*WD, 128>>>(dA, dec_w, dec_b, out_w, out_b, (float*)d_out);
}

// round 12
// speedup vs baseline: 1.4079x; 1.0751x over previous
#include <cuda_runtime.h>
#include <math.h>

#define BB   4
#define TT0  128
#define WD   128
#define EB   16
#define LL   2048
#define ODIM 24
#define TF   122

// ---------------- scratch (no allocations allowed) ----------------
__device__ float g_bufA[BB*WD*TT0*EB];   // 4 MB
__device__ float g_bufB[BB*WD*TT0*EB];   // 4 MB
__device__ float g_Mt[2*WD*WD];          // Mt[m*128+n] = (Wq Wk^T)[n][m]
__device__ float g_uu[2*WD];             // u = Wq bk
__device__ float g_ww[2*WD];             // w = Wk bq
__device__ float g_cc[2];                // c = bq . bk
__device__ float g_yv[BB*126*WD];        // per-(b,t) y vectors

// ---------------- f32x2 packed helpers ----------------
__device__ __forceinline__ unsigned long long fma2(unsigned long long a,
                                                   unsigned long long b,
                                                   unsigned long long c) {
    unsigned long long d;
    asm("fma.rn.f32x2 %0, %1, %2, %3;" : "=l"(d) : "l"(a), "l"(b), "l"(c));
    return d;
}
__device__ __forceinline__ unsigned long long pack2(float v) {
    unsigned long long r;
    asm("mov.b64 %0, {%1, %1};" : "=l"(r) : "f"(v));
    return r;
}
__device__ __forceinline__ void unpack2(unsigned long long v, float& lo, float& hi) {
    asm("mov.b64 {%0, %1}, %2;" : "=f"(lo), "=f"(hi) : "l"(v));
}

// ---------------- embed: x_in -> (B,N,T,E) ----------------
__global__ void k_embed(const float* __restrict__ x_in,
                        const float* __restrict__ emb_w,
                        const float* __restrict__ emb_b,
                        float* __restrict__ out) {
    int idx = blockIdx.x*blockDim.x + threadIdx.x;   // over B*T*N
    if (idx >= BB*TT0*WD) return;
    int n = idx & 127;
    int t = (idx >> 7) & 127;
    int b = idx >> 14;
    const float* xi = x_in + (b*TT0 + t)*131;
    float v  = xi[n];
    float f0 = xi[128], f1 = xi[129], f2 = xi[130];
    float* o = out + ((b*WD + n)*TT0 + t)*EB;
    #pragma unroll
    for (int e = 0; e < EB; e++)
        o[e] = v*emb_w[e] + f0*emb_w[16+e] + f1*emb_w[32+e] + f2*emb_w[48+e] + emb_b[e];
}

// ---------------- precompute Mt[m*128+n] = sum_l Wq[n,l]*Wk[m,l], both layers ----------------
__global__ void k_mt(const float* __restrict__ Wq0, const float* __restrict__ Wk0,
                     const float* __restrict__ Wq1, const float* __restrict__ Wk1,
                     float* __restrict__ Mt) {
    __shared__ float Aq[16][65], Ak[16][65];
    int ly = blockIdx.y;
    const float* Wq = ly ? Wq1 : Wq0;
    const float* Wk = ly ? Wk1 : Wk0;
    float* Mto = Mt + ly*WD*WD;
    int bm = blockIdx.x >> 3, bn = blockIdx.x & 7;
    int m0 = bm*16, n0 = bn*16;
    int ty = threadIdx.x >> 4, tx = threadIdx.x & 15;  // ty -> m, tx -> n
    float acc = 0.f;
    for (int l0 = 0; l0 < LL; l0 += 64) {
        #pragma unroll
        for (int r = 0; r < 4; r++) {
            int idx = threadIdx.x + r*256;
            int row = idx >> 6, col = idx & 63;
            Aq[row][col] = Wq[(n0+row)*LL + l0 + col];
            Ak[row][col] = Wk[(m0+row)*LL + l0 + col];
        }
        __syncthreads();
        #pragma unroll
        for (int lc = 0; lc < 64; lc++)
            acc += Ak[ty][lc]*Aq[tx][lc];
        __syncthreads();
    }
    Mto[(m0+ty)*WD + (n0+tx)] = acc;
}

// ---------------- precompute u, w, c (both layers) ----------------
__global__ void k_uw(const float* __restrict__ Wq0, const float* __restrict__ Wk0,
                     const float* __restrict__ bq0, const float* __restrict__ bk0,
                     const float* __restrict__ Wq1, const float* __restrict__ Wk1,
                     const float* __restrict__ bq1, const float* __restrict__ bk1,
                     float* __restrict__ u, float* __restrict__ w, float* __restrict__ cp) {
    int ly = blockIdx.y;
    const float* Wq = ly ? Wq1 : Wq0;
    const float* Wk = ly ? Wk1 : Wk0;
    const float* bq = ly ? bq1 : bq0;
    const float* bk = ly ? bk1 : bk0;
    int n = blockIdx.x;
    __shared__ float su[256], sw[256], sc[256];
    float pu = 0.f, pw = 0.f, pc = 0.f;
    for (int l = threadIdx.x; l < LL; l += 256) {
        float bkl = bk[l], bql = bq[l];
        pu += Wq[n*LL + l]*bkl;
        pw += Wk[n*LL + l]*bql;
        if (n == 0) pc += bql*bkl;
    }
    su[threadIdx.x] = pu; sw[threadIdx.x] = pw; sc[threadIdx.x] = pc;
    __syncthreads();
    for (int s = 128; s > 0; s >>= 1) {
        if (threadIdx.x < s) {
            su[threadIdx.x] += su[threadIdx.x + s];
            sw[threadIdx.x] += sw[threadIdx.x + s];
            sc[threadIdx.x] += sc[threadIdx.x + s];
        }
        __syncthreads();
    }
    if (threadIdx.x == 0) {
        u[ly*WD + n] = su[0]; w[ly*WD + n] = sw[0];
        if (n == 0) cp[ly] = sc[0];
    }
}

// ---------------- gated conv GEMM v1 + double-buffered pipeline ----------------
// j = t*16+e flattened per batch. Block tile 64o x 64j, thread 4o x 8j, 128 thr.
// Y[o,j] = tanh(F+bf)*sigmoid(G+bg)
template<int TIN, int TOUT, int D>
__global__ void k_gatedg(const float* __restrict__ X,
                         const float* __restrict__ wf, const float* __restrict__ bf,
                         const float* __restrict__ wg, const float* __restrict__ bg,
                         float* __restrict__ Y) {
    constexpr int TIN16  = TIN*16;
    constexpr int TOUT16 = TOUT*16;
    constexpr int OFF    = 16*D;          // tap-1 column offset (32 or 64)
    constexpr int AFS    = 64*33;         // Af/Ag floats per buffer
    constexpr int BSS    = 16*136;        // Bs floats per buffer
    constexpr int STRIDE = 2*AFS + BSS;   // 6400 floats per buffer
    extern __shared__ float sm[];         // 2*STRIDE floats = 51200 bytes

    int bx = blockIdx.x;
    int oB = bx & 1;                      // o-half
    int jT = bx >> 1;                     // j tile
    int b  = blockIdx.y;
    int j0b = jT*64;
    int tid = threadIdx.x;                // 128
    int jt = tid & 7;                     // j-group: j = j0b + jt*8 .. +7
    int ot = tid >> 3;                    // o-group: o_local = ot*4 .. +3

    unsigned long long fa[4][4], ga[4][4];
    #pragma unroll
    for (int oo = 0; oo < 4; oo++)
        #pragma unroll
        for (int p = 0; p < 4; p++) { fa[oo][p] = 0ull; ga[oo][p] = 0ull; }

    // stage chunk i0 into buffer buf
    auto stage = [&](int i0, int buf) {
        float* Af_ = sm + buf*STRIDE;
        float* Ag_ = Af_ + AFS;
        float* Bs_ = Ag_ + AFS;
        #pragma unroll
        for (int r = 0; r < 16; r++) {     // 64 ol x 32 kk
            int idx = tid + r*128;
            int kk = idx & 31, ol = idx >> 5;
            Af_[ol*33 + kk] = wf[(oB*64 + ol)*(WD*2) + i0*2 + kk];
            Ag_[ol*33 + kk] = wg[(oB*64 + ol)*(WD*2) + i0*2 + kk];
        }
        #pragma unroll
        for (int r = 0; r < 16; r++) {     // 16 il x 128 c
            int idx = tid + r*128;
            int c = idx & 127, il = idx >> 7;
            int jg = j0b + c;
            Bs_[il*136 + c] = (jg < TIN16) ? X[((size_t)(b*WD + i0 + il))*TIN16 + jg] : 0.f;
        }
    };

    stage(0, 0);
    __syncthreads();

    #pragma unroll
    for (int ch = 0; ch < 8; ch++) {
        int cur = ch & 1;
        if (ch < 7) stage((ch + 1)*16, cur ^ 1);   // prefetch next chunk (no sync yet)

        const float* Af_ = sm + cur*STRIDE;
        const float* Ag_ = Af_ + AFS;
        const float* Bs_ = Ag_ + AFS;
        #pragma unroll 4
        for (int il = 0; il < 16; il++) {
            #pragma unroll
            for (int tap = 0; tap < 2; tap++) {
                int k = il*2 + tap;
                const float* bp = Bs_ + il*136 + jt*8 + tap*OFF;
                ulonglong2 q0 = *(const ulonglong2*)bp;
                ulonglong2 q1 = *(const ulonglong2*)(bp + 4);
                unsigned long long bq[4] = {q0.x, q0.y, q1.x, q1.y};
                #pragma unroll
                for (int oo = 0; oo < 4; oo++) {
                    unsigned long long paf = pack2(Af_[(ot*4 + oo)*33 + k]);
                    unsigned long long pag = pack2(Ag_[(ot*4 + oo)*33 + k]);
                    #pragma unroll
                    for (int p = 0; p < 4; p++) {
                        fa[oo][p] = fma2(paf, bq[p], fa[oo][p]);
                        ga[oo][p] = fma2(pag, bq[p], ga[oo][p]);
                    }
                }
            }
        }
        __syncthreads();   // compute(cur) done + stage(nxt) stores visible
    }

    int jbase = j0b + jt*8;
    if (jbase < TOUT16) {   // TOUT16 % 8 == 0 -> whole 8-j group valid
        #pragma unroll
        for (int oo = 0; oo < 4; oo++) {
            int o = oB*64 + ot*4 + oo;
            float bfo = bf[o], bgo = bg[o];
            float fv[8], gv[8];
            #pragma unroll
            for (int p = 0; p < 4; p++) {
                unpack2(fa[oo][p], fv[2*p], fv[2*p+1]);
                unpack2(ga[oo][p], gv[2*p], gv[2*p+1]);
            }
            float yv[8];
            #pragma unroll
            for (int q = 0; q < 8; q++)
                yv[q] = tanhf(fv[q] + bfo)*(1.f/(1.f + expf(-(gv[q] + bgo))));
            float* yp = Y + ((size_t)(b*WD + o))*TOUT16 + jbase;
            *(float4*)(yp)     = make_float4(yv[0], yv[1], yv[2], yv[3]);
            *(float4*)(yp + 4) = make_float4(yv[4], yv[5], yv[6], yv[7]);
        }
    }
}

// ---------------- gated residual v2: tiled smem GEMM (RPB=64, += epilogue) ----------------
template<int TIN, int TOUT>
__global__ void k_res2(const float* __restrict__ X, const float* __restrict__ ws,
                       const float* __restrict__ bs, float* __restrict__ Y) {
    constexpr int RPB = 64;
    constexpr int KC  = 32;
    __shared__ float As[KC][RPB];       // [t][row]
    __shared__ float Ws[KC][132];       // [t][s], 16B-aligned rows
    int b  = blockIdx.x >> 5;
    int r0 = (blockIdx.x & 31)*RPB;
    int tid = threadIdx.x;              // 256
    int rq = tid >> 4;                  // 0..15 -> rows rq*4..+3
    int sg = tid & 15;                  // s = sg*8 .. +7

    unsigned long long acc[4][4];
    #pragma unroll
    for (int r = 0; r < 4; r++)
        #pragma unroll
        for (int j = 0; j < 4; j++) acc[r][j] = 0ull;

    for (int t0 = 0; t0 < TIN; t0 += KC) {
        __syncthreads();
        #pragma unroll
        for (int j = 0; j < (RPB*KC)/256; j++) {
            int idx = tid + j*256;
            int row = idx & (RPB-1);
            int t = idx >> 6;
            int rr = r0 + row;
            int n = rr >> 4, e = rr & 15;
            int tg = t0 + t;
            As[t][row] = (tg < TIN) ? X[((b*WD + n)*TIN + tg)*EB + e] : 0.f;
        }
        #pragma unroll
        for (int j = 0; j < (KC*128)/256; j++) {
            int idx = tid + j*256;
            int s = idx & 127;
            int t = idx >> 7;
            int tg = t0 + t;
            Ws[t][s] = (tg < TIN && s < TOUT) ? ws[tg*TOUT + s] : 0.f;
        }
        __syncthreads();
        #pragma unroll
        for (int t = 0; t < KC; t++) {
            float4 w0 = *(const float4*)(&Ws[t][sg*8]);
            float4 w1 = *(const float4*)(&Ws[t][sg*8 + 4]);
            unsigned long long wv[4];
            wv[0] = ((unsigned long long)__float_as_uint(w0.y) << 32) | __float_as_uint(w0.x);
            wv[1] = ((unsigned long long)__float_as_uint(w0.w) << 32) | __float_as_uint(w0.z);
            wv[2] = ((unsigned long long)__float_as_uint(w1.y) << 32) | __float_as_uint(w1.x);
            wv[3] = ((unsigned long long)__float_as_uint(w1.w) << 32) | __float_as_uint(w1.z);
            #pragma unroll
            for (int r = 0; r < 4; r++) {
                unsigned long long av = pack2(As[t][rq*4 + r]);
                #pragma unroll
                for (int j = 0; j < 4; j++)
                    acc[r][j] = fma2(av, wv[j], acc[r][j]);
            }
        }
    }
    #pragma unroll
    for (int r = 0; r < 4; r++) {
        int rr = r0 + rq*4 + r;
        int n = rr >> 4, e = rr & 15;
        float* yp = Y + ((size_t)(b*WD + n)*TOUT)*EB + e;
        #pragma unroll
        for (int j = 0; j < 4; j++) {
            float lo, hi; unpack2(acc[r][j], lo, hi);
            int s0 = sg*8 + j*2;
            if (s0 < TOUT)   yp[s0*EB]       += lo + bs[s0];
            if (s0+1 < TOUT) yp[(s0+1)*EB]   += hi + bs[s0+1];
        }
    }
}

// ---------------- fused attention: Z (in-block GEMM) + softmax + ybar ----------------
template<int T>
__global__ void k_attn2(const float* __restrict__ X, const float* __restrict__ Mt,
                        const float* __restrict__ u, const float* __restrict__ w,
                        const float* __restrict__ cptr, float* __restrict__ yout) {
    __shared__ __align__(16) float Xs[WD*EB];   // [n][e] 8KB
    __shared__ __align__(16) float Ms[32*WD];   // Mt chunk [k][n] 16KB
    __shared__ float Zs[EB][WD+5];              // [f][n]
    __shared__ float Ss[EB][EB+1];
    __shared__ float uev[EB], wfv[EB], abar[EB];
    int bt = blockIdx.x;
    int b = bt / T, t = bt % T;
    int tid = threadIdx.x;                      // 256
    // load Xs (vectorized)
    for (int idx = tid; idx < WD*4; idx += 256) {
        int n = idx >> 2, q = idx & 3;
        ((float4*)Xs)[idx] = *(const float4*)(X + ((b*WD + n)*T + t)*EB + q*4);
    }
    // Z[fh*8..+7][n] per thread (n = tid&127, fh = tid>>7)
    int n_ = tid & 127, fh = tid >> 7;
    unsigned long long zacc[4] = {0ull, 0ull, 0ull, 0ull};
    for (int m0 = 0; m0 < WD; m0 += 32) {
        __syncthreads();
        #pragma unroll
        for (int rep = 0; rep < (32*WD/4)/256; rep++)
            ((float4*)Ms)[tid + rep*256] = ((const float4*)(Mt + m0*WD))[tid + rep*256];
        __syncthreads();
        #pragma unroll
        for (int k = 0; k < 32; k++) {
            unsigned long long pm = pack2(Ms[k*WD + n_]);
            const ulonglong2* xp = (const ulonglong2*)(Xs + (m0 + k)*16 + fh*8);
            ulonglong2 xa = xp[0];
            zacc[0] = fma2(pm, xa.x, zacc[0]);
            zacc[1] = fma2(pm, xa.y, zacc[1]);
            ulonglong2 xb = xp[1];
            zacc[2] = fma2(pm, xb.x, zacc[2]);
            zacc[3] = fma2(pm, xb.y, zacc[3]);
        }
    }
    #pragma unroll
    for (int j = 0; j < 4; j++) {
        float lo, hi; unpack2(zacc[j], lo, hi);
        Zs[fh*8 + 2*j][n_]     = lo;
        Zs[fh*8 + 2*j + 1][n_] = hi;
    }
    if (tid < 16) {
        float a = 0.f;
        for (int n = 0; n < WD; n++) a += Xs[n*16 + tid]*u[n];
        uev[tid] = a;
    } else if (tid < 32) {
        int f = tid - 16;
        float a = 0.f;
        for (int n = 0; n < WD; n++) a += Xs[n*16 + f]*w[n];
        wfv[f] = a;
    }
    __syncthreads();
    {
        int e = tid >> 4, f = tid & 15;
        float acc = 0.f;
        #pragma unroll 4
        for (int n = 0; n < WD; n++)
            acc += Xs[n*16 + e]*Zs[f][n];
        const float scale = 0.022097086912079608f; // 1/sqrt(2048)
        Ss[e][f] = (acc + uev[e] + wfv[f] + cptr[0])*scale;
    }
    __syncthreads();
    if (tid < 16) {
        int e = tid;
        float mx = -1e30f;
        #pragma unroll
        for (int f = 0; f < 16; f++) mx = fmaxf(mx, Ss[e][f]);
        float ex[16]; float sum = 0.f;
        #pragma unroll
        for (int f = 0; f < 16; f++) { ex[f] = expf(Ss[e][f] - mx); sum += ex[f]; }
        float inv = 1.f/sum;
        #pragma unroll
        for (int f = 0; f < 16; f++) Ss[e][f] = ex[f]*inv;
    }
    __syncthreads();
    if (tid < 16) {
        int f = tid;
        float a = 0.f;
        #pragma unroll
        for (int e = 0; e < 16; e++) a += Ss[e][f];
        abar[f] = a*(1.f/16.f);
    }
    __syncthreads();
    if (tid < 128) {
        int n = tid;
        float a = 0.f;
        #pragma unroll
        for (int f = 0; f < 16; f++) a += Xs[n*16 + f]*abar[f];
        yout[bt*WD + n] = a;
    }
}

// ---------------- attention out: Y = X + y @ Wv + bv ----------------
template<int T>
__global__ void k_attn_out(const float* __restrict__ Xin, const float* __restrict__ yv,
                           const float* __restrict__ Wv, const float* __restrict__ bv,
                           float* __restrict__ Yout) {
    __shared__ float ys[64][WD];
    const int BT = BB*T;
    int bt0 = blockIdx.y*64;
    int l = blockIdx.x*128 + (threadIdx.x & 127);
    int half = threadIdx.x >> 7;
    for (int idx = threadIdx.x; idx < 64*WD; idx += 256) {
        int r = idx >> 7, m = idx & 127;
        int bt = bt0 + r;
        ys[r][m] = (bt < BT) ? yv[bt*WD + m] : 0.f;
    }
    __syncthreads();
    float acc[32];
    #pragma unroll
    for (int j = 0; j < 32; j++) acc[j] = 0.f;
    for (int m = 0; m < WD; m++) {
        float wvv = Wv[m*LL + l];
        #pragma unroll
        for (int j = 0; j < 32; j++) acc[j] += ys[half*32 + j][m]*wvv;
    }
    float bvl = bv[l];
    int n = l >> 4, e = l & 15;
    #pragma unroll
    for (int j = 0; j < 32; j++) {
        int bt = bt0 + half*32 + j;
        if (bt < BT) {
            int b = bt / T, t = bt % T;
            int idx = ((b*WD + n)*T + t)*EB + e;
            Yout[idx] = Xin[idx] + acc[j] + bvl;
        }
    }
}

// ---------------- decode + time-mix output ----------------
__global__ void k_decode(const float* __restrict__ X, const float* __restrict__ dec_w,
                         const float* __restrict__ dec_b, const float* __restrict__ out_w,
                         const float* __restrict__ out_b, float* __restrict__ out) {
    __shared__ float sy[TF];
    int b = blockIdx.x >> 7, n = blockIdx.x & 127;
    int t = threadIdx.x;
    if (t < TF) {
        const float* xp = X + ((size_t)(b*WD + n)*TF + t)*EB;
        float a = dec_b[n];
        #pragma unroll
        for (int e = 0; e < EB; e++) a += xp[e]*dec_w[n*EB + e];
        sy[t] = a;
    }
    __syncthreads();
    if (t < ODIM) {
        float a = out_b[t];
        for (int tt = 0; tt < TF; tt++) a += sy[tt]*out_w[tt*ODIM + t];
        out[(b*ODIM + t)*WD + n] = a;
    }
}

// ---------------- launcher: minimal fork (mt/uw overlapped with gated0 chain) ----------------
extern "C" void kernel_launch(void* const* d_in, const int* in_sizes, int n_in,
                              void* d_out, int out_size) {
    const float* x_in  = (const float*)d_in[0];
    const float* emb_w = (const float*)d_in[1];
    const float* emb_b = (const float*)d_in[2];
    const float* g0_wf = (const float*)d_in[3];
    const float* g0_bf = (const float*)d_in[4];
    const float* g0_wg = (const float*)d_in[5];
    const float* g0_bg = (const float*)d_in[6];
    const float* g0_ws = (const float*)d_in[7];
    const float* g0_bs = (const float*)d_in[8];
    const float* a0_wq = (const float*)d_in[9];
    const float* a0_bq = (const float*)d_in[10];
    const float* a0_wk = (const float*)d_in[11];
    const float* a0_bk = (const float*)d_in[12];
    const float* a0_wv = (const float*)d_in[13];
    const float* a0_bv = (const float*)d_in[14];
    const float* g1_wf = (const float*)d_in[15];
    const float* g1_bf = (const float*)d_in[16];
    const float* g1_wg = (const float*)d_in[17];
    const float* g1_bg = (const float*)d_in[18];
    const float* g1_ws = (const float*)d_in[19];
    const float* g1_bs = (const float*)d_in[20];
    const float* a1_wq = (const float*)d_in[21];
    const float* a1_bq = (const float*)d_in[22];
    const float* a1_wk = (const float*)d_in[23];
    const float* a1_bk = (const float*)d_in[24];
    const float* a1_wv = (const float*)d_in[25];
    const float* a1_bv = (const float*)d_in[26];
    const float* dec_w = (const float*)d_in[27];
    const float* dec_b = (const float*)d_in[28];
    const float* out_w = (const float*)d_in[29];
    const float* out_b = (const float*)d_in[30];

    float *dA, *dB, *dMt, *dU, *dW, *dC, *dY;
    cudaGetSymbolAddress((void**)&dA,  g_bufA);
    cudaGetSymbolAddress((void**)&dB,  g_bufB);
    cudaGetSymbolAddress((void**)&dMt, g_Mt);
    cudaGetSymbolAddress((void**)&dU,  g_uu);
    cudaGetSymbolAddress((void**)&dW,  g_ww);
    cudaGetSymbolAddress((void**)&dC,  g_cc);
    cudaGetSymbolAddress((void**)&dY,  g_yv);

    // double-buffered smem: 2*(2*64*33 + 16*136)*4 = 51200 bytes
    const int SMEM_G = 2*(2*64*33 + 16*136)*4;
    cudaFuncSetAttribute(k_gatedg<128,126,2>, cudaFuncAttributeMaxDynamicSharedMemorySize, SMEM_G);
    cudaFuncSetAttribute(k_gatedg<126,122,4>, cudaFuncAttributeMaxDynamicSharedMemorySize, SMEM_G);

    // side stream + events (host resources, created once)
    static cudaStream_t s2 = nullptr;
    static cudaEvent_t evOrigin = nullptr, evPre = nullptr;
    if (s2 == nullptr) {
        cudaStreamCreateWithFlags(&s2, cudaStreamNonBlocking);
        cudaEventCreateWithFlags(&evOrigin, cudaEventDisableTiming);
        cudaEventCreateWithFlags(&evPre,    cudaEventDisableTiming);
    }

    // fork: side stream computes mt/uw while main does embed -> gated0 -> res0
    cudaEventRecord(evOrigin, 0);
    cudaStreamWaitEvent(s2, evOrigin, 0);
    k_mt<<<dim3(64,2), 256, 0, s2>>>(a0_wq, a0_wk, a1_wq, a1_wk, dMt);
    k_uw<<<dim3(128,2), 256, 0, s2>>>(a0_wq, a0_wk, a0_bq, a0_bk,
                                      a1_wq, a1_wk, a1_bq, a1_bk, dU, dW, dC);
    cudaEventRecord(evPre, s2);

    // main stream
    k_embed<<<(BB*TT0*WD + 255)/256, 256>>>(x_in, emb_w, emb_b, dA);

    // layer 0: gated (TIN=128 -> 126, d=2), attention T=126
    {
        const int ntileJ = (126*16 + 63)/64;  // 32
        k_gatedg<128,126,2><<<dim3(ntileJ*2, BB), 128, SMEM_G>>>(dA, g0_wf, g0_bf, g0_wg, g0_bg, dB);
        k_res2<128,126><<<BB*32, 256>>>(dA, g0_ws, g0_bs, dB);
        cudaStreamWaitEvent(0, evPre, 0);   // join: attn needs Mt/u/w/c
        k_attn2<126><<<BB*126, 256>>>(dB, dMt, dU, dW, dC, dY);
        k_attn_out<126><<<dim3(16, (BB*126 + 63)/64), 256>>>(dB, dY, a0_wv, a0_bv, dA);
    }

    // layer 1: gated (TIN=126 -> 122, d=4), attention T=122
    {
        const int ntileJ = (122*16 + 63)/64;  // 31
        k_gatedg<126,122,4><<<dim3(ntileJ*2, BB), 128, SMEM_G>>>(dA, g1_wf, g1_bf, g1_wg, g1_bg, dB);
        k_res2<126,122><<<BB*32, 256>>>(dA, g1_ws, g1_bs, dB);
        k_attn2<122><<<BB*122, 256>>>(dB, dMt + WD*WD, dU + WD, dW + WD, dC + 1, dY);
        k_attn_out<122><<<dim3(16, (BB*122 + 63)/64), 256>>>(dB, dY, a1_wv, a1_bv, dA);
    }

    // decode
    k_decode<<<BB*WD, 128>>>(dA, dec_w, dec_b, out_w, out_b, (float*)d_out);
}

// round 13
// speedup vs baseline: 1.4430x; 1.0249x over previous
#include <cuda_runtime.h>
#include <math.h>

#define BB   4
#define TT0  128
#define WD   128
#define EB   16
#define LL   2048
#define ODIM 24
#define TF   122

// ---------------- scratch (no allocations allowed) ----------------
__device__ float g_bufA[BB*WD*TT0*EB];   // 4 MB
__device__ float g_bufB[BB*WD*TT0*EB];   // 4 MB
__device__ float g_bufR[BB*WD*TT0*EB];   // 4 MB (residual-path output)
__device__ float g_Mt[2*WD*WD];          // Mt[m*128+n] = (Wq Wk^T)[n][m]
__device__ float g_uu[2*WD];             // u = Wq bk
__device__ float g_ww[2*WD];             // w = Wk bq
__device__ float g_cc[2];                // c = bq . bk
__device__ float g_yv[BB*126*WD];        // per-(b,t) y vectors

// ---------------- f32x2 packed helpers ----------------
__device__ __forceinline__ unsigned long long fma2(unsigned long long a,
                                                   unsigned long long b,
                                                   unsigned long long c) {
    unsigned long long d;
    asm("fma.rn.f32x2 %0, %1, %2, %3;" : "=l"(d) : "l"(a), "l"(b), "l"(c));
    return d;
}
__device__ __forceinline__ unsigned long long pack2(float v) {
    unsigned long long r;
    asm("mov.b64 %0, {%1, %1};" : "=l"(r) : "f"(v));
    return r;
}
__device__ __forceinline__ void unpack2(unsigned long long v, float& lo, float& hi) {
    asm("mov.b64 {%0, %1}, %2;" : "=f"(lo), "=f"(hi) : "l"(v));
}

// ---------------- embed: x_in -> (B,N,T,E) ----------------
__global__ void k_embed(const float* __restrict__ x_in,
                        const float* __restrict__ emb_w,
                        const float* __restrict__ emb_b,
                        float* __restrict__ out) {
    int idx = blockIdx.x*blockDim.x + threadIdx.x;   // over B*T*N
    if (idx >= BB*TT0*WD) return;
    int n = idx & 127;
    int t = (idx >> 7) & 127;
    int b = idx >> 14;
    const float* xi = x_in + (b*TT0 + t)*131;
    float v  = xi[n];
    float f0 = xi[128], f1 = xi[129], f2 = xi[130];
    float* o = out + ((b*WD + n)*TT0 + t)*EB;
    #pragma unroll
    for (int e = 0; e < EB; e++)
        o[e] = v*emb_w[e] + f0*emb_w[16+e] + f1*emb_w[32+e] + f2*emb_w[48+e] + emb_b[e];
}

// ---------------- precompute Mt[m*128+n] = sum_l Wq[n,l]*Wk[m,l], both layers ----------------
__global__ void k_mt(const float* __restrict__ Wq0, const float* __restrict__ Wk0,
                     const float* __restrict__ Wq1, const float* __restrict__ Wk1,
                     float* __restrict__ Mt) {
    __shared__ float Aq[16][65], Ak[16][65];
    int ly = blockIdx.y;
    const float* Wq = ly ? Wq1 : Wq0;
    const float* Wk = ly ? Wk1 : Wk0;
    float* Mto = Mt + ly*WD*WD;
    int bm = blockIdx.x >> 3, bn = blockIdx.x & 7;
    int m0 = bm*16, n0 = bn*16;
    int ty = threadIdx.x >> 4, tx = threadIdx.x & 15;  // ty -> m, tx -> n
    float acc = 0.f;
    for (int l0 = 0; l0 < LL; l0 += 64) {
        #pragma unroll
        for (int r = 0; r < 4; r++) {
            int idx = threadIdx.x + r*256;
            int row = idx >> 6, col = idx & 63;
            Aq[row][col] = Wq[(n0+row)*LL + l0 + col];
            Ak[row][col] = Wk[(m0+row)*LL + l0 + col];
        }
        __syncthreads();
        #pragma unroll
        for (int lc = 0; lc < 64; lc++)
            acc += Ak[ty][lc]*Aq[tx][lc];
        __syncthreads();
    }
    Mto[(m0+ty)*WD + (n0+tx)] = acc;
}

// ---------------- precompute u, w, c (both layers) ----------------
__global__ void k_uw(const float* __restrict__ Wq0, const float* __restrict__ Wk0,
                     const float* __restrict__ bq0, const float* __restrict__ bk0,
                     const float* __restrict__ Wq1, const float* __restrict__ Wk1,
                     const float* __restrict__ bq1, const float* __restrict__ bk1,
                     float* __restrict__ u, float* __restrict__ w, float* __restrict__ cp) {
    int ly = blockIdx.y;
    const float* Wq = ly ? Wq1 : Wq0;
    const float* Wk = ly ? Wk1 : Wk0;
    const float* bq = ly ? bq1 : bq0;
    const float* bk = ly ? bk1 : bk0;
    int n = blockIdx.x;
    __shared__ float su[256], sw[256], sc[256];
    float pu = 0.f, pw = 0.f, pc = 0.f;
    for (int l = threadIdx.x; l < LL; l += 256) {
        float bkl = bk[l], bql = bq[l];
        pu += Wq[n*LL + l]*bkl;
        pw += Wk[n*LL + l]*bql;
        if (n == 0) pc += bql*bkl;
    }
    su[threadIdx.x] = pu; sw[threadIdx.x] = pw; sc[threadIdx.x] = pc;
    __syncthreads();
    for (int s = 128; s > 0; s >>= 1) {
        if (threadIdx.x < s) {
            su[threadIdx.x] += su[threadIdx.x + s];
            sw[threadIdx.x] += sw[threadIdx.x + s];
            sc[threadIdx.x] += sc[threadIdx.x + s];
        }
        __syncthreads();
    }
    if (threadIdx.x == 0) {
        u[ly*WD + n] = su[0]; w[ly*WD + n] = sw[0];
        if (n == 0) cp[ly] = sc[0];
    }
}

// ---------------- gated conv GEMM v1 + double-buffered pipeline ----------------
// j = t*16+e flattened per batch. Block tile 64o x 64j, thread 4o x 8j, 128 thr.
// Y[o,j] = tanh(F+bf)*sigmoid(G+bg)
template<int TIN, int TOUT, int D>
__global__ void k_gatedg(const float* __restrict__ X,
                         const float* __restrict__ wf, const float* __restrict__ bf,
                         const float* __restrict__ wg, const float* __restrict__ bg,
                         float* __restrict__ Y) {
    constexpr int TIN16  = TIN*16;
    constexpr int TOUT16 = TOUT*16;
    constexpr int OFF    = 16*D;          // tap-1 column offset (32 or 64)
    constexpr int AFS    = 64*33;         // Af/Ag floats per buffer
    constexpr int BSS    = 16*136;        // Bs floats per buffer
    constexpr int STRIDE = 2*AFS + BSS;   // 6400 floats per buffer
    extern __shared__ float sm[];         // 2*STRIDE floats = 51200 bytes

    int bx = blockIdx.x;
    int oB = bx & 1;                      // o-half
    int jT = bx >> 1;                     // j tile
    int b  = blockIdx.y;
    int j0b = jT*64;
    int tid = threadIdx.x;                // 128
    int jt = tid & 7;                     // j-group: j = j0b + jt*8 .. +7
    int ot = tid >> 3;                    // o-group: o_local = ot*4 .. +3

    unsigned long long fa[4][4], ga[4][4];
    #pragma unroll
    for (int oo = 0; oo < 4; oo++)
        #pragma unroll
        for (int p = 0; p < 4; p++) { fa[oo][p] = 0ull; ga[oo][p] = 0ull; }

    // stage chunk i0 into buffer buf
    auto stage = [&](int i0, int buf) {
        float* Af_ = sm + buf*STRIDE;
        float* Ag_ = Af_ + AFS;
        float* Bs_ = Ag_ + AFS;
        #pragma unroll
        for (int r = 0; r < 16; r++) {     // 64 ol x 32 kk
            int idx = tid + r*128;
            int kk = idx & 31, ol = idx >> 5;
            Af_[ol*33 + kk] = wf[(oB*64 + ol)*(WD*2) + i0*2 + kk];
            Ag_[ol*33 + kk] = wg[(oB*64 + ol)*(WD*2) + i0*2 + kk];
        }
        #pragma unroll
        for (int r = 0; r < 16; r++) {     // 16 il x 128 c
            int idx = tid + r*128;
            int c = idx & 127, il = idx >> 7;
            int jg = j0b + c;
            Bs_[il*136 + c] = (jg < TIN16) ? X[((size_t)(b*WD + i0 + il))*TIN16 + jg] : 0.f;
        }
    };

    stage(0, 0);
    __syncthreads();

    #pragma unroll
    for (int ch = 0; ch < 8; ch++) {
        int cur = ch & 1;
        if (ch < 7) stage((ch + 1)*16, cur ^ 1);   // prefetch next chunk (no sync yet)

        const float* Af_ = sm + cur*STRIDE;
        const float* Ag_ = Af_ + AFS;
        const float* Bs_ = Ag_ + AFS;
        #pragma unroll 4
        for (int il = 0; il < 16; il++) {
            #pragma unroll
            for (int tap = 0; tap < 2; tap++) {
                int k = il*2 + tap;
                const float* bp = Bs_ + il*136 + jt*8 + tap*OFF;
                ulonglong2 q0 = *(const ulonglong2*)bp;
                ulonglong2 q1 = *(const ulonglong2*)(bp + 4);
                unsigned long long bq[4] = {q0.x, q0.y, q1.x, q1.y};
                #pragma unroll
                for (int oo = 0; oo < 4; oo++) {
                    unsigned long long paf = pack2(Af_[(ot*4 + oo)*33 + k]);
                    unsigned long long pag = pack2(Ag_[(ot*4 + oo)*33 + k]);
                    #pragma unroll
                    for (int p = 0; p < 4; p++) {
                        fa[oo][p] = fma2(paf, bq[p], fa[oo][p]);
                        ga[oo][p] = fma2(pag, bq[p], ga[oo][p]);
                    }
                }
            }
        }
        __syncthreads();   // compute(cur) done + stage(nxt) stores visible
    }

    int jbase = j0b + jt*8;
    if (jbase < TOUT16) {   // TOUT16 % 8 == 0 -> whole 8-j group valid
        #pragma unroll
        for (int oo = 0; oo < 4; oo++) {
            int o = oB*64 + ot*4 + oo;
            float bfo = bf[o], bgo = bg[o];
            float fv[8], gv[8];
            #pragma unroll
            for (int p = 0; p < 4; p++) {
                unpack2(fa[oo][p], fv[2*p], fv[2*p+1]);
                unpack2(ga[oo][p], gv[2*p], gv[2*p+1]);
            }
            float yv[8];
            #pragma unroll
            for (int q = 0; q < 8; q++)
                yv[q] = tanhf(fv[q] + bfo)*(1.f/(1.f + expf(-(gv[q] + bgo))));
            float* yp = Y + ((size_t)(b*WD + o))*TOUT16 + jbase;
            *(float4*)(yp)     = make_float4(yv[0], yv[1], yv[2], yv[3]);
            *(float4*)(yp + 4) = make_float4(yv[4], yv[5], yv[6], yv[7]);
        }
    }
}

// ---------------- residual path: R = X @ ws + bs (pure write, RPB=64) ----------------
template<int TIN, int TOUT>
__global__ void k_res2(const float* __restrict__ X, const float* __restrict__ ws,
                       const float* __restrict__ bs, float* __restrict__ R) {
    constexpr int RPB = 64;
    constexpr int KC  = 32;
    __shared__ float As[KC][RPB];       // [t][row]
    __shared__ float Ws[KC][132];       // [t][s], 16B-aligned rows
    int b  = blockIdx.x >> 5;
    int r0 = (blockIdx.x & 31)*RPB;
    int tid = threadIdx.x;              // 256
    int rq = tid >> 4;                  // 0..15 -> rows rq*4..+3
    int sg = tid & 15;                  // s = sg*8 .. +7

    unsigned long long acc[4][4];
    #pragma unroll
    for (int r = 0; r < 4; r++)
        #pragma unroll
        for (int j = 0; j < 4; j++) acc[r][j] = 0ull;

    for (int t0 = 0; t0 < TIN; t0 += KC) {
        __syncthreads();
        #pragma unroll
        for (int j = 0; j < (RPB*KC)/256; j++) {
            int idx = tid + j*256;
            int row = idx & (RPB-1);
            int t = idx >> 6;
            int rr = r0 + row;
            int n = rr >> 4, e = rr & 15;
            int tg = t0 + t;
            As[t][row] = (tg < TIN) ? X[((b*WD + n)*TIN + tg)*EB + e] : 0.f;
        }
        #pragma unroll
        for (int j = 0; j < (KC*128)/256; j++) {
            int idx = tid + j*256;
            int s = idx & 127;
            int t = idx >> 7;
            int tg = t0 + t;
            Ws[t][s] = (tg < TIN && s < TOUT) ? ws[tg*TOUT + s] : 0.f;
        }
        __syncthreads();
        #pragma unroll
        for (int t = 0; t < KC; t++) {
            float4 w0 = *(const float4*)(&Ws[t][sg*8]);
            float4 w1 = *(const float4*)(&Ws[t][sg*8 + 4]);
            unsigned long long wv[4];
            wv[0] = ((unsigned long long)__float_as_uint(w0.y) << 32) | __float_as_uint(w0.x);
            wv[1] = ((unsigned long long)__float_as_uint(w0.w) << 32) | __float_as_uint(w0.z);
            wv[2] = ((unsigned long long)__float_as_uint(w1.y) << 32) | __float_as_uint(w1.x);
            wv[3] = ((unsigned long long)__float_as_uint(w1.w) << 32) | __float_as_uint(w1.z);
            #pragma unroll
            for (int r = 0; r < 4; r++) {
                unsigned long long av = pack2(As[t][rq*4 + r]);
                #pragma unroll
                for (int j = 0; j < 4; j++)
                    acc[r][j] = fma2(av, wv[j], acc[r][j]);
            }
        }
    }
    #pragma unroll
    for (int r = 0; r < 4; r++) {
        int rr = r0 + rq*4 + r;
        int n = rr >> 4, e = rr & 15;
        float* yp = R + ((size_t)(b*WD + n)*TOUT)*EB + e;
        #pragma unroll
        for (int j = 0; j < 4; j++) {
            float lo, hi; unpack2(acc[r][j], lo, hi);
            int s0 = sg*8 + j*2;
            if (s0 < TOUT)   yp[s0*EB]     = lo + bs[s0];
            if (s0+1 < TOUT) yp[(s0+1)*EB] = hi + bs[s0+1];
        }
    }
}

// ---------------- fused attention: X = Xg+Xr; Z GEMM + softmax + ybar ----------------
template<int T>
__global__ void k_attn2(const float* __restrict__ Xg, const float* __restrict__ Xr,
                        const float* __restrict__ Mt,
                        const float* __restrict__ u, const float* __restrict__ w,
                        const float* __restrict__ cptr, float* __restrict__ yout) {
    __shared__ __align__(16) float Xs[WD*EB];   // [n][e] 8KB
    __shared__ __align__(16) float Ms[32*WD];   // Mt chunk [k][n] 16KB
    __shared__ float Zs[EB][WD+5];              // [f][n]
    __shared__ float Ss[EB][EB+1];
    __shared__ float uev[EB], wfv[EB], abar[EB];
    int bt = blockIdx.x;
    int b = bt / T, t = bt % T;
    int tid = threadIdx.x;                      // 256
    // load Xs = Xg + Xr (vectorized)
    for (int idx = tid; idx < WD*4; idx += 256) {
        int n = idx >> 2, q = idx & 3;
        size_t off = ((size_t)((b*WD + n)*T + t))*EB + q*4;
        float4 a = *(const float4*)(Xg + off);
        float4 r = *(const float4*)(Xr + off);
        ((float4*)Xs)[idx] = make_float4(a.x + r.x, a.y + r.y, a.z + r.z, a.w + r.w);
    }
    // Z[fh*8..+7][n] per thread (n = tid&127, fh = tid>>7)
    int n_ = tid & 127, fh = tid >> 7;
    unsigned long long zacc[4] = {0ull, 0ull, 0ull, 0ull};
    for (int m0 = 0; m0 < WD; m0 += 32) {
        __syncthreads();
        #pragma unroll
        for (int rep = 0; rep < (32*WD/4)/256; rep++)
            ((float4*)Ms)[tid + rep*256] = ((const float4*)(Mt + m0*WD))[tid + rep*256];
        __syncthreads();
        #pragma unroll
        for (int k = 0; k < 32; k++) {
            unsigned long long pm = pack2(Ms[k*WD + n_]);
            const ulonglong2* xp = (const ulonglong2*)(Xs + (m0 + k)*16 + fh*8);
            ulonglong2 xa = xp[0];
            zacc[0] = fma2(pm, xa.x, zacc[0]);
            zacc[1] = fma2(pm, xa.y, zacc[1]);
            ulonglong2 xb = xp[1];
            zacc[2] = fma2(pm, xb.x, zacc[2]);
            zacc[3] = fma2(pm, xb.y, zacc[3]);
        }
    }
    #pragma unroll
    for (int j = 0; j < 4; j++) {
        float lo, hi; unpack2(zacc[j], lo, hi);
        Zs[fh*8 + 2*j][n_]     = lo;
        Zs[fh*8 + 2*j + 1][n_] = hi;
    }
    if (tid < 16) {
        float a = 0.f;
        for (int n = 0; n < WD; n++) a += Xs[n*16 + tid]*u[n];
        uev[tid] = a;
    } else if (tid < 32) {
        int f = tid - 16;
        float a = 0.f;
        for (int n = 0; n < WD; n++) a += Xs[n*16 + f]*w[n];
        wfv[f] = a;
    }
    __syncthreads();
    {
        int e = tid >> 4, f = tid & 15;
        float acc = 0.f;
        #pragma unroll 4
        for (int n = 0; n < WD; n++)
            acc += Xs[n*16 + e]*Zs[f][n];
        const float scale = 0.022097086912079608f; // 1/sqrt(2048)
        Ss[e][f] = (acc + uev[e] + wfv[f] + cptr[0])*scale;
    }
    __syncthreads();
    if (tid < 16) {
        int e = tid;
        float mx = -1e30f;
        #pragma unroll
        for (int f = 0; f < 16; f++) mx = fmaxf(mx, Ss[e][f]);
        float ex[16]; float sum = 0.f;
        #pragma unroll
        for (int f = 0; f < 16; f++) { ex[f] = expf(Ss[e][f] - mx); sum += ex[f]; }
        float inv = 1.f/sum;
        #pragma unroll
        for (int f = 0; f < 16; f++) Ss[e][f] = ex[f]*inv;
    }
    __syncthreads();
    if (tid < 16) {
        int f = tid;
        float a = 0.f;
        #pragma unroll
        for (int e = 0; e < 16; e++) a += Ss[e][f];
        abar[f] = a*(1.f/16.f);
    }
    __syncthreads();
    if (tid < 128) {
        int n = tid;
        float a = 0.f;
        #pragma unroll
        for (int f = 0; f < 16; f++) a += Xs[n*16 + f]*abar[f];
        yout[bt*WD + n] = a;
    }
}

// ---------------- attention out: Y = (Xg+Xr) + y @ Wv + bv ----------------
template<int T>
__global__ void k_attn_out(const float* __restrict__ Xg, const float* __restrict__ Xr,
                           const float* __restrict__ yv,
                           const float* __restrict__ Wv, const float* __restrict__ bv,
                           float* __restrict__ Yout) {
    __shared__ float ys[64][WD];
    const int BT = BB*T;
    int bt0 = blockIdx.y*64;
    int l = blockIdx.x*128 + (threadIdx.x & 127);
    int half = threadIdx.x >> 7;
    for (int idx = threadIdx.x; idx < 64*WD; idx += 256) {
        int r = idx >> 7, m = idx & 127;
        int bt = bt0 + r;
        ys[r][m] = (bt < BT) ? yv[bt*WD + m] : 0.f;
    }
    __syncthreads();
    float acc[32];
    #pragma unroll
    for (int j = 0; j < 32; j++) acc[j] = 0.f;
    for (int m = 0; m < WD; m++) {
        float wvv = Wv[m*LL + l];
        #pragma unroll
        for (int j = 0; j < 32; j++) acc[j] += ys[half*32 + j][m]*wvv;
    }
    float bvl = bv[l];
    int n = l >> 4, e = l & 15;
    #pragma unroll
    for (int j = 0; j < 32; j++) {
        int bt = bt0 + half*32 + j;
        if (bt < BT) {
            int b = bt / T, t = bt % T;
            size_t idx = ((size_t)((b*WD + n)*T + t))*EB + e;
            Yout[idx] = Xg[idx] + Xr[idx] + acc[j] + bvl;
        }
    }
}

// ---------------- decode + time-mix output ----------------
__global__ void k_decode(const float* __restrict__ X, const float* __restrict__ dec_w,
                         const float* __restrict__ dec_b, const float* __restrict__ out_w,
                         const float* __restrict__ out_b, float* __restrict__ out) {
    __shared__ float sy[TF];
    int b = blockIdx.x >> 7, n = blockIdx.x & 127;
    int t = threadIdx.x;
    if (t < TF) {
        const float* xp = X + ((size_t)(b*WD + n)*TF + t)*EB;
        float a = dec_b[n];
        #pragma unroll
        for (int e = 0; e < EB; e++) a += xp[e]*dec_w[n*EB + e];
        sy[t] = a;
    }
    __syncthreads();
    if (t < ODIM) {
        float a = out_b[t];
        for (int tt = 0; tt < TF; tt++) a += sy[tt]*out_w[tt*ODIM + t];
        out[(b*ODIM + t)*WD + n] = a;
    }
}

// ---------------- launcher: fork (mt/uw + res on side stream) ----------------
extern "C" void kernel_launch(void* const* d_in, const int* in_sizes, int n_in,
                              void* d_out, int out_size) {
    const float* x_in  = (const float*)d_in[0];
    const float* emb_w = (const float*)d_in[1];
    const float* emb_b = (const float*)d_in[2];
    const float* g0_wf = (const float*)d_in[3];
    const float* g0_bf = (const float*)d_in[4];
    const float* g0_wg = (const float*)d_in[5];
    const float* g0_bg = (const float*)d_in[6];
    const float* g0_ws = (const float*)d_in[7];
    const float* g0_bs = (const float*)d_in[8];
    const float* a0_wq = (const float*)d_in[9];
    const float* a0_bq = (const float*)d_in[10];
    const float* a0_wk = (const float*)d_in[11];
    const float* a0_bk = (const float*)d_in[12];
    const float* a0_wv = (const float*)d_in[13];
    const float* a0_bv = (const float*)d_in[14];
    const float* g1_wf = (const float*)d_in[15];
    const float* g1_bf = (const float*)d_in[16];
    const float* g1_wg = (const float*)d_in[17];
    const float* g1_bg = (const float*)d_in[18];
    const float* g1_ws = (const float*)d_in[19];
    const float* g1_bs = (const float*)d_in[20];
    const float* a1_wq = (const float*)d_in[21];
    const float* a1_bq = (const float*)d_in[22];
    const float* a1_wk = (const float*)d_in[23];
    const float* a1_bk = (const float*)d_in[24];
    const float* a1_wv = (const float*)d_in[25];
    const float* a1_bv = (const float*)d_in[26];
    const float* dec_w = (const float*)d_in[27];
    const float* dec_b = (const float*)d_in[28];
    const float* out_w = (const float*)d_in[29];
    const float* out_b = (const float*)d_in[30];

    float *dA, *dB, *dR, *dMt, *dU, *dW, *dC, *dY;
    cudaGetSymbolAddress((void**)&dA,  g_bufA);
    cudaGetSymbolAddress((void**)&dB,  g_bufB);
    cudaGetSymbolAddress((void**)&dR,  g_bufR);
    cudaGetSymbolAddress((void**)&dMt, g_Mt);
    cudaGetSymbolAddress((void**)&dU,  g_uu);
    cudaGetSymbolAddress((void**)&dW,  g_ww);
    cudaGetSymbolAddress((void**)&dC,  g_cc);
    cudaGetSymbolAddress((void**)&dY,  g_yv);

    // double-buffered smem: 2*(2*64*33 + 16*136)*4 = 51200 bytes
    const int SMEM_G = 2*(2*64*33 + 16*136)*4;
    cudaFuncSetAttribute(k_gatedg<128,126,2>, cudaFuncAttributeMaxDynamicSharedMemorySize, SMEM_G);
    cudaFuncSetAttribute(k_gatedg<126,122,4>, cudaFuncAttributeMaxDynamicSharedMemorySize, SMEM_G);

    // side stream + events (host resources, created once)
    static cudaStream_t s2 = nullptr;
    static cudaEvent_t evOrigin = nullptr, evEmbed = nullptr,
                       evRes0 = nullptr, evAO0 = nullptr, evRes1 = nullptr;
    if (s2 == nullptr) {
        cudaStreamCreateWithFlags(&s2, cudaStreamNonBlocking);
        cudaEventCreateWithFlags(&evOrigin, cudaEventDisableTiming);
        cudaEventCreateWithFlags(&evEmbed,  cudaEventDisableTiming);
        cudaEventCreateWithFlags(&evRes0,   cudaEventDisableTiming);
        cudaEventCreateWithFlags(&evAO0,    cudaEventDisableTiming);
        cudaEventCreateWithFlags(&evRes1,   cudaEventDisableTiming);
    }

    // fork: side stream computes mt/uw, then res0/res1 when inputs ready
    cudaEventRecord(evOrigin, 0);
    cudaStreamWaitEvent(s2, evOrigin, 0);
    k_mt<<<dim3(64,2), 256, 0, s2>>>(a0_wq, a0_wk, a1_wq, a1_wk, dMt);
    k_uw<<<dim3(128,2), 256, 0, s2>>>(a0_wq, a0_wk, a0_bq, a0_bk,
                                      a1_wq, a1_wk, a1_bq, a1_bk, dU, dW, dC);

    // main stream: embed
    k_embed<<<(BB*TT0*WD + 255)/256, 256>>>(x_in, emb_w, emb_b, dA);
    cudaEventRecord(evEmbed, 0);

    // side stream: res0 (needs embed output dA)
    cudaStreamWaitEvent(s2, evEmbed, 0);
    k_res2<128,126><<<BB*32, 256, 0, s2>>>(dA, g0_ws, g0_bs, dR);
    cudaEventRecord(evRes0, s2);

    // layer 0: gated0 (main, concurrent with mt/uw/res0), then attn
    {
        const int ntileJ = (126*16 + 63)/64;  // 32
        k_gatedg<128,126,2><<<dim3(ntileJ*2, BB), 128, SMEM_G>>>(dA, g0_wf, g0_bf, g0_wg, g0_bg, dB);
        cudaStreamWaitEvent(0, evRes0, 0);   // join: implies mt/uw done too (same stream order)
        k_attn2<126><<<BB*126, 256>>>(dB, dR, dMt, dU, dW, dC, dY);
        k_attn_out<126><<<dim3(16, (BB*126 + 63)/64), 256>>>(dB, dR, dY, a0_wv, a0_bv, dA);
        cudaEventRecord(evAO0, 0);
    }

    // side stream: res1 (needs attn_out0's dA; dR free after attn_out0)
    cudaStreamWaitEvent(s2, evAO0, 0);
    k_res2<126,122><<<BB*32, 256, 0, s2>>>(dA, g1_ws, g1_bs, dR);
    cudaEventRecord(evRes1, s2);

    // layer 1: gated1 (main, concurrent with res1), then attn
    {
        const int ntileJ = (122*16 + 63)/64;  // 31
        k_gatedg<126,122,4><<<dim3(ntileJ*2, BB), 128, SMEM_G>>>(dA, g1_wf, g1_bf, g1_wg, g1_bg, dB);
        cudaStreamWaitEvent(0, evRes1, 0);   // joins s2 back before graph end
        k_attn2<122><<<BB*122, 256>>>(dB, dR, dMt + WD*WD, dU + WD, dW + WD, dC + 1, dY);
        k_attn_out<122><<<dim3(16, (BB*122 + 63)/64), 256>>>(dB, dR, dY, a1_wv, a1_bv, dA);
    }

    // decode
    k_decode<<<BB*WD, 128>>>(dA, dec_w, dec_b, out_w, out_b, (float*)d_out);
}

// round 14
// speedup vs baseline: 1.4663x; 1.0161x over previous
#include <cuda_runtime.h>
#include <cuda_pipeline.h>
#include <math.h>

#define BB   4
#define TT0  128
#define WD   128
#define EB   16
#define LL   2048
#define ODIM 24
#define TF   122

// ---------------- scratch (no allocations allowed) ----------------
__device__ float g_bufA[BB*WD*TT0*EB];   // 4 MB
__device__ float g_bufB[BB*WD*TT0*EB];   // 4 MB
__device__ float g_bufR[BB*WD*TT0*EB];   // 4 MB (residual-path output)
__device__ float g_Mt[2*WD*WD];          // Mt[m*128+n] = (Wq Wk^T)[n][m]
__device__ float g_uu[2*WD];             // u = Wq bk
__device__ float g_ww[2*WD];             // w = Wk bq
__device__ float g_cc[2];                // c = bq . bk
__device__ float g_yv[BB*126*WD];        // per-(b,t) y vectors

// ---------------- f32x2 packed helpers ----------------
__device__ __forceinline__ unsigned long long fma2(unsigned long long a,
                                                   unsigned long long b,
                                                   unsigned long long c) {
    unsigned long long d;
    asm("fma.rn.f32x2 %0, %1, %2, %3;" : "=l"(d) : "l"(a), "l"(b), "l"(c));
    return d;
}
__device__ __forceinline__ unsigned long long pack2(float v) {
    unsigned long long r;
    asm("mov.b64 %0, {%1, %1};" : "=l"(r) : "f"(v));
    return r;
}
__device__ __forceinline__ void unpack2(unsigned long long v, float& lo, float& hi) {
    asm("mov.b64 {%0, %1}, %2;" : "=f"(lo), "=f"(hi) : "l"(v));
}

// ---------------- embed: x_in -> (B,N,T,E) ----------------
__global__ void k_embed(const float* __restrict__ x_in,
                        const float* __restrict__ emb_w,
                        const float* __restrict__ emb_b,
                        float* __restrict__ out) {
    int idx = blockIdx.x*blockDim.x + threadIdx.x;   // over B*T*N
    if (idx >= BB*TT0*WD) return;
    int n = idx & 127;
    int t = (idx >> 7) & 127;
    int b = idx >> 14;
    const float* xi = x_in + (b*TT0 + t)*131;
    float v  = xi[n];
    float f0 = xi[128], f1 = xi[129], f2 = xi[130];
    float* o = out + ((b*WD + n)*TT0 + t)*EB;
    #pragma unroll
    for (int e = 0; e < EB; e++)
        o[e] = v*emb_w[e] + f0*emb_w[16+e] + f1*emb_w[32+e] + f2*emb_w[48+e] + emb_b[e];
}

// ---------------- precompute Mt[m*128+n] = sum_l Wq[n,l]*Wk[m,l], both layers ----------------
__global__ void k_mt(const float* __restrict__ Wq0, const float* __restrict__ Wk0,
                     const float* __restrict__ Wq1, const float* __restrict__ Wk1,
                     float* __restrict__ Mt) {
    __shared__ float Aq[16][65], Ak[16][65];
    int ly = blockIdx.y;
    const float* Wq = ly ? Wq1 : Wq0;
    const float* Wk = ly ? Wk1 : Wk0;
    float* Mto = Mt + ly*WD*WD;
    int bm = blockIdx.x >> 3, bn = blockIdx.x & 7;
    int m0 = bm*16, n0 = bn*16;
    int ty = threadIdx.x >> 4, tx = threadIdx.x & 15;  // ty -> m, tx -> n
    float acc = 0.f;
    for (int l0 = 0; l0 < LL; l0 += 64) {
        #pragma unroll
        for (int r = 0; r < 4; r++) {
            int idx = threadIdx.x + r*256;
            int row = idx >> 6, col = idx & 63;
            Aq[row][col] = Wq[(n0+row)*LL + l0 + col];
            Ak[row][col] = Wk[(m0+row)*LL + l0 + col];
        }
        __syncthreads();
        #pragma unroll
        for (int lc = 0; lc < 64; lc++)
            acc += Ak[ty][lc]*Aq[tx][lc];
        __syncthreads();
    }
    Mto[(m0+ty)*WD + (n0+tx)] = acc;
}

// ---------------- precompute u, w, c (both layers) ----------------
__global__ void k_uw(const float* __restrict__ Wq0, const float* __restrict__ Wk0,
                     const float* __restrict__ bq0, const float* __restrict__ bk0,
                     const float* __restrict__ Wq1, const float* __restrict__ Wk1,
                     const float* __restrict__ bq1, const float* __restrict__ bk1,
                     float* __restrict__ u, float* __restrict__ w, float* __restrict__ cp) {
    int ly = blockIdx.y;
    const float* Wq = ly ? Wq1 : Wq0;
    const float* Wk = ly ? Wk1 : Wk0;
    const float* bq = ly ? bq1 : bq0;
    const float* bk = ly ? bk1 : bk0;
    int n = blockIdx.x;
    __shared__ float su[256], sw[256], sc[256];
    float pu = 0.f, pw = 0.f, pc = 0.f;
    for (int l = threadIdx.x; l < LL; l += 256) {
        float bkl = bk[l], bql = bq[l];
        pu += Wq[n*LL + l]*bkl;
        pw += Wk[n*LL + l]*bql;
        if (n == 0) pc += bql*bkl;
    }
    su[threadIdx.x] = pu; sw[threadIdx.x] = pw; sc[threadIdx.x] = pc;
    __syncthreads();
    for (int s = 128; s > 0; s >>= 1) {
        if (threadIdx.x < s) {
            su[threadIdx.x] += su[threadIdx.x + s];
            sw[threadIdx.x] += sw[threadIdx.x + s];
            sc[threadIdx.x] += sc[threadIdx.x + s];
        }
        __syncthreads();
    }
    if (threadIdx.x == 0) {
        u[ly*WD + n] = su[0]; w[ly*WD + n] = sw[0];
        if (n == 0) cp[ly] = sc[0];
    }
}

// ---------------- gated conv GEMM + cp.async double-buffered pipeline ----------------
// j = t*16+e flattened per batch. Block tile 64o x 64j, thread 4o x 8j, 128 thr.
// Y[o,j] = tanh(F+bf)*sigmoid(G+bg)
template<int TIN, int TOUT, int D>
__global__ void k_gatedg(const float* __restrict__ X,
                         const float* __restrict__ wf, const float* __restrict__ bf,
                         const float* __restrict__ wg, const float* __restrict__ bg,
                         float* __restrict__ Y) {
    constexpr int TIN16  = TIN*16;
    constexpr int TOUT16 = TOUT*16;
    constexpr int OFF    = 16*D;          // tap-1 column offset (32 or 64)
    constexpr int APAD   = 36;            // 16B-aligned padded row for Af/Ag
    constexpr int AFS    = 64*APAD;       // 2304 floats per weight buffer
    constexpr int BSS    = 16*136;        // 2176 floats
    constexpr int STRIDE = 2*AFS + BSS;   // 6784 floats per buffer
    extern __shared__ float sm[];         // 2*STRIDE*4 = 54272 bytes

    int bx = blockIdx.x;
    int oB = bx & 1;                      // o-half
    int jT = bx >> 1;                     // j tile
    int b  = blockIdx.y;
    int j0b = jT*64;
    int tid = threadIdx.x;                // 128
    int jt = tid & 7;                     // j-group: j = j0b + jt*8 .. +7
    int ot = tid >> 3;                    // o-group: o_local = ot*4 .. +3

    unsigned long long fa[4][4], ga[4][4];
    #pragma unroll
    for (int oo = 0; oo < 4; oo++)
        #pragma unroll
        for (int p = 0; p < 4; p++) { fa[oo][p] = 0ull; ga[oo][p] = 0ull; }

    // stage chunk i0 into buffer buf via cp.async (16B ops)
    auto stage = [&](int i0, int buf) {
        float* Af_ = sm + buf*STRIDE;
        float* Ag_ = Af_ + AFS;
        float* Bs_ = Ag_ + AFS;
        // weights: 64 ol x 8 kk-quads per matrix = 512 tasks each
        #pragma unroll
        for (int r = 0; r < 4; r++) {
            int idx = tid + r*128;
            int kq = idx & 7, ol = idx >> 3;
            const float* srcF = wf + (size_t)(oB*64 + ol)*(WD*2) + i0*2 + kq*4;
            const float* srcG = wg + (size_t)(oB*64 + ol)*(WD*2) + i0*2 + kq*4;
            __pipeline_memcpy_async(Af_ + ol*APAD + kq*4, srcF, 16);
            __pipeline_memcpy_async(Ag_ + ol*APAD + kq*4, srcG, 16);
        }
        // X: 16 il x 32 c-quads = 512 tasks; boundary chunks are fully in/out (4 | TIN16)
        #pragma unroll
        for (int r = 0; r < 4; r++) {
            int idx = tid + r*128;
            int cq = idx & 31, il = idx >> 5;
            int jg = j0b + cq*4;
            float* dst = Bs_ + il*136 + cq*4;
            if (jg + 3 < TIN16) {
                const float* src = X + ((size_t)(b*WD + i0 + il))*TIN16 + jg;
                __pipeline_memcpy_async(dst, src, 16);
            } else {
                *(float4*)dst = make_float4(0.f, 0.f, 0.f, 0.f);
            }
        }
    };

    stage(0, 0);
    __pipeline_commit();
    __pipeline_wait_prior(0);
    __syncthreads();

    #pragma unroll
    for (int ch = 0; ch < 8; ch++) {
        int cur = ch & 1;
        if (ch < 7) {                       // prefetch next chunk under compute
            stage((ch + 1)*16, cur ^ 1);
            __pipeline_commit();
        }

        const float* Af_ = sm + cur*STRIDE;
        const float* Ag_ = Af_ + AFS;
        const float* Bs_ = Ag_ + AFS;
        #pragma unroll 4
        for (int il = 0; il < 16; il++) {
            #pragma unroll
            for (int tap = 0; tap < 2; tap++) {
                int k = il*2 + tap;
                const float* bp = Bs_ + il*136 + jt*8 + tap*OFF;
                ulonglong2 q0 = *(const ulonglong2*)bp;
                ulonglong2 q1 = *(const ulonglong2*)(bp + 4);
                unsigned long long bq[4] = {q0.x, q0.y, q1.x, q1.y};
                #pragma unroll
                for (int oo = 0; oo < 4; oo++) {
                    unsigned long long paf = pack2(Af_[(ot*4 + oo)*APAD + k]);
                    unsigned long long pag = pack2(Ag_[(ot*4 + oo)*APAD + k]);
                    #pragma unroll
                    for (int p = 0; p < 4; p++) {
                        fa[oo][p] = fma2(paf, bq[p], fa[oo][p]);
                        ga[oo][p] = fma2(pag, bq[p], ga[oo][p]);
                    }
                }
            }
        }
        if (ch < 7) __pipeline_wait_prior(0);
        __syncthreads();   // compute(cur) done + prefetched stores visible
    }

    int jbase = j0b + jt*8;
    if (jbase < TOUT16) {   // TOUT16 % 8 == 0 -> whole 8-j group valid
        #pragma unroll
        for (int oo = 0; oo < 4; oo++) {
            int o = oB*64 + ot*4 + oo;
            float bfo = bf[o], bgo = bg[o];
            float fv[8], gv[8];
            #pragma unroll
            for (int p = 0; p < 4; p++) {
                unpack2(fa[oo][p], fv[2*p], fv[2*p+1]);
                unpack2(ga[oo][p], gv[2*p], gv[2*p+1]);
            }
            float yv[8];
            #pragma unroll
            for (int q = 0; q < 8; q++)
                yv[q] = tanhf(fv[q] + bfo)*(1.f/(1.f + expf(-(gv[q] + bgo))));
            float* yp = Y + ((size_t)(b*WD + o))*TOUT16 + jbase;
            *(float4*)(yp)     = make_float4(yv[0], yv[1], yv[2], yv[3]);
            *(float4*)(yp + 4) = make_float4(yv[4], yv[5], yv[6], yv[7]);
        }
    }
}

// ---------------- residual path: R = X @ ws + bs (pure write, RPB=64) ----------------
template<int TIN, int TOUT>
__global__ void k_res2(const float* __restrict__ X, const float* __restrict__ ws,
                       const float* __restrict__ bs, float* __restrict__ R) {
    constexpr int RPB = 64;
    constexpr int KC  = 32;
    __shared__ float As[KC][RPB];       // [t][row]
    __shared__ float Ws[KC][132];       // [t][s], 16B-aligned rows
    int b  = blockIdx.x >> 5;
    int r0 = (blockIdx.x & 31)*RPB;
    int tid = threadIdx.x;              // 256
    int rq = tid >> 4;                  // 0..15 -> rows rq*4..+3
    int sg = tid & 15;                  // s = sg*8 .. +7

    unsigned long long acc[4][4];
    #pragma unroll
    for (int r = 0; r < 4; r++)
        #pragma unroll
        for (int j = 0; j < 4; j++) acc[r][j] = 0ull;

    for (int t0 = 0; t0 < TIN; t0 += KC) {
        __syncthreads();
        #pragma unroll
        for (int j = 0; j < (RPB*KC)/256; j++) {
            int idx = tid + j*256;
            int row = idx & (RPB-1);
            int t = idx >> 6;
            int rr = r0 + row;
            int n = rr >> 4, e = rr & 15;
            int tg = t0 + t;
            As[t][row] = (tg < TIN) ? X[((b*WD + n)*TIN + tg)*EB + e] : 0.f;
        }
        #pragma unroll
        for (int j = 0; j < (KC*128)/256; j++) {
            int idx = tid + j*256;
            int s = idx & 127;
            int t = idx >> 7;
            int tg = t0 + t;
            Ws[t][s] = (tg < TIN && s < TOUT) ? ws[tg*TOUT + s] : 0.f;
        }
        __syncthreads();
        #pragma unroll
        for (int t = 0; t < KC; t++) {
            float4 w0 = *(const float4*)(&Ws[t][sg*8]);
            float4 w1 = *(const float4*)(&Ws[t][sg*8 + 4]);
            unsigned long long wv[4];
            wv[0] = ((unsigned long long)__float_as_uint(w0.y) << 32) | __float_as_uint(w0.x);
            wv[1] = ((unsigned long long)__float_as_uint(w0.w) << 32) | __float_as_uint(w0.z);
            wv[2] = ((unsigned long long)__float_as_uint(w1.y) << 32) | __float_as_uint(w1.x);
            wv[3] = ((unsigned long long)__float_as_uint(w1.w) << 32) | __float_as_uint(w1.z);
            #pragma unroll
            for (int r = 0; r < 4; r++) {
                unsigned long long av = pack2(As[t][rq*4 + r]);
                #pragma unroll
                for (int j = 0; j < 4; j++)
                    acc[r][j] = fma2(av, wv[j], acc[r][j]);
            }
        }
    }
    #pragma unroll
    for (int r = 0; r < 4; r++) {
        int rr = r0 + rq*4 + r;
        int n = rr >> 4, e = rr & 15;
        float* yp = R + ((size_t)(b*WD + n)*TOUT)*EB + e;
        #pragma unroll
        for (int j = 0; j < 4; j++) {
            float lo, hi; unpack2(acc[r][j], lo, hi);
            int s0 = sg*8 + j*2;
            if (s0 < TOUT)   yp[s0*EB]     = lo + bs[s0];
            if (s0+1 < TOUT) yp[(s0+1)*EB] = hi + bs[s0+1];
        }
    }
}

// ---------------- fused attention: X = Xg+Xr; Z GEMM + softmax + ybar ----------------
template<int T>
__global__ void k_attn2(const float* __restrict__ Xg, const float* __restrict__ Xr,
                        const float* __restrict__ Mt,
                        const float* __restrict__ u, const float* __restrict__ w,
                        const float* __restrict__ cptr, float* __restrict__ yout) {
    __shared__ __align__(16) float Xs[WD*EB];   // [n][e] 8KB
    __shared__ __align__(16) float Ms[32*WD];   // Mt chunk [k][n] 16KB
    __shared__ float Zs[EB][WD+5];              // [f][n]
    __shared__ float Ss[EB][EB+1];
    __shared__ float uev[EB], wfv[EB], abar[EB];
    int bt = blockIdx.x;
    int b = bt / T, t = bt % T;
    int tid = threadIdx.x;                      // 256
    // load Xs = Xg + Xr (vectorized)
    for (int idx = tid; idx < WD*4; idx += 256) {
        int n = idx >> 2, q = idx & 3;
        size_t off = ((size_t)((b*WD + n)*T + t))*EB + q*4;
        float4 a = *(const float4*)(Xg + off);
        float4 r = *(const float4*)(Xr + off);
        ((float4*)Xs)[idx] = make_float4(a.x + r.x, a.y + r.y, a.z + r.z, a.w + r.w);
    }
    // Z[fh*8..+7][n] per thread (n = tid&127, fh = tid>>7)
    int n_ = tid & 127, fh = tid >> 7;
    unsigned long long zacc[4] = {0ull, 0ull, 0ull, 0ull};
    for (int m0 = 0; m0 < WD; m0 += 32) {
        __syncthreads();
        #pragma unroll
        for (int rep = 0; rep < (32*WD/4)/256; rep++)
            ((float4*)Ms)[tid + rep*256] = ((const float4*)(Mt + m0*WD))[tid + rep*256];
        __syncthreads();
        #pragma unroll
        for (int k = 0; k < 32; k++) {
            unsigned long long pm = pack2(Ms[k*WD + n_]);
            const ulonglong2* xp = (const ulonglong2*)(Xs + (m0 + k)*16 + fh*8);
            ulonglong2 xa = xp[0];
            zacc[0] = fma2(pm, xa.x, zacc[0]);
            zacc[1] = fma2(pm, xa.y, zacc[1]);
            ulonglong2 xb = xp[1];
            zacc[2] = fma2(pm, xb.x, zacc[2]);
            zacc[3] = fma2(pm, xb.y, zacc[3]);
        }
    }
    #pragma unroll
    for (int j = 0; j < 4; j++) {
        float lo, hi; unpack2(zacc[j], lo, hi);
        Zs[fh*8 + 2*j][n_]     = lo;
        Zs[fh*8 + 2*j + 1][n_] = hi;
    }
    if (tid < 16) {
        float a = 0.f;
        for (int n = 0; n < WD; n++) a += Xs[n*16 + tid]*u[n];
        uev[tid] = a;
    } else if (tid < 32) {
        int f = tid - 16;
        float a = 0.f;
        for (int n = 0; n < WD; n++) a += Xs[n*16 + f]*w[n];
        wfv[f] = a;
    }
    __syncthreads();
    {
        int e = tid >> 4, f = tid & 15;
        float acc = 0.f;
        #pragma unroll 4
        for (int n = 0; n < WD; n++)
            acc += Xs[n*16 + e]*Zs[f][n];
        const float scale = 0.022097086912079608f; // 1/sqrt(2048)
        Ss[e][f] = (acc + uev[e] + wfv[f] + cptr[0])*scale;
    }
    __syncthreads();
    if (tid < 16) {
        int e = tid;
        float mx = -1e30f;
        #pragma unroll
        for (int f = 0; f < 16; f++) mx = fmaxf(mx, Ss[e][f]);
        float ex[16]; float sum = 0.f;
        #pragma unroll
        for (int f = 0; f < 16; f++) { ex[f] = expf(Ss[e][f] - mx); sum += ex[f]; }
        float inv = 1.f/sum;
        #pragma unroll
        for (int f = 0; f < 16; f++) Ss[e][f] = ex[f]*inv;
    }
    __syncthreads();
    if (tid < 16) {
        int f = tid;
        float a = 0.f;
        #pragma unroll
        for (int e = 0; e < 16; e++) a += Ss[e][f];
        abar[f] = a*(1.f/16.f);
    }
    __syncthreads();
    if (tid < 128) {
        int n = tid;
        float a = 0.f;
        #pragma unroll
        for (int f = 0; f < 16; f++) a += Xs[n*16 + f]*abar[f];
        yout[bt*WD + n] = a;
    }
}

// ---------------- attention out: Y = (Xg+Xr) + y @ Wv + bv ----------------
template<int T>
__global__ void k_attn_out(const float* __restrict__ Xg, const float* __restrict__ Xr,
                           const float* __restrict__ yv,
                           const float* __restrict__ Wv, const float* __restrict__ bv,
                           float* __restrict__ Yout) {
    __shared__ float ys[64][WD];
    const int BT = BB*T;
    int bt0 = blockIdx.y*64;
    int l = blockIdx.x*128 + (threadIdx.x & 127);
    int half = threadIdx.x >> 7;
    for (int idx = threadIdx.x; idx < 64*WD; idx += 256) {
        int r = idx >> 7, m = idx & 127;
        int bt = bt0 + r;
        ys[r][m] = (bt < BT) ? yv[bt*WD + m] : 0.f;
    }
    __syncthreads();
    float acc[32];
    #pragma unroll
    for (int j = 0; j < 32; j++) acc[j] = 0.f;
    for (int m = 0; m < WD; m++) {
        float wvv = Wv[m*LL + l];
        #pragma unroll
        for (int j = 0; j < 32; j++) acc[j] += ys[half*32 + j][m]*wvv;
    }
    float bvl = bv[l];
    int n = l >> 4, e = l & 15;
    #pragma unroll
    for (int j = 0; j < 32; j++) {
        int bt = bt0 + half*32 + j;
        if (bt < BT) {
            int b = bt / T, t = bt % T;
            size_t idx = ((size_t)((b*WD + n)*T + t))*EB + e;
            Yout[idx] = Xg[idx] + Xr[idx] + acc[j] + bvl;
        }
    }
}

// ---------------- decode + time-mix output ----------------
__global__ void k_decode(const float* __restrict__ X, const float* __restrict__ dec_w,
                         const float* __restrict__ dec_b, const float* __restrict__ out_w,
                         const float* __restrict__ out_b, float* __restrict__ out) {
    __shared__ float sy[TF];
    int b = blockIdx.x >> 7, n = blockIdx.x & 127;
    int t = threadIdx.x;
    if (t < TF) {
        const float* xp = X + ((size_t)(b*WD + n)*TF + t)*EB;
        float a = dec_b[n];
        #pragma unroll
        for (int e = 0; e < EB; e++) a += xp[e]*dec_w[n*EB + e];
        sy[t] = a;
    }
    __syncthreads();
    if (t < ODIM) {
        float a = out_b[t];
        for (int tt = 0; tt < TF; tt++) a += sy[tt]*out_w[tt*ODIM + t];
        out[(b*ODIM + t)*WD + n] = a;
    }
}

// ---------------- launcher: fork (mt/uw + res on side stream) ----------------
extern "C" void kernel_launch(void* const* d_in, const int* in_sizes, int n_in,
                              void* d_out, int out_size) {
    const float* x_in  = (const float*)d_in[0];
    const float* emb_w = (const float*)d_in[1];
    const float* emb_b = (const float*)d_in[2];
    const float* g0_wf = (const float*)d_in[3];
    const float* g0_bf = (const float*)d_in[4];
    const float* g0_wg = (const float*)d_in[5];
    const float* g0_bg = (const float*)d_in[6];
    const float* g0_ws = (const float*)d_in[7];
    const float* g0_bs = (const float*)d_in[8];
    const float* a0_wq = (const float*)d_in[9];
    const float* a0_bq = (const float*)d_in[10];
    const float* a0_wk = (const float*)d_in[11];
    const float* a0_bk = (const float*)d_in[12];
    const float* a0_wv = (const float*)d_in[13];
    const float* a0_bv = (const float*)d_in[14];
    const float* g1_wf = (const float*)d_in[15];
    const float* g1_bf = (const float*)d_in[16];
    const float* g1_wg = (const float*)d_in[17];
    const float* g1_bg = (const float*)d_in[18];
    const float* g1_ws = (const float*)d_in[19];
    const float* g1_bs = (const float*)d_in[20];
    const float* a1_wq = (const float*)d_in[21];
    const float* a1_bq = (const float*)d_in[22];
    const float* a1_wk = (const float*)d_in[23];
    const float* a1_bk = (const float*)d_in[24];
    const float* a1_wv = (const float*)d_in[25];
    const float* a1_bv = (const float*)d_in[26];
    const float* dec_w = (const float*)d_in[27];
    const float* dec_b = (const float*)d_in[28];
    const float* out_w = (const float*)d_in[29];
    const float* out_b = (const float*)d_in[30];

    float *dA, *dB, *dR, *dMt, *dU, *dW, *dC, *dY;
    cudaGetSymbolAddress((void**)&dA,  g_bufA);
    cudaGetSymbolAddress((void**)&dB,  g_bufB);
    cudaGetSymbolAddress((void**)&dR,  g_bufR);
    cudaGetSymbolAddress((void**)&dMt, g_Mt);
    cudaGetSymbolAddress((void**)&dU,  g_uu);
    cudaGetSymbolAddress((void**)&dW,  g_ww);
    cudaGetSymbolAddress((void**)&dC,  g_cc);
    cudaGetSymbolAddress((void**)&dY,  g_yv);

    // double-buffered smem: 2*(2*64*36 + 16*136)*4 = 54272 bytes
    const int SMEM_G = 2*(2*64*36 + 16*136)*4;
    cudaFuncSetAttribute(k_gatedg<128,126,2>, cudaFuncAttributeMaxDynamicSharedMemorySize, SMEM_G);
    cudaFuncSetAttribute(k_gatedg<126,122,4>, cudaFuncAttributeMaxDynamicSharedMemorySize, SMEM_G);

    // side stream + events (host resources, created once)
    static cudaStream_t s2 = nullptr;
    static cudaEvent_t evOrigin = nullptr, evEmbed = nullptr,
                       evRes0 = nullptr, evAO0 = nullptr, evRes1 = nullptr;
    if (s2 == nullptr) {
        cudaStreamCreateWithFlags(&s2, cudaStreamNonBlocking);
        cudaEventCreateWithFlags(&evOrigin, cudaEventDisableTiming);
        cudaEventCreateWithFlags(&evEmbed,  cudaEventDisableTiming);
        cudaEventCreateWithFlags(&evRes0,   cudaEventDisableTiming);
        cudaEventCreateWithFlags(&evAO0,    cudaEventDisableTiming);
        cudaEventCreateWithFlags(&evRes1,   cudaEventDisableTiming);
    }

    // fork: side stream computes mt/uw, then res0/res1 when inputs ready
    cudaEventRecord(evOrigin, 0);
    cudaStreamWaitEvent(s2, evOrigin, 0);
    k_mt<<<dim3(64,2), 256, 0, s2>>>(a0_wq, a0_wk, a1_wq, a1_wk, dMt);
    k_uw<<<dim3(128,2), 256, 0, s2>>>(a0_wq, a0_wk, a0_bq, a0_bk,
                                      a1_wq, a1_wk, a1_bq, a1_bk, dU, dW, dC);

    // main stream: embed
    k_embed<<<(BB*TT0*WD + 255)/256, 256>>>(x_in, emb_w, emb_b, dA);
    cudaEventRecord(evEmbed, 0);

    // side stream: res0 (needs embed output dA)
    cudaStreamWaitEvent(s2, evEmbed, 0);
    k_res2<128,126><<<BB*32, 256, 0, s2>>>(dA, g0_ws, g0_bs, dR);
    cudaEventRecord(evRes0, s2);

    // layer 0: gated0 (main, concurrent with mt/uw/res0), then attn
    {
        const int ntileJ = (126*16 + 63)/64;  // 32
        k_gatedg<128,126,2><<<dim3(ntileJ*2, BB), 128, SMEM_G>>>(dA, g0_wf, g0_bf, g0_wg, g0_bg, dB);
        cudaStreamWaitEvent(0, evRes0, 0);   // join: implies mt/uw done too (same stream order)
        k_attn2<126><<<BB*126, 256>>>(dB, dR, dMt, dU, dW, dC, dY);
        k_attn_out<126><<<dim3(16, (BB*126 + 63)/64), 256>>>(dB, dR, dY, a0_wv, a0_bv, dA);
        cudaEventRecord(evAO0, 0);
    }

    // side stream: res1 (needs attn_out0's dA; dR free after attn_out0)
    cudaStreamWaitEvent(s2, evAO0, 0);
    k_res2<126,122><<<BB*32, 256, 0, s2>>>(dA, g1_ws, g1_bs, dR);
    cudaEventRecord(evRes1, s2);

    // layer 1: gated1 (main, concurrent with res1), then attn
    {
        const int ntileJ = (122*16 + 63)/64;  // 31
        k_gatedg<126,122,4><<<dim3(ntileJ*2, BB), 128, SMEM_G>>>(dA, g1_wf, g1_bf, g1_wg, g1_bg, dB);
        cudaStreamWaitEvent(0, evRes1, 0);   // joins s2 back before graph end
        k_attn2<122><<<BB*122, 256>>>(dB, dR, dMt + WD*WD, dU + WD, dW + WD, dC + 1, dY);
        k_attn_out<122><<<dim3(16, (BB*122 + 63)/64), 256>>>(dB, dR, dY, a1_wv, a1_bv, dA);
    }

    // decode
    k_decode<<<BB*WD, 128>>>(dA, dec_w, dec_b, out_w, out_b, (float*)d_out);
}

// round 16
// speedup vs baseline: 1.8639x; 1.2712x over previous
#include <cuda_runtime.h>
#include <cuda_pipeline.h>
#include <math.h>

#define BB   4
#define TT0  128
#define WD   128
#define EB   16
#define LL   2048
#define ODIM 24
#define TF   122

// ---------------- scratch (no allocations allowed) ----------------
__device__ float g_bufA[BB*WD*TT0*EB];   // 4 MB
__device__ float g_bufB[BB*WD*TT0*EB];   // 4 MB
__device__ float g_bufR[BB*WD*TT0*EB];   // 4 MB (residual-path output)
__device__ float g_Mt[2*WD*WD];          // Mt[m*128+n] = (Wq Wk^T)[n][m]
__device__ float g_uu[2*WD];             // u = Wq bk
__device__ float g_ww[2*WD];             // w = Wk bq
__device__ float g_cc[2];                // c = bq . bk
__device__ float g_yv[BB*126*WD];        // per-(b,t) y vectors

// ---------------- f32x2 packed helpers ----------------
__device__ __forceinline__ unsigned long long fma2(unsigned long long a,
                                                   unsigned long long b,
                                                   unsigned long long c) {
    unsigned long long d;
    asm("fma.rn.f32x2 %0, %1, %2, %3;" : "=l"(d) : "l"(a), "l"(b), "l"(c));
    return d;
}
__device__ __forceinline__ unsigned long long pack2(float v) {
    unsigned long long r;
    asm("mov.b64 %0, {%1, %1};" : "=l"(r) : "f"(v));
    return r;
}
__device__ __forceinline__ void unpack2(unsigned long long v, float& lo, float& hi) {
    asm("mov.b64 {%0, %1}, %2;" : "=f"(lo), "=f"(hi) : "l"(v));
}

// ---------------- embed: x_in -> (B,N,T,E) ----------------
__global__ void k_embed(const float* __restrict__ x_in,
                        const float* __restrict__ emb_w,
                        const float* __restrict__ emb_b,
                        float* __restrict__ out) {
    int idx = blockIdx.x*blockDim.x + threadIdx.x;   // over B*T*N
    if (idx >= BB*TT0*WD) return;
    int n = idx & 127;
    int t = (idx >> 7) & 127;
    int b = idx >> 14;
    const float* xi = x_in + (b*TT0 + t)*131;
    float v  = xi[n];
    float f0 = xi[128], f1 = xi[129], f2 = xi[130];
    float* o = out + ((b*WD + n)*TT0 + t)*EB;
    #pragma unroll
    for (int e = 0; e < EB; e++)
        o[e] = v*emb_w[e] + f0*emb_w[16+e] + f1*emb_w[32+e] + f2*emb_w[48+e] + emb_b[e];
}

// ---------------- precompute Mt[m*128+n] = sum_l Wq[n,l]*Wk[m,l], both layers ----------------
__global__ void k_mt(const float* __restrict__ Wq0, const float* __restrict__ Wk0,
                     const float* __restrict__ Wq1, const float* __restrict__ Wk1,
                     float* __restrict__ Mt) {
    __shared__ float Aq[16][65], Ak[16][65];
    int ly = blockIdx.y;
    const float* Wq = ly ? Wq1 : Wq0;
    const float* Wk = ly ? Wk1 : Wk0;
    float* Mto = Mt + ly*WD*WD;
    int bm = blockIdx.x >> 3, bn = blockIdx.x & 7;
    int m0 = bm*16, n0 = bn*16;
    int ty = threadIdx.x >> 4, tx = threadIdx.x & 15;  // ty -> m, tx -> n
    float acc = 0.f;
    for (int l0 = 0; l0 < LL; l0 += 64) {
        #pragma unroll
        for (int r = 0; r < 4; r++) {
            int idx = threadIdx.x + r*256;
            int row = idx >> 6, col = idx & 63;
            Aq[row][col] = Wq[(n0+row)*LL + l0 + col];
            Ak[row][col] = Wk[(m0+row)*LL + l0 + col];
        }
        __syncthreads();
        #pragma unroll
        for (int lc = 0; lc < 64; lc++)
            acc += Ak[ty][lc]*Aq[tx][lc];
        __syncthreads();
    }
    Mto[(m0+ty)*WD + (n0+tx)] = acc;
}

// ---------------- precompute u, w, c (both layers) ----------------
__global__ void k_uw(const float* __restrict__ Wq0, const float* __restrict__ Wk0,
                     const float* __restrict__ bq0, const float* __restrict__ bk0,
                     const float* __restrict__ Wq1, const float* __restrict__ Wk1,
                     const float* __restrict__ bq1, const float* __restrict__ bk1,
                     float* __restrict__ u, float* __restrict__ w, float* __restrict__ cp) {
    int ly = blockIdx.y;
    const float* Wq = ly ? Wq1 : Wq0;
    const float* Wk = ly ? Wk1 : Wk0;
    const float* bq = ly ? bq1 : bq0;
    const float* bk = ly ? bk1 : bk0;
    int n = blockIdx.x;
    __shared__ float su[256], sw[256], sc[256];
    float pu = 0.f, pw = 0.f, pc = 0.f;
    for (int l = threadIdx.x; l < LL; l += 256) {
        float bkl = bk[l], bql = bq[l];
        pu += Wq[n*LL + l]*bkl;
        pw += Wk[n*LL + l]*bql;
        if (n == 0) pc += bql*bkl;
    }
    su[threadIdx.x] = pu; sw[threadIdx.x] = pw; sc[threadIdx.x] = pc;
    __syncthreads();
    for (int s = 128; s > 0; s >>= 1) {
        if (threadIdx.x < s) {
            su[threadIdx.x] += su[threadIdx.x + s];
            sw[threadIdx.x] += sw[threadIdx.x + s];
            sc[threadIdx.x] += sc[threadIdx.x + s];
        }
        __syncthreads();
    }
    if (threadIdx.x == 0) {
        u[ly*WD + n] = su[0]; w[ly*WD + n] = sw[0];
        if (n == 0) cp[ly] = sc[0];
    }
}

// ---------------- gated conv GEMM + cp.async double-buffered pipeline ----------------
// j = t*16+e flattened per batch. Block tile 64o x 64j, thread 4o x 8j, 128 thr.
// Y[o,j] = tanh(F+bf)*sigmoid(G+bg)
template<int TIN, int TOUT, int D>
__global__ void k_gatedg(const float* __restrict__ X,
                         const float* __restrict__ wf, const float* __restrict__ bf,
                         const float* __restrict__ wg, const float* __restrict__ bg,
                         float* __restrict__ Y) {
    constexpr int TIN16  = TIN*16;
    constexpr int TOUT16 = TOUT*16;
    constexpr int OFF    = 16*D;          // tap-1 column offset (32 or 64)
    constexpr int APAD   = 36;            // 16B-aligned padded row for Af/Ag
    constexpr int AFS    = 64*APAD;       // 2304 floats per weight buffer
    constexpr int BSS    = 16*136;        // 2176 floats
    constexpr int STRIDE = 2*AFS + BSS;   // 6784 floats per buffer
    extern __shared__ float sm[];         // 2*STRIDE*4 = 54272 bytes

    int bx = blockIdx.x;
    int oB = bx & 1;                      // o-half
    int jT = bx >> 1;                     // j tile
    int b  = blockIdx.y;
    int j0b = jT*64;
    int tid = threadIdx.x;                // 128
    int jt = tid & 7;                     // j-group: j = j0b + jt*8 .. +7
    int ot = tid >> 3;                    // o-group: o_local = ot*4 .. +3

    unsigned long long fa[4][4], ga[4][4];
    #pragma unroll
    for (int oo = 0; oo < 4; oo++)
        #pragma unroll
        for (int p = 0; p < 4; p++) { fa[oo][p] = 0ull; ga[oo][p] = 0ull; }

    // stage chunk i0 into buffer buf via cp.async (16B ops)
    auto stage = [&](int i0, int buf) {
        float* Af_ = sm + buf*STRIDE;
        float* Ag_ = Af_ + AFS;
        float* Bs_ = Ag_ + AFS;
        #pragma unroll
        for (int r = 0; r < 4; r++) {
            int idx = tid + r*128;
            int kq = idx & 7, ol = idx >> 3;
            const float* srcF = wf + (size_t)(oB*64 + ol)*(WD*2) + i0*2 + kq*4;
            const float* srcG = wg + (size_t)(oB*64 + ol)*(WD*2) + i0*2 + kq*4;
            __pipeline_memcpy_async(Af_ + ol*APAD + kq*4, srcF, 16);
            __pipeline_memcpy_async(Ag_ + ol*APAD + kq*4, srcG, 16);
        }
        #pragma unroll
        for (int r = 0; r < 4; r++) {
            int idx = tid + r*128;
            int cq = idx & 31, il = idx >> 5;
            int jg = j0b + cq*4;
            float* dst = Bs_ + il*136 + cq*4;
            if (jg + 3 < TIN16) {
                const float* src = X + ((size_t)(b*WD + i0 + il))*TIN16 + jg;
                __pipeline_memcpy_async(dst, src, 16);
            } else {
                *(float4*)dst = make_float4(0.f, 0.f, 0.f, 0.f);
            }
        }
    };

    stage(0, 0);
    __pipeline_commit();
    __pipeline_wait_prior(0);
    __syncthreads();

    #pragma unroll
    for (int ch = 0; ch < 8; ch++) {
        int cur = ch & 1;
        if (ch < 7) {
            stage((ch + 1)*16, cur ^ 1);
            __pipeline_commit();
        }

        const float* Af_ = sm + cur*STRIDE;
        const float* Ag_ = Af_ + AFS;
        const float* Bs_ = Ag_ + AFS;
        #pragma unroll 4
        for (int il = 0; il < 16; il++) {
            #pragma unroll
            for (int tap = 0; tap < 2; tap++) {
                int k = il*2 + tap;
                const float* bp = Bs_ + il*136 + jt*8 + tap*OFF;
                ulonglong2 q0 = *(const ulonglong2*)bp;
                ulonglong2 q1 = *(const ulonglong2*)(bp + 4);
                unsigned long long bq[4] = {q0.x, q0.y, q1.x, q1.y};
                #pragma unroll
                for (int oo = 0; oo < 4; oo++) {
                    unsigned long long paf = pack2(Af_[(ot*4 + oo)*APAD + k]);
                    unsigned long long pag = pack2(Ag_[(ot*4 + oo)*APAD + k]);
                    #pragma unroll
                    for (int p = 0; p < 4; p++) {
                        fa[oo][p] = fma2(paf, bq[p], fa[oo][p]);
                        ga[oo][p] = fma2(pag, bq[p], ga[oo][p]);
                    }
                }
            }
        }
        if (ch < 7) __pipeline_wait_prior(0);
        __syncthreads();
    }

    int jbase = j0b + jt*8;
    if (jbase < TOUT16) {
        #pragma unroll
        for (int oo = 0; oo < 4; oo++) {
            int o = oB*64 + ot*4 + oo;
            float bfo = bf[o], bgo = bg[o];
            float fv[8], gv[8];
            #pragma unroll
            for (int p = 0; p < 4; p++) {
                unpack2(fa[oo][p], fv[2*p], fv[2*p+1]);
                unpack2(ga[oo][p], gv[2*p], gv[2*p+1]);
            }
            float yv[8];
            #pragma unroll
            for (int q = 0; q < 8; q++)
                yv[q] = tanhf(fv[q] + bfo)*(1.f/(1.f + expf(-(gv[q] + bgo))));
            float* yp = Y + ((size_t)(b*WD + o))*TOUT16 + jbase;
            *(float4*)(yp)     = make_float4(yv[0], yv[1], yv[2], yv[3]);
            *(float4*)(yp + 4) = make_float4(yv[4], yv[5], yv[6], yv[7]);
        }
    }
}

// ---------------- residual path: R = X @ ws + bs (pure write, RPB=64) ----------------
template<int TIN, int TOUT>
__global__ void k_res2(const float* __restrict__ X, const float* __restrict__ ws,
                       const float* __restrict__ bs, float* __restrict__ R) {
    constexpr int RPB = 64;
    constexpr int KC  = 32;
    __shared__ float As[KC][RPB];       // [t][row]
    __shared__ float Ws[KC][132];       // [t][s], 16B-aligned rows
    int b  = blockIdx.x >> 5;
    int r0 = (blockIdx.x & 31)*RPB;
    int tid = threadIdx.x;              // 256
    int rq = tid >> 4;                  // 0..15 -> rows rq*4..+3
    int sg = tid & 15;                  // s = sg*8 .. +7

    unsigned long long acc[4][4];
    #pragma unroll
    for (int r = 0; r < 4; r++)
        #pragma unroll
        for (int j = 0; j < 4; j++) acc[r][j] = 0ull;

    for (int t0 = 0; t0 < TIN; t0 += KC) {
        __syncthreads();
        #pragma unroll
        for (int j = 0; j < (RPB*KC)/256; j++) {
            int idx = tid + j*256;
            int row = idx & (RPB-1);
            int t = idx >> 6;
            int rr = r0 + row;
            int n = rr >> 4, e = rr & 15;
            int tg = t0 + t;
            As[t][row] = (tg < TIN) ? X[((b*WD + n)*TIN + tg)*EB + e] : 0.f;
        }
        #pragma unroll
        for (int j = 0; j < (KC*128)/256; j++) {
            int idx = tid + j*256;
            int s = idx & 127;
            int t = idx >> 7;
            int tg = t0 + t;
            Ws[t][s] = (tg < TIN && s < TOUT) ? ws[tg*TOUT + s] : 0.f;
        }
        __syncthreads();
        #pragma unroll
        for (int t = 0; t < KC; t++) {
            float4 w0 = *(const float4*)(&Ws[t][sg*8]);
            float4 w1 = *(const float4*)(&Ws[t][sg*8 + 4]);
            unsigned long long wv[4];
            wv[0] = ((unsigned long long)__float_as_uint(w0.y) << 32) | __float_as_uint(w0.x);
            wv[1] = ((unsigned long long)__float_as_uint(w0.w) << 32) | __float_as_uint(w0.z);
            wv[2] = ((unsigned long long)__float_as_uint(w1.y) << 32) | __float_as_uint(w1.x);
            wv[3] = ((unsigned long long)__float_as_uint(w1.w) << 32) | __float_as_uint(w1.z);
            #pragma unroll
            for (int r = 0; r < 4; r++) {
                unsigned long long av = pack2(As[t][rq*4 + r]);
                #pragma unroll
                for (int j = 0; j < 4; j++)
                    acc[r][j] = fma2(av, wv[j], acc[r][j]);
            }
        }
    }
    #pragma unroll
    for (int r = 0; r < 4; r++) {
        int rr = r0 + rq*4 + r;
        int n = rr >> 4, e = rr & 15;
        float* yp = R + ((size_t)(b*WD + n)*TOUT)*EB + e;
        #pragma unroll
        for (int j = 0; j < 4; j++) {
            float lo, hi; unpack2(acc[r][j], lo, hi);
            int s0 = sg*8 + j*2;
            if (s0 < TOUT)   yp[s0*EB]     = lo + bs[s0];
            if (s0+1 < TOUT) yp[(s0+1)*EB] = hi + bs[s0+1];
        }
    }
}

// ---------------- fused attention: X = Xg+Xr; Z GEMM + softmax + ybar ----------------
template<int T>
__global__ void k_attn2(const float* __restrict__ Xg, const float* __restrict__ Xr,
                        const float* __restrict__ Mt,
                        const float* __restrict__ u, const float* __restrict__ w,
                        const float* __restrict__ cptr, float* __restrict__ yout) {
    __shared__ __align__(16) float Xs[WD*EB];   // [n][e] 8KB
    __shared__ __align__(16) float Ms[32*WD];   // Mt chunk [k][n] 16KB
    __shared__ float Zs[EB][WD+5];              // [f][n]
    __shared__ float Ss[EB][EB+1];
    __shared__ float uev[EB], wfv[EB], abar[EB];
    int bt = blockIdx.x;
    int b = bt / T, t = bt % T;
    int tid = threadIdx.x;                      // 256
    for (int idx = tid; idx < WD*4; idx += 256) {
        int n = idx >> 2, q = idx & 3;
        size_t off = ((size_t)((b*WD + n)*T + t))*EB + q*4;
        float4 a = *(const float4*)(Xg + off);
        float4 r = *(const float4*)(Xr + off);
        ((float4*)Xs)[idx] = make_float4(a.x + r.x, a.y + r.y, a.z + r.z, a.w + r.w);
    }
    int n_ = tid & 127, fh = tid >> 7;
    unsigned long long zacc[4] = {0ull, 0ull, 0ull, 0ull};
    for (int m0 = 0; m0 < WD; m0 += 32) {
        __syncthreads();
        #pragma unroll
        for (int rep = 0; rep < (32*WD/4)/256; rep++)
            ((float4*)Ms)[tid + rep*256] = ((const float4*)(Mt + m0*WD))[tid + rep*256];
        __syncthreads();
        #pragma unroll
        for (int k = 0; k < 32; k++) {
            unsigned long long pm = pack2(Ms[k*WD + n_]);
            const ulonglong2* xp = (const ulonglong2*)(Xs + (m0 + k)*16 + fh*8);
            ulonglong2 xa = xp[0];
            zacc[0] = fma2(pm, xa.x, zacc[0]);
            zacc[1] = fma2(pm, xa.y, zacc[1]);
            ulonglong2 xb = xp[1];
            zacc[2] = fma2(pm, xb.x, zacc[2]);
            zacc[3] = fma2(pm, xb.y, zacc[3]);
        }
    }
    #pragma unroll
    for (int j = 0; j < 4; j++) {
        float lo, hi; unpack2(zacc[j], lo, hi);
        Zs[fh*8 + 2*j][n_]     = lo;
        Zs[fh*8 + 2*j + 1][n_] = hi;
    }
    if (tid < 16) {
        float a = 0.f;
        for (int n = 0; n < WD; n++) a += Xs[n*16 + tid]*u[n];
        uev[tid] = a;
    } else if (tid < 32) {
        int f = tid - 16;
        float a = 0.f;
        for (int n = 0; n < WD; n++) a += Xs[n*16 + f]*w[n];
        wfv[f] = a;
    }
    __syncthreads();
    {
        int e = tid >> 4, f = tid & 15;
        float acc = 0.f;
        #pragma unroll 4
        for (int n = 0; n < WD; n++)
            acc += Xs[n*16 + e]*Zs[f][n];
        const float scale = 0.022097086912079608f; // 1/sqrt(2048)
        Ss[e][f] = (acc + uev[e] + wfv[f] + cptr[0])*scale;
    }
    __syncthreads();
    if (tid < 16) {
        int e = tid;
        float mx = -1e30f;
        #pragma unroll
        for (int f = 0; f < 16; f++) mx = fmaxf(mx, Ss[e][f]);
        float ex[16]; float sum = 0.f;
        #pragma unroll
        for (int f = 0; f < 16; f++) { ex[f] = expf(Ss[e][f] - mx); sum += ex[f]; }
        float inv = 1.f/sum;
        #pragma unroll
        for (int f = 0; f < 16; f++) Ss[e][f] = ex[f]*inv;
    }
    __syncthreads();
    if (tid < 16) {
        int f = tid;
        float a = 0.f;
        #pragma unroll
        for (int e = 0; e < 16; e++) a += Ss[e][f];
        abar[f] = a*(1.f/16.f);
    }
    __syncthreads();
    if (tid < 128) {
        int n = tid;
        float a = 0.f;
        #pragma unroll
        for (int f = 0; f < 16; f++) a += Xs[n*16 + f]*abar[f];
        yout[bt*WD + n] = a;
    }
}

// ---------------- attention out v3: tiled GEMM. Y = (Xg+Xr) + ys @ Wv + bv ----------------
// out[bt, l] = sum_m ys[bt, m] * Wv[m, l]. Block 64bt x 64l, thread 4bt x 8l, 128 thr.
template<int T>
__global__ void k_attn_out(const float* __restrict__ Xg, const float* __restrict__ Xr,
                           const float* __restrict__ yv,
                           const float* __restrict__ Wv, const float* __restrict__ bv,
                           float* __restrict__ Yout) {
    const int BT = BB*T;
    __shared__ float Ys[64][132];   // [btl][m], full K
    __shared__ float Ws[32][68];    // [k][l_local] chunk
    int l0  = blockIdx.x*64;
    int bt0 = blockIdx.y*64;
    int tid = threadIdx.x;          // 128
    int rq = tid >> 3;              // 0..15 -> bt rows rq*4..+3 (64 bt)
    int sg = tid & 7;               // l = l0 + sg*8 .. +7 (64 l)

    // stage Ys: 64 bt x 128 m = 2048 float4 / 128 thr = 16 each
    #pragma unroll
    for (int r = 0; r < 16; r++) {
        int i = tid + r*128;
        int btl = i >> 5, q = i & 31;
        int bt = bt0 + btl;
        float4 v = make_float4(0.f, 0.f, 0.f, 0.f);
        if (bt < BT) v = *(const float4*)(yv + (size_t)bt*WD + q*4);
        *(float4*)(&Ys[btl][q*4]) = v;
    }

    unsigned long long acc[4][4];
    #pragma unroll
    for (int r = 0; r < 4; r++)
        #pragma unroll
        for (int j = 0; j < 4; j++) acc[r][j] = 0ull;

    for (int k0 = 0; k0 < WD; k0 += 32) {
        __syncthreads();   // first iter: covers Ys staging too
        // stage Ws chunk: 32 k x 64 l = 512 float4 / 128 thr = 4 each
        #pragma unroll
        for (int r = 0; r < 4; r++) {
            int i = tid + r*128;
            int k = i >> 4, q = i & 15;
            *(float4*)(&Ws[k][q*4]) = *(const float4*)(Wv + (size_t)(k0 + k)*LL + l0 + q*4);
        }
        __syncthreads();
        #pragma unroll
        for (int k = 0; k < 32; k++) {
            float4 w0 = *(const float4*)(&Ws[k][sg*8]);
            float4 w1 = *(const float4*)(&Ws[k][sg*8 + 4]);
            unsigned long long wv2[4];
            wv2[0] = ((unsigned long long)__float_as_uint(w0.y) << 32) | __float_as_uint(w0.x);
            wv2[1] = ((unsigned long long)__float_as_uint(w0.w) << 32) | __float_as_uint(w0.z);
            wv2[2] = ((unsigned long long)__float_as_uint(w1.y) << 32) | __float_as_uint(w1.x);
            wv2[3] = ((unsigned long long)__float_as_uint(w1.w) << 32) | __float_as_uint(w1.z);
            #pragma unroll
            for (int r = 0; r < 4; r++) {
                unsigned long long av = pack2(Ys[rq*4 + r][k0 + k]);
                #pragma unroll
                for (int j = 0; j < 4; j++)
                    acc[r][j] = fma2(av, wv2[j], acc[r][j]);
            }
        }
    }

    int l = l0 + sg*8;              // <= 1984 + 56 = 2040; +7 <= 2047 in-range
    int n = l >> 4, e = l & 15;     // 8 consecutive e within one n (l%16 in {0,8})
    float4 bv0 = *(const float4*)(bv + l);
    float4 bv1 = *(const float4*)(bv + l + 4);
    #pragma unroll
    for (int r = 0; r < 4; r++) {
        int bt = bt0 + rq*4 + r;
        if (bt < BT) {
            int b = bt / T, t = bt % T;
            size_t idx = ((size_t)((b*WD + n)*T + t))*EB + e;
            float4 xa0 = *(const float4*)(Xg + idx);
            float4 xa1 = *(const float4*)(Xg + idx + 4);
            float4 xr0 = *(const float4*)(Xr + idx);
            float4 xr1 = *(const float4*)(Xr + idx + 4);
            float a[8];
            unpack2(acc[r][0], a[0], a[1]);
            unpack2(acc[r][1], a[2], a[3]);
            unpack2(acc[r][2], a[4], a[5]);
            unpack2(acc[r][3], a[6], a[7]);
            float4 o0 = make_float4(xa0.x + xr0.x + a[0] + bv0.x,
                                    xa0.y + xr0.y + a[1] + bv0.y,
                                    xa0.z + xr0.z + a[2] + bv0.z,
                                    xa0.w + xr0.w + a[3] + bv0.w);
            float4 o1 = make_float4(xa1.x + xr1.x + a[4] + bv1.x,
                                    xa1.y + xr1.y + a[5] + bv1.y,
                                    xa1.z + xr1.z + a[6] + bv1.z,
                                    xa1.w + xr1.w + a[7] + bv1.w);
            *(float4*)(Yout + idx)     = o0;
            *(float4*)(Yout + idx + 4) = o1;
        }
    }
}

// ---------------- decode + time-mix output ----------------
__global__ void k_decode(const float* __restrict__ X, const float* __restrict__ dec_w,
                         const float* __restrict__ dec_b, const float* __restrict__ out_w,
                         const float* __restrict__ out_b, float* __restrict__ out) {
    __shared__ float sy[TF];
    int b = blockIdx.x >> 7, n = blockIdx.x & 127;
    int t = threadIdx.x;
    if (t < TF) {
        const float* xp = X + ((size_t)(b*WD + n)*TF + t)*EB;
        float a = dec_b[n];
        #pragma unroll
        for (int e = 0; e < EB; e++) a += xp[e]*dec_w[n*EB + e];
        sy[t] = a;
    }
    __syncthreads();
    if (t < ODIM) {
        float a = out_b[t];
        for (int tt = 0; tt < TF; tt++) a += sy[tt]*out_w[tt*ODIM + t];
        out[(b*ODIM + t)*WD + n] = a;
    }
}

// ---------------- launcher: fork (mt/uw + res on side stream) ----------------
extern "C" void kernel_launch(void* const* d_in, const int* in_sizes, int n_in,
                              void* d_out, int out_size) {
    const float* x_in  = (const float*)d_in[0];
    const float* emb_w = (const float*)d_in[1];
    const float* emb_b = (const float*)d_in[2];
    const float* g0_wf = (const float*)d_in[3];
    const float* g0_bf = (const float*)d_in[4];
    const float* g0_wg = (const float*)d_in[5];
    const float* g0_bg = (const float*)d_in[6];
    const float* g0_ws = (const float*)d_in[7];
    const float* g0_bs = (const float*)d_in[8];
    const float* a0_wq = (const float*)d_in[9];
    const float* a0_bq = (const float*)d_in[10];
    const float* a0_wk = (const float*)d_in[11];
    const float* a0_bk = (const float*)d_in[12];
    const float* a0_wv = (const float*)d_in[13];
    const float* a0_bv = (const float*)d_in[14];
    const float* g1_wf = (const float*)d_in[15];
    const float* g1_bf = (const float*)d_in[16];
    const float* g1_wg = (const float*)d_in[17];
    const float* g1_bg = (const float*)d_in[18];
    const float* g1_ws = (const float*)d_in[19];
    const float* g1_bs = (const float*)d_in[20];
    const float* a1_wq = (const float*)d_in[21];
    const float* a1_bq = (const float*)d_in[22];
    const float* a1_wk = (const float*)d_in[23];
    const float* a1_bk = (const float*)d_in[24];
    const float* a1_wv = (const float*)d_in[25];
    const float* a1_bv = (const float*)d_in[26];
    const float* dec_w = (const float*)d_in[27];
    const float* dec_b = (const float*)d_in[28];
    const float* out_w = (const float*)d_in[29];
    const float* out_b = (const float*)d_in[30];

    float *dA, *dB, *dR, *dMt, *dU, *dW, *dC, *dY;
    cudaGetSymbolAddress((void**)&dA,  g_bufA);
    cudaGetSymbolAddress((void**)&dB,  g_bufB);
    cudaGetSymbolAddress((void**)&dR,  g_bufR);
    cudaGetSymbolAddress((void**)&dMt, g_Mt);
    cudaGetSymbolAddress((void**)&dU,  g_uu);
    cudaGetSymbolAddress((void**)&dW,  g_ww);
    cudaGetSymbolAddress((void**)&dC,  g_cc);
    cudaGetSymbolAddress((void**)&dY,  g_yv);

    // double-buffered smem: 2*(2*64*36 + 16*136)*4 = 54272 bytes
    const int SMEM_G = 2*(2*64*36 + 16*136)*4;
    cudaFuncSetAttribute(k_gatedg<128,126,2>, cudaFuncAttributeMaxDynamicSharedMemorySize, SMEM_G);
    cudaFuncSetAttribute(k_gatedg<126,122,4>, cudaFuncAttributeMaxDynamicSharedMemorySize, SMEM_G);

    // side stream + events (host resources, created once)
    static cudaStream_t s2 = nullptr;
    static cudaEvent_t evOrigin = nullptr, evEmbed = nullptr,
                       evRes0 = nullptr, evAO0 = nullptr, evRes1 = nullptr;
    if (s2 == nullptr) {
        cudaStreamCreateWithFlags(&s2, cudaStreamNonBlocking);
        cudaEventCreateWithFlags(&evOrigin, cudaEventDisableTiming);
        cudaEventCreateWithFlags(&evEmbed,  cudaEventDisableTiming);
        cudaEventCreateWithFlags(&evRes0,   cudaEventDisableTiming);
        cudaEventCreateWithFlags(&evAO0,    cudaEventDisableTiming);
        cudaEventCreateWithFlags(&evRes1,   cudaEventDisableTiming);
    }

    // fork: side stream computes mt/uw, then res0/res1 when inputs ready
    cudaEventRecord(evOrigin, 0);
    cudaStreamWaitEvent(s2, evOrigin, 0);
    k_mt<<<dim3(64,2), 256, 0, s2>>>(a0_wq, a0_wk, a1_wq, a1_wk, dMt);
    k_uw<<<dim3(128,2), 256, 0, s2>>>(a0_wq, a0_wk, a0_bq, a0_bk,
                                      a1_wq, a1_wk, a1_bq, a1_bk, dU, dW, dC);

    // main stream: embed
    k_embed<<<(BB*TT0*WD + 255)/256, 256>>>(x_in, emb_w, emb_b, dA);
    cudaEventRecord(evEmbed, 0);

    // side stream: res0 (needs embed output dA)
    cudaStreamWaitEvent(s2, evEmbed, 0);
    k_res2<128,126><<<BB*32, 256, 0, s2>>>(dA, g0_ws, g0_bs, dR);
    cudaEventRecord(evRes0, s2);

    // layer 0: gated0 (main, concurrent with mt/uw/res0), then attn
    {
        const int ntileJ = (126*16 + 63)/64;  // 32
        k_gatedg<128,126,2><<<dim3(ntileJ*2, BB), 128, SMEM_G>>>(dA, g0_wf, g0_bf, g0_wg, g0_bg, dB);
        cudaStreamWaitEvent(0, evRes0, 0);   // join: implies mt/uw done too (same stream order)
        k_attn2<126><<<BB*126, 256>>>(dB, dR, dMt, dU, dW, dC, dY);
        k_attn_out<126><<<dim3(32, (BB*126 + 63)/64), 128>>>(dB, dR, dY, a0_wv, a0_bv, dA);
        cudaEventRecord(evAO0, 0);
    }

    // side stream: res1 (needs attn_out0's dA; dR free after attn_out0)
    cudaStreamWaitEvent(s2, evAO0, 0);
    k_res2<126,122><<<BB*32, 256, 0, s2>>>(dA, g1_ws, g1_bs, dR);
    cudaEventRecord(evRes1, s2);

    // layer 1: gated1 (main, concurrent with res1), then attn
    {
        const int ntileJ = (122*16 + 63)/64;  // 31
        k_gatedg<126,122,4><<<dim3(ntileJ*2, BB), 128, SMEM_G>>>(dA, g1_wf, g1_bf, g1_wg, g1_bg, dB);
        cudaStreamWaitEvent(0, evRes1, 0);   // joins s2 back before graph end
        k_attn2<122><<<BB*122, 256>>>(dB, dR, dMt + WD*WD, dU + WD, dW + WD, dC + 1, dY);
        k_attn_out<122><<<dim3(32, (BB*122 + 63)/64), 128>>>(dB, dR, dY, a1_wv, a1_bv, dA);
    }

    // decode
    k_decode<<<BB*WD, 128>>>(dA, dec_w, dec_b, out_w, out_b, (float*)d_out);
}

// round 17
// speedup vs baseline: 2.0555x; 1.1028x over previous
#include <cuda_runtime.h>
#include <cuda_pipeline.h>
#include <math.h>

#define BB   4
#define TT0  128
#define WD   128
#define EB   16
#define LL   2048
#define ODIM 24
#define TF   122

// ---------------- scratch (no allocations allowed) ----------------
__device__ float g_bufA[BB*WD*TT0*EB];   // 4 MB
__device__ float g_bufB[BB*WD*TT0*EB];   // 4 MB
__device__ float g_bufR[BB*WD*TT0*EB];   // 4 MB (residual-path output)
__device__ float g_Mt[2*WD*WD];          // Mt[m*128+n] = (Wq Wk^T)[n][m]
__device__ float g_uu[2*WD];             // u = Wq bk
__device__ float g_ww[2*WD];             // w = Wk bq
__device__ float g_cc[2];                // c = bq . bk
__device__ float g_yv[BB*126*WD];        // per-(b,t) y vectors

// ---------------- f32x2 packed helpers ----------------
__device__ __forceinline__ unsigned long long fma2(unsigned long long a,
                                                   unsigned long long b,
                                                   unsigned long long c) {
    unsigned long long d;
    asm("fma.rn.f32x2 %0, %1, %2, %3;" : "=l"(d) : "l"(a), "l"(b), "l"(c));
    return d;
}
__device__ __forceinline__ unsigned long long pack2(float v) {
    unsigned long long r;
    asm("mov.b64 %0, {%1, %1};" : "=l"(r) : "f"(v));
    return r;
}
__device__ __forceinline__ void unpack2(unsigned long long v, float& lo, float& hi) {
    asm("mov.b64 {%0, %1}, %2;" : "=f"(lo), "=f"(hi) : "l"(v));
}

// ---------------- embed: x_in -> (B,N,T,E) ----------------
__global__ void k_embed(const float* __restrict__ x_in,
                        const float* __restrict__ emb_w,
                        const float* __restrict__ emb_b,
                        float* __restrict__ out) {
    int idx = blockIdx.x*blockDim.x + threadIdx.x;   // over B*T*N
    if (idx >= BB*TT0*WD) return;
    int n = idx & 127;
    int t = (idx >> 7) & 127;
    int b = idx >> 14;
    const float* xi = x_in + (b*TT0 + t)*131;
    float v  = xi[n];
    float f0 = xi[128], f1 = xi[129], f2 = xi[130];
    float* o = out + ((b*WD + n)*TT0 + t)*EB;
    #pragma unroll
    for (int e = 0; e < EB; e++)
        o[e] = v*emb_w[e] + f0*emb_w[16+e] + f1*emb_w[32+e] + f2*emb_w[48+e] + emb_b[e];
}

// ---------------- precompute Mt[m*128+n] = sum_l Wq[n,l]*Wk[m,l], both layers ----------------
__global__ void k_mt(const float* __restrict__ Wq0, const float* __restrict__ Wk0,
                     const float* __restrict__ Wq1, const float* __restrict__ Wk1,
                     float* __restrict__ Mt) {
    __shared__ float Aq[16][65], Ak[16][65];
    int ly = blockIdx.y;
    const float* Wq = ly ? Wq1 : Wq0;
    const float* Wk = ly ? Wk1 : Wk0;
    float* Mto = Mt + ly*WD*WD;
    int bm = blockIdx.x >> 3, bn = blockIdx.x & 7;
    int m0 = bm*16, n0 = bn*16;
    int ty = threadIdx.x >> 4, tx = threadIdx.x & 15;  // ty -> m, tx -> n
    float acc = 0.f;
    for (int l0 = 0; l0 < LL; l0 += 64) {
        #pragma unroll
        for (int r = 0; r < 4; r++) {
            int idx = threadIdx.x + r*256;
            int row = idx >> 6, col = idx & 63;
            Aq[row][col] = Wq[(n0+row)*LL + l0 + col];
            Ak[row][col] = Wk[(m0+row)*LL + l0 + col];
        }
        __syncthreads();
        #pragma unroll
        for (int lc = 0; lc < 64; lc++)
            acc += Ak[ty][lc]*Aq[tx][lc];
        __syncthreads();
    }
    Mto[(m0+ty)*WD + (n0+tx)] = acc;
}

// ---------------- precompute u, w, c (both layers) ----------------
__global__ void k_uw(const float* __restrict__ Wq0, const float* __restrict__ Wk0,
                     const float* __restrict__ bq0, const float* __restrict__ bk0,
                     const float* __restrict__ Wq1, const float* __restrict__ Wk1,
                     const float* __restrict__ bq1, const float* __restrict__ bk1,
                     float* __restrict__ u, float* __restrict__ w, float* __restrict__ cp) {
    int ly = blockIdx.y;
    const float* Wq = ly ? Wq1 : Wq0;
    const float* Wk = ly ? Wk1 : Wk0;
    const float* bq = ly ? bq1 : bq0;
    const float* bk = ly ? bk1 : bk0;
    int n = blockIdx.x;
    __shared__ float su[256], sw[256], sc[256];
    float pu = 0.f, pw = 0.f, pc = 0.f;
    for (int l = threadIdx.x; l < LL; l += 256) {
        float bkl = bk[l], bql = bq[l];
        pu += Wq[n*LL + l]*bkl;
        pw += Wk[n*LL + l]*bql;
        if (n == 0) pc += bql*bkl;
    }
    su[threadIdx.x] = pu; sw[threadIdx.x] = pw; sc[threadIdx.x] = pc;
    __syncthreads();
    for (int s = 128; s > 0; s >>= 1) {
        if (threadIdx.x < s) {
            su[threadIdx.x] += su[threadIdx.x + s];
            sw[threadIdx.x] += sw[threadIdx.x + s];
            sc[threadIdx.x] += sc[threadIdx.x + s];
        }
        __syncthreads();
    }
    if (threadIdx.x == 0) {
        u[ly*WD + n] = su[0]; w[ly*WD + n] = sw[0];
        if (n == 0) cp[ly] = sc[0];
    }
}

// ---------------- gated conv GEMM + cp.async double-buffered pipeline ----------------
// j = t*16+e flattened per batch. Block tile 64o x 64j, thread 4o x 8j, 128 thr.
// Y[o,j] = tanh(F+bf)*sigmoid(G+bg)
template<int TIN, int TOUT, int D>
__global__ void k_gatedg(const float* __restrict__ X,
                         const float* __restrict__ wf, const float* __restrict__ bf,
                         const float* __restrict__ wg, const float* __restrict__ bg,
                         float* __restrict__ Y) {
    constexpr int TIN16  = TIN*16;
    constexpr int TOUT16 = TOUT*16;
    constexpr int OFF    = 16*D;          // tap-1 column offset (32 or 64)
    constexpr int APAD   = 36;            // 16B-aligned padded row for Af/Ag
    constexpr int AFS    = 64*APAD;       // 2304 floats per weight buffer
    constexpr int BSS    = 16*136;        // 2176 floats
    constexpr int STRIDE = 2*AFS + BSS;   // 6784 floats per buffer
    extern __shared__ float sm[];         // 2*STRIDE*4 = 54272 bytes

    int bx = blockIdx.x;
    int oB = bx & 1;                      // o-half
    int jT = bx >> 1;                     // j tile
    int b  = blockIdx.y;
    int j0b = jT*64;
    int tid = threadIdx.x;                // 128
    int jt = tid & 7;                     // j-group: j = j0b + jt*8 .. +7
    int ot = tid >> 3;                    // o-group: o_local = ot*4 .. +3

    unsigned long long fa[4][4], ga[4][4];
    #pragma unroll
    for (int oo = 0; oo < 4; oo++)
        #pragma unroll
        for (int p = 0; p < 4; p++) { fa[oo][p] = 0ull; ga[oo][p] = 0ull; }

    // stage chunk i0 into buffer buf via cp.async (16B ops)
    auto stage = [&](int i0, int buf) {
        float* Af_ = sm + buf*STRIDE;
        float* Ag_ = Af_ + AFS;
        float* Bs_ = Ag_ + AFS;
        #pragma unroll
        for (int r = 0; r < 4; r++) {
            int idx = tid + r*128;
            int kq = idx & 7, ol = idx >> 3;
            const float* srcF = wf + (size_t)(oB*64 + ol)*(WD*2) + i0*2 + kq*4;
            const float* srcG = wg + (size_t)(oB*64 + ol)*(WD*2) + i0*2 + kq*4;
            __pipeline_memcpy_async(Af_ + ol*APAD + kq*4, srcF, 16);
            __pipeline_memcpy_async(Ag_ + ol*APAD + kq*4, srcG, 16);
        }
        #pragma unroll
        for (int r = 0; r < 4; r++) {
            int idx = tid + r*128;
            int cq = idx & 31, il = idx >> 5;
            int jg = j0b + cq*4;
            float* dst = Bs_ + il*136 + cq*4;
            if (jg + 3 < TIN16) {
                const float* src = X + ((size_t)(b*WD + i0 + il))*TIN16 + jg;
                __pipeline_memcpy_async(dst, src, 16);
            } else {
                *(float4*)dst = make_float4(0.f, 0.f, 0.f, 0.f);
            }
        }
    };

    stage(0, 0);
    __pipeline_commit();
    __pipeline_wait_prior(0);
    __syncthreads();

    #pragma unroll
    for (int ch = 0; ch < 8; ch++) {
        int cur = ch & 1;
        if (ch < 7) {
            stage((ch + 1)*16, cur ^ 1);
            __pipeline_commit();
        }

        const float* Af_ = sm + cur*STRIDE;
        const float* Ag_ = Af_ + AFS;
        const float* Bs_ = Ag_ + AFS;
        #pragma unroll 4
        for (int il = 0; il < 16; il++) {
            #pragma unroll
            for (int tap = 0; tap < 2; tap++) {
                int k = il*2 + tap;
                const float* bp = Bs_ + il*136 + jt*8 + tap*OFF;
                ulonglong2 q0 = *(const ulonglong2*)bp;
                ulonglong2 q1 = *(const ulonglong2*)(bp + 4);
                unsigned long long bq[4] = {q0.x, q0.y, q1.x, q1.y};
                #pragma unroll
                for (int oo = 0; oo < 4; oo++) {
                    unsigned long long paf = pack2(Af_[(ot*4 + oo)*APAD + k]);
                    unsigned long long pag = pack2(Ag_[(ot*4 + oo)*APAD + k]);
                    #pragma unroll
                    for (int p = 0; p < 4; p++) {
                        fa[oo][p] = fma2(paf, bq[p], fa[oo][p]);
                        ga[oo][p] = fma2(pag, bq[p], ga[oo][p]);
                    }
                }
            }
        }
        if (ch < 7) __pipeline_wait_prior(0);
        __syncthreads();
    }

    int jbase = j0b + jt*8;
    if (jbase < TOUT16) {
        #pragma unroll
        for (int oo = 0; oo < 4; oo++) {
            int o = oB*64 + ot*4 + oo;
            float bfo = bf[o], bgo = bg[o];
            float fv[8], gv[8];
            #pragma unroll
            for (int p = 0; p < 4; p++) {
                unpack2(fa[oo][p], fv[2*p], fv[2*p+1]);
                unpack2(ga[oo][p], gv[2*p], gv[2*p+1]);
            }
            float yv[8];
            #pragma unroll
            for (int q = 0; q < 8; q++)
                yv[q] = tanhf(fv[q] + bfo)*(1.f/(1.f + expf(-(gv[q] + bgo))));
            float* yp = Y + ((size_t)(b*WD + o))*TOUT16 + jbase;
            *(float4*)(yp)     = make_float4(yv[0], yv[1], yv[2], yv[3]);
            *(float4*)(yp + 4) = make_float4(yv[4], yv[5], yv[6], yv[7]);
        }
    }
}

// ---------------- residual path v3: split-s tiled GEMM, R = X @ ws + bs ----------------
// Block: 64 rows x 64 s-half, thread 4r x 8s, 128 thr. grid = BB*32*2 = 256.
template<int TIN, int TOUT>
__global__ void k_res3s(const float* __restrict__ X, const float* __restrict__ ws,
                        const float* __restrict__ bs, float* __restrict__ R) {
    constexpr int RPB = 64;
    constexpr int KC  = 32;
    __shared__ float As[KC][RPB];       // [t][row]
    __shared__ float Ws[KC][68];        // [t][s_local]
    int bidx = blockIdx.x;
    int half = bidx & 1;
    int tile = bidx >> 1;               // BB*32
    int b  = tile >> 5;
    int r0 = (tile & 31)*RPB;
    int s0 = half*64;
    int tid = threadIdx.x;              // 128
    int rq = tid >> 3;                  // 16 groups -> rows rq*4..+3
    int sg = tid & 7;                   // s_local = sg*8 .. +7

    unsigned long long acc[4][4];
    #pragma unroll
    for (int r = 0; r < 4; r++)
        #pragma unroll
        for (int j = 0; j < 4; j++) acc[r][j] = 0ull;

    for (int t0 = 0; t0 < TIN; t0 += KC) {
        __syncthreads();
        // As: 32 t x 64 rows = 2048 / 128 = 16 per thread
        #pragma unroll
        for (int j = 0; j < 16; j++) {
            int idx = tid + j*128;
            int row = idx & 63;
            int t = idx >> 6;
            int rr = r0 + row;
            int n = rr >> 4, e = rr & 15;
            int tg = t0 + t;
            As[t][row] = (tg < TIN) ? X[((b*WD + n)*TIN + tg)*EB + e] : 0.f;
        }
        // Ws: 32 t x 64 s = 2048 / 128 = 16 per thread
        #pragma unroll
        for (int j = 0; j < 16; j++) {
            int idx = tid + j*128;
            int sl = idx & 63;
            int t = idx >> 6;
            int tg = t0 + t;
            int s = s0 + sl;
            Ws[t][sl] = (tg < TIN && s < TOUT) ? ws[tg*TOUT + s] : 0.f;
        }
        __syncthreads();
        #pragma unroll
        for (int t = 0; t < KC; t++) {
            float4 w0 = *(const float4*)(&Ws[t][sg*8]);
            float4 w1 = *(const float4*)(&Ws[t][sg*8 + 4]);
            unsigned long long wv[4];
            wv[0] = ((unsigned long long)__float_as_uint(w0.y) << 32) | __float_as_uint(w0.x);
            wv[1] = ((unsigned long long)__float_as_uint(w0.w) << 32) | __float_as_uint(w0.z);
            wv[2] = ((unsigned long long)__float_as_uint(w1.y) << 32) | __float_as_uint(w1.x);
            wv[3] = ((unsigned long long)__float_as_uint(w1.w) << 32) | __float_as_uint(w1.z);
            #pragma unroll
            for (int r = 0; r < 4; r++) {
                unsigned long long av = pack2(As[t][rq*4 + r]);
                #pragma unroll
                for (int j = 0; j < 4; j++)
                    acc[r][j] = fma2(av, wv[j], acc[r][j]);
            }
        }
    }
    #pragma unroll
    for (int r = 0; r < 4; r++) {
        int rr = r0 + rq*4 + r;
        int n = rr >> 4, e = rr & 15;
        float* yp = R + ((size_t)(b*WD + n)*TOUT)*EB + e;
        #pragma unroll
        for (int j = 0; j < 4; j++) {
            float lo, hi; unpack2(acc[r][j], lo, hi);
            int sl = sg*8 + j*2;
            int s = s0 + sl;
            if (s < TOUT)   yp[s*EB]     = lo + bs[s];
            if (s+1 < TOUT) yp[(s+1)*EB] = hi + bs[s+1];
        }
    }
}

// ---------------- fused attention: X = Xg+Xr; Z GEMM + softmax + ybar ----------------
template<int T>
__global__ void k_attn2(const float* __restrict__ Xg, const float* __restrict__ Xr,
                        const float* __restrict__ Mt,
                        const float* __restrict__ u, const float* __restrict__ w,
                        const float* __restrict__ cptr, float* __restrict__ yout) {
    __shared__ __align__(16) float Xs[WD*EB];   // [n][e] 8KB
    __shared__ __align__(16) float Ms[32*WD];   // Mt chunk [k][n] 16KB
    __shared__ float Zs[EB][WD+5];              // [f][n]
    __shared__ float Ss[EB][EB+1];
    __shared__ float uev[EB], wfv[EB], abar[EB];
    int bt = blockIdx.x;
    int b = bt / T, t = bt % T;
    int tid = threadIdx.x;                      // 256
    for (int idx = tid; idx < WD*4; idx += 256) {
        int n = idx >> 2, q = idx & 3;
        size_t off = ((size_t)((b*WD + n)*T + t))*EB + q*4;
        float4 a = *(const float4*)(Xg + off);
        float4 r = *(const float4*)(Xr + off);
        ((float4*)Xs)[idx] = make_float4(a.x + r.x, a.y + r.y, a.z + r.z, a.w + r.w);
    }
    int n_ = tid & 127, fh = tid >> 7;
    unsigned long long zacc[4] = {0ull, 0ull, 0ull, 0ull};
    for (int m0 = 0; m0 < WD; m0 += 32) {
        __syncthreads();
        #pragma unroll
        for (int rep = 0; rep < (32*WD/4)/256; rep++)
            ((float4*)Ms)[tid + rep*256] = ((const float4*)(Mt + m0*WD))[tid + rep*256];
        __syncthreads();
        #pragma unroll
        for (int k = 0; k < 32; k++) {
            unsigned long long pm = pack2(Ms[k*WD + n_]);
            const ulonglong2* xp = (const ulonglong2*)(Xs + (m0 + k)*16 + fh*8);
            ulonglong2 xa = xp[0];
            zacc[0] = fma2(pm, xa.x, zacc[0]);
            zacc[1] = fma2(pm, xa.y, zacc[1]);
            ulonglong2 xb = xp[1];
            zacc[2] = fma2(pm, xb.x, zacc[2]);
            zacc[3] = fma2(pm, xb.y, zacc[3]);
        }
    }
    #pragma unroll
    for (int j = 0; j < 4; j++) {
        float lo, hi; unpack2(zacc[j], lo, hi);
        Zs[fh*8 + 2*j][n_]     = lo;
        Zs[fh*8 + 2*j + 1][n_] = hi;
    }
    if (tid < 16) {
        float a = 0.f;
        for (int n = 0; n < WD; n++) a += Xs[n*16 + tid]*u[n];
        uev[tid] = a;
    } else if (tid < 32) {
        int f = tid - 16;
        float a = 0.f;
        for (int n = 0; n < WD; n++) a += Xs[n*16 + f]*w[n];
        wfv[f] = a;
    }
    __syncthreads();
    {
        int e = tid >> 4, f = tid & 15;
        float acc = 0.f;
        #pragma unroll 4
        for (int n = 0; n < WD; n++)
            acc += Xs[n*16 + e]*Zs[f][n];
        const float scale = 0.022097086912079608f; // 1/sqrt(2048)
        Ss[e][f] = (acc + uev[e] + wfv[f] + cptr[0])*scale;
    }
    __syncthreads();
    if (tid < 16) {
        int e = tid;
        float mx = -1e30f;
        #pragma unroll
        for (int f = 0; f < 16; f++) mx = fmaxf(mx, Ss[e][f]);
        float ex[16]; float sum = 0.f;
        #pragma unroll
        for (int f = 0; f < 16; f++) { ex[f] = expf(Ss[e][f] - mx); sum += ex[f]; }
        float inv = 1.f/sum;
        #pragma unroll
        for (int f = 0; f < 16; f++) Ss[e][f] = ex[f]*inv;
    }
    __syncthreads();
    if (tid < 16) {
        int f = tid;
        float a = 0.f;
        #pragma unroll
        for (int e = 0; e < 16; e++) a += Ss[e][f];
        abar[f] = a*(1.f/16.f);
    }
    __syncthreads();
    if (tid < 128) {
        int n = tid;
        float a = 0.f;
        #pragma unroll
        for (int f = 0; f < 16; f++) a += Xs[n*16 + f]*abar[f];
        yout[bt*WD + n] = a;
    }
}

// ---------------- attention out v3: tiled GEMM. Y = (Xg+Xr) + ys @ Wv + bv ----------------
// out[bt, l] = sum_m ys[bt, m] * Wv[m, l]. Block 64bt x 64l, thread 4bt x 8l, 128 thr.
template<int T>
__global__ void k_attn_out(const float* __restrict__ Xg, const float* __restrict__ Xr,
                           const float* __restrict__ yv,
                           const float* __restrict__ Wv, const float* __restrict__ bv,
                           float* __restrict__ Yout) {
    const int BT = BB*T;
    __shared__ float Ys[64][132];   // [btl][m], full K
    __shared__ float Ws[32][68];    // [k][l_local] chunk
    int l0  = blockIdx.x*64;
    int bt0 = blockIdx.y*64;
    int tid = threadIdx.x;          // 128
    int rq = tid >> 3;              // 0..15 -> bt rows rq*4..+3 (64 bt)
    int sg = tid & 7;               // l = l0 + sg*8 .. +7 (64 l)

    #pragma unroll
    for (int r = 0; r < 16; r++) {
        int i = tid + r*128;
        int btl = i >> 5, q = i & 31;
        int bt = bt0 + btl;
        float4 v = make_float4(0.f, 0.f, 0.f, 0.f);
        if (bt < BT) v = *(const float4*)(yv + (size_t)bt*WD + q*4);
        *(float4*)(&Ys[btl][q*4]) = v;
    }

    unsigned long long acc[4][4];
    #pragma unroll
    for (int r = 0; r < 4; r++)
        #pragma unroll
        for (int j = 0; j < 4; j++) acc[r][j] = 0ull;

    for (int k0 = 0; k0 < WD; k0 += 32) {
        __syncthreads();
        #pragma unroll
        for (int r = 0; r < 4; r++) {
            int i = tid + r*128;
            int k = i >> 4, q = i & 15;
            *(float4*)(&Ws[k][q*4]) = *(const float4*)(Wv + (size_t)(k0 + k)*LL + l0 + q*4);
        }
        __syncthreads();
        #pragma unroll
        for (int k = 0; k < 32; k++) {
            float4 w0 = *(const float4*)(&Ws[k][sg*8]);
            float4 w1 = *(const float4*)(&Ws[k][sg*8 + 4]);
            unsigned long long wv2[4];
            wv2[0] = ((unsigned long long)__float_as_uint(w0.y) << 32) | __float_as_uint(w0.x);
            wv2[1] = ((unsigned long long)__float_as_uint(w0.w) << 32) | __float_as_uint(w0.z);
            wv2[2] = ((unsigned long long)__float_as_uint(w1.y) << 32) | __float_as_uint(w1.x);
            wv2[3] = ((unsigned long long)__float_as_uint(w1.w) << 32) | __float_as_uint(w1.z);
            #pragma unroll
            for (int r = 0; r < 4; r++) {
                unsigned long long av = pack2(Ys[rq*4 + r][k0 + k]);
                #pragma unroll
                for (int j = 0; j < 4; j++)
                    acc[r][j] = fma2(av, wv2[j], acc[r][j]);
            }
        }
    }

    int l = l0 + sg*8;
    int n = l >> 4, e = l & 15;
    float4 bv0 = *(const float4*)(bv + l);
    float4 bv1 = *(const float4*)(bv + l + 4);
    #pragma unroll
    for (int r = 0; r < 4; r++) {
        int bt = bt0 + rq*4 + r;
        if (bt < BT) {
            int b = bt / T, t = bt % T;
            size_t idx = ((size_t)((b*WD + n)*T + t))*EB + e;
            float4 xa0 = *(const float4*)(Xg + idx);
            float4 xa1 = *(const float4*)(Xg + idx + 4);
            float4 xr0 = *(const float4*)(Xr + idx);
            float4 xr1 = *(const float4*)(Xr + idx + 4);
            float a[8];
            unpack2(acc[r][0], a[0], a[1]);
            unpack2(acc[r][1], a[2], a[3]);
            unpack2(acc[r][2], a[4], a[5]);
            unpack2(acc[r][3], a[6], a[7]);
            float4 o0 = make_float4(xa0.x + xr0.x + a[0] + bv0.x,
                                    xa0.y + xr0.y + a[1] + bv0.y,
                                    xa0.z + xr0.z + a[2] + bv0.z,
                                    xa0.w + xr0.w + a[3] + bv0.w);
            float4 o1 = make_float4(xa1.x + xr1.x + a[4] + bv1.x,
                                    xa1.y + xr1.y + a[5] + bv1.y,
                                    xa1.z + xr1.z + a[6] + bv1.z,
                                    xa1.w + xr1.w + a[7] + bv1.w);
            *(float4*)(Yout + idx)     = o0;
            *(float4*)(Yout + idx + 4) = o1;
        }
    }
}

// ---------------- decode + time-mix output ----------------
__global__ void k_decode(const float* __restrict__ X, const float* __restrict__ dec_w,
                         const float* __restrict__ dec_b, const float* __restrict__ out_w,
                         const float* __restrict__ out_b, float* __restrict__ out) {
    __shared__ float sy[TF];
    int b = blockIdx.x >> 7, n = blockIdx.x & 127;
    int t = threadIdx.x;
    if (t < TF) {
        const float* xp = X + ((size_t)(b*WD + n)*TF + t)*EB;
        float a = dec_b[n];
        #pragma unroll
        for (int e = 0; e < EB; e++) a += xp[e]*dec_w[n*EB + e];
        sy[t] = a;
    }
    __syncthreads();
    if (t < ODIM) {
        float a = out_b[t];
        for (int tt = 0; tt < TF; tt++) a += sy[tt]*out_w[tt*ODIM + t];
        out[(b*ODIM + t)*WD + n] = a;
    }
}

// ---------------- launcher: 3-stream fork ----------------
extern "C" void kernel_launch(void* const* d_in, const int* in_sizes, int n_in,
                              void* d_out, int out_size) {
    const float* x_in  = (const float*)d_in[0];
    const float* emb_w = (const float*)d_in[1];
    const float* emb_b = (const float*)d_in[2];
    const float* g0_wf = (const float*)d_in[3];
    const float* g0_bf = (const float*)d_in[4];
    const float* g0_wg = (const float*)d_in[5];
    const float* g0_bg = (const float*)d_in[6];
    const float* g0_ws = (const float*)d_in[7];
    const float* g0_bs = (const float*)d_in[8];
    const float* a0_wq = (const float*)d_in[9];
    const float* a0_bq = (const float*)d_in[10];
    const float* a0_wk = (const float*)d_in[11];
    const float* a0_bk = (const float*)d_in[12];
    const float* a0_wv = (const float*)d_in[13];
    const float* a0_bv = (const float*)d_in[14];
    const float* g1_wf = (const float*)d_in[15];
    const float* g1_bf = (const float*)d_in[16];
    const float* g1_wg = (const float*)d_in[17];
    const float* g1_bg = (const float*)d_in[18];
    const float* g1_ws = (const float*)d_in[19];
    const float* g1_bs = (const float*)d_in[20];
    const float* a1_wq = (const float*)d_in[21];
    const float* a1_bq = (const float*)d_in[22];
    const float* a1_wk = (const float*)d_in[23];
    const float* a1_bk = (const float*)d_in[24];
    const float* a1_wv = (const float*)d_in[25];
    const float* a1_bv = (const float*)d_in[26];
    const float* dec_w = (const float*)d_in[27];
    const float* dec_b = (const float*)d_in[28];
    const float* out_w = (const float*)d_in[29];
    const float* out_b = (const float*)d_in[30];

    float *dA, *dB, *dR, *dMt, *dU, *dW, *dC, *dY;
    cudaGetSymbolAddress((void**)&dA,  g_bufA);
    cudaGetSymbolAddress((void**)&dB,  g_bufB);
    cudaGetSymbolAddress((void**)&dR,  g_bufR);
    cudaGetSymbolAddress((void**)&dMt, g_Mt);
    cudaGetSymbolAddress((void**)&dU,  g_uu);
    cudaGetSymbolAddress((void**)&dW,  g_ww);
    cudaGetSymbolAddress((void**)&dC,  g_cc);
    cudaGetSymbolAddress((void**)&dY,  g_yv);

    // double-buffered smem: 2*(2*64*36 + 16*136)*4 = 54272 bytes
    const int SMEM_G = 2*(2*64*36 + 16*136)*4;
    cudaFuncSetAttribute(k_gatedg<128,126,2>, cudaFuncAttributeMaxDynamicSharedMemorySize, SMEM_G);
    cudaFuncSetAttribute(k_gatedg<126,122,4>, cudaFuncAttributeMaxDynamicSharedMemorySize, SMEM_G);

    // side streams + events (host resources, created once)
    static cudaStream_t s2 = nullptr, s3 = nullptr;
    static cudaEvent_t evOrigin = nullptr, evEmbed = nullptr, evPre = nullptr,
                       evRes0 = nullptr, evAO0 = nullptr, evRes1 = nullptr;
    if (s2 == nullptr) {
        cudaStreamCreateWithFlags(&s2, cudaStreamNonBlocking);
        cudaStreamCreateWithFlags(&s3, cudaStreamNonBlocking);
        cudaEventCreateWithFlags(&evOrigin, cudaEventDisableTiming);
        cudaEventCreateWithFlags(&evEmbed,  cudaEventDisableTiming);
        cudaEventCreateWithFlags(&evPre,    cudaEventDisableTiming);
        cudaEventCreateWithFlags(&evRes0,   cudaEventDisableTiming);
        cudaEventCreateWithFlags(&evAO0,    cudaEventDisableTiming);
        cudaEventCreateWithFlags(&evRes1,   cudaEventDisableTiming);
    }

    // fork
    cudaEventRecord(evOrigin, 0);
    cudaStreamWaitEvent(s2, evOrigin, 0);
    cudaStreamWaitEvent(s3, evOrigin, 0);

    // s3: attention precompute (independent of everything)
    k_mt<<<dim3(64,2), 256, 0, s3>>>(a0_wq, a0_wk, a1_wq, a1_wk, dMt);
    k_uw<<<dim3(128,2), 256, 0, s3>>>(a0_wq, a0_wk, a0_bq, a0_bk,
                                      a1_wq, a1_wk, a1_bq, a1_bk, dU, dW, dC);
    cudaEventRecord(evPre, s3);

    // main stream: embed
    k_embed<<<(BB*TT0*WD + 255)/256, 256>>>(x_in, emb_w, emb_b, dA);
    cudaEventRecord(evEmbed, 0);

    // s2: res0 (needs embed output dA)
    cudaStreamWaitEvent(s2, evEmbed, 0);
    k_res3s<128,126><<<BB*32*2, 128, 0, s2>>>(dA, g0_ws, g0_bs, dR);
    cudaEventRecord(evRes0, s2);

    // layer 0: gated0 (main, concurrent with mt/uw/res0), then attn
    {
        const int ntileJ = (126*16 + 63)/64;  // 32
        k_gatedg<128,126,2><<<dim3(ntileJ*2, BB), 128, SMEM_G>>>(dA, g0_wf, g0_bf, g0_wg, g0_bg, dB);
        cudaStreamWaitEvent(0, evRes0, 0);
        cudaStreamWaitEvent(0, evPre, 0);
        k_attn2<126><<<BB*126, 256>>>(dB, dR, dMt, dU, dW, dC, dY);
        k_attn_out<126><<<dim3(32, (BB*126 + 63)/64), 128>>>(dB, dR, dY, a0_wv, a0_bv, dA);
        cudaEventRecord(evAO0, 0);
    }

    // s2: res1 (needs attn_out0's dA; dR free after attn_out0)
    cudaStreamWaitEvent(s2, evAO0, 0);
    k_res3s<126,122><<<BB*32*2, 128, 0, s2>>>(dA, g1_ws, g1_bs, dR);
    cudaEventRecord(evRes1, s2);

    // layer 1: gated1 (main, concurrent with res1), then attn
    {
        const int ntileJ = (122*16 + 63)/64;  // 31
        k_gatedg<126,122,4><<<dim3(ntileJ*2, BB), 128, SMEM_G>>>(dA, g1_wf, g1_bf, g1_wg, g1_bg, dB);
        cudaStreamWaitEvent(0, evRes1, 0);   // joins s2 back before graph end
        k_attn2<122><<<BB*122, 256>>>(dB, dR, dMt + WD*WD, dU + WD, dW + WD, dC + 1, dY);
        k_attn_out<122><<<dim3(32, (BB*122 + 63)/64), 128>>>(dB, dR, dY, a1_wv, a1_bv, dA);
    }

    // decode
    k_decode<<<BB*WD, 128>>>(dA, dec_w, dec_b, out_w, out_b, (float*)d_out);
}